// round 11
// baseline (speedup 1.0000x reference)
#include <cuda_runtime.h>
#include <cuda_bf16.h>
#include <cuda_fp16.h>
#include <math.h>
#include <stdint.h>

#define BSZ 16
#define HW 12544
#define C1 256
#define C2 512
#define TT 32
#define HID 512
#define VOC 32000

// ---------------- scratch (static device arrays; no allocation) ----------------
__device__ __half  g_conv1[(size_t)BSZ*C1*HW];
__device__ double  g_part [C2*BSZ*2];
__device__ double2 g_part2[(size_t)C2*BSZ*98];
__device__ float   g_scale1[C1], g_shift1[C1];
__device__ float   g_scale2[C2], g_shift2[C2];
__device__ float   g_pooled[BSZ*C2], g_t1[BSZ*128], g_f[BSZ*C2], g_feats[BSZ*C2], g_ctx[BSZ*C2];
__device__ float   g_gctx[BSZ*1536];
__device__ float   g_gi  [(size_t)BSZ*TT*1536];
__device__ float   g_hall[(size_t)BSZ*TT*HID];
__device__ int     g_gbar[TT];

// fp16 planes for the pointwise-conv GEMM (single pass)
__device__ __half g_dwh[(size_t)BSZ*C1*HW];
__device__ __half g_pwwh[C2*C1];
__device__ __half g_pwout[(size_t)BSZ*C2*HW];
// bf16 hi/lo planes for precision-critical GEMMs (gi, logits)
__device__ __nv_bfloat16 g_fcwh[(size_t)VOC*HID],  g_fcwl[(size_t)VOC*HID];
__device__ __nv_bfloat16 g_wihh[1536*HID],         g_wihl[1536*HID];
__device__ __nv_bfloat16 g_embsh[512*HID],         g_embsl[512*HID];
__device__ __nv_bfloat16 g_hallh[512*HID],         g_halll[512*HID];

// =====================================================================
//                    helpers
// =====================================================================
__device__ __forceinline__ uint32_t smem_u32(const void* p) {
    uint32_t a;
    asm("{ .reg .u64 t; cvta.to.shared.u64 t, %1; cvt.u32.u64 %0, t; }" : "=r"(a) : "l"(p));
    return a;
}
__device__ __forceinline__ void ldsm4(uint32_t* r, uint32_t addr) {
    asm volatile("ldmatrix.sync.aligned.m8n8.x4.shared.b16 {%0,%1,%2,%3}, [%4];"
                 : "=r"(r[0]), "=r"(r[1]), "=r"(r[2]), "=r"(r[3]) : "r"(addr));
}
__device__ __forceinline__ void ldsm4t(uint32_t* r, uint32_t addr) {
    asm volatile("ldmatrix.sync.aligned.m8n8.x4.trans.shared.b16 {%0,%1,%2,%3}, [%4];"
                 : "=r"(r[0]), "=r"(r[1]), "=r"(r[2]), "=r"(r[3]) : "r"(addr));
}
__device__ __forceinline__ void mma_bf(float* d, const uint32_t* a, uint32_t b0, uint32_t b1) {
    asm volatile(
        "mma.sync.aligned.m16n8k16.row.col.f32.bf16.bf16.f32 "
        "{%0,%1,%2,%3}, {%4,%5,%6,%7}, {%8,%9}, {%0,%1,%2,%3};"
        : "+f"(d[0]), "+f"(d[1]), "+f"(d[2]), "+f"(d[3])
        : "r"(a[0]), "r"(a[1]), "r"(a[2]), "r"(a[3]), "r"(b0), "r"(b1));
}
__device__ __forceinline__ void mma_fp(float* d, const uint32_t* a, uint32_t b0, uint32_t b1) {
    asm volatile(
        "mma.sync.aligned.m16n8k16.row.col.f32.f16.f16.f32 "
        "{%0,%1,%2,%3}, {%4,%5,%6,%7}, {%8,%9}, {%0,%1,%2,%3};"
        : "+f"(d[0]), "+f"(d[1]), "+f"(d[2]), "+f"(d[3])
        : "r"(a[0]), "r"(a[1]), "r"(a[2]), "r"(a[3]), "r"(b0), "r"(b1));
}
__device__ __forceinline__ uint32_t pack_bf2(float lo, float hi) {
    uint32_t r;
    asm("cvt.rn.bf16x2.f32 %0, %1, %2;" : "=r"(r) : "f"(hi), "f"(lo));
    return r;
}
__device__ __forceinline__ void split2(float x, float& h, float& l) {
    h = __bfloat162float(__float2bfloat16(x));
    l = x - h;
}
__device__ __forceinline__ void cpa16(uint32_t dst, const void* src) {
    asm volatile("cp.async.cg.shared.global [%0], [%1], 16;" :: "r"(dst), "l"(src));
}
__device__ __forceinline__ void cp_commit() { asm volatile("cp.async.commit_group;"); }
template<int NW> __device__ __forceinline__ void cp_wait() {
    asm volatile("cp.async.wait_group %0;" :: "n"(NW));
}

// =====================================================================
//   split kernels
// =====================================================================
__global__ void split_mat(const float* __restrict__ src, __nv_bfloat16* __restrict__ dh,
                          __nv_bfloat16* __restrict__ dl, size_t n) {
    size_t i = ((size_t)blockIdx.x*256 + threadIdx.x)*4;
    if (i >= n) return;
    float4 v = *(const float4*)&src[i];
    float hx, lx, hy, ly, hz, lz, hw, lw;
    split2(v.x, hx, lx); split2(v.y, hy, ly); split2(v.z, hz, lz); split2(v.w, hw, lw);
    *(uint2*)&dh[i] = make_uint2(pack_bf2(hx, hy), pack_bf2(hz, hw));
    *(uint2*)&dl[i] = make_uint2(pack_bf2(lx, ly), pack_bf2(lz, lw));
}
__global__ void split_strided(const float* __restrict__ src, int ld,
                              __nv_bfloat16* __restrict__ dh, __nv_bfloat16* __restrict__ dl) {
    size_t i = ((size_t)blockIdx.x*256 + threadIdx.x)*4;
    int row = (int)(i >> 9), col = (int)(i & 511);
    float4 v = *(const float4*)&src[(size_t)row*ld + col];
    float hx, lx, hy, ly, hz, lz, hw, lw;
    split2(v.x, hx, lx); split2(v.y, hy, ly); split2(v.z, hz, lz); split2(v.w, hw, lw);
    *(uint2*)&dh[i] = make_uint2(pack_bf2(hx, hy), pack_bf2(hz, hw));
    *(uint2*)&dl[i] = make_uint2(pack_bf2(lx, ly), pack_bf2(lz, lw));
}
__global__ void to_half(const float* __restrict__ src, __half* __restrict__ dst, size_t n) {
    size_t i = ((size_t)blockIdx.x*256 + threadIdx.x)*4;
    if (i >= n) return;
    float4 v = *(const float4*)&src[i];
    __half2 a = __floats2half2_rn(v.x, v.y), b = __floats2half2_rn(v.z, v.w);
    *(uint2*)&dst[i] = make_uint2(*(uint32_t*)&a, *(uint32_t*)&b);
}

// =====================================================================
//   bf16 3-pass GEMM (NT), cp.async double-buffered — for gi + logits
//   NOTE: m0 <- blockIdx.x (fast axis) so row-tiles sharing a B column-tile
//   are adjacent in issue order -> B (the big weight planes) hits L2.
// =====================================================================
#define KTILE 32
#define LDA   80
#define PLANE 10240
#define STAGE (4*PLANE)
#define SMEM_REQ (2*STAGE + 1024)

__global__ void __launch_bounds__(256) mma_gemm_nt(
        const __nv_bfloat16* __restrict__ Ah, const __nv_bfloat16* __restrict__ Al,
        const __nv_bfloat16* __restrict__ Bh, const __nv_bfloat16* __restrict__ Bl,
        float* __restrict__ C, int M, int N, int K, int ldb,
        const float* __restrict__ bias, const float* __restrict__ rowaux) {
    extern __shared__ char dsm[];
    char* base = (char*)((((uintptr_t)dsm) + 1023) & ~(uintptr_t)1023);
    uint32_t sb0 = smem_u32(base);

    int m0 = blockIdx.x * 128, n0 = blockIdx.y * 128;
    int tid = threadIdx.x;
    int lane = tid & 31, wid = tid >> 5;
    int warp_m = wid & 3, warp_n = wid >> 2;

    float acc[2][8][4];
#pragma unroll
    for (int i = 0; i < 2; i++)
#pragma unroll
        for (int j = 0; j < 8; j++)
#pragma unroll
            for (int q = 0; q < 4; q++) acc[i][j][q] = 0.f;

    int KT = K / KTILE;

    auto load_stage = [&](int s, int kt) {
        uint32_t st = sb0 + s*STAGE;
        uint32_t ah_s = st, al_s = st + PLANE, bh_s = st + 2*PLANE, bl_s = st + 3*PLANE;
        int k0 = kt * KTILE;
#pragma unroll
        for (int i = 0; i < 2; i++) {
            int idx = tid + i*256;
            int row = idx >> 2, kc = idx & 3;
            uint32_t doff = row*LDA + kc*16;
            cpa16(ah_s + doff, Ah + (size_t)(m0 + row)*K + k0 + kc*8);
            cpa16(al_s + doff, Al + (size_t)(m0 + row)*K + k0 + kc*8);
            cpa16(bh_s + doff, Bh + (size_t)(n0 + row)*ldb + k0 + kc*8);
            cpa16(bl_s + doff, Bl + (size_t)(n0 + row)*ldb + k0 + kc*8);
        }
        cp_commit();
    };

    load_stage(0, 0);
    for (int kt = 0; kt < KT; kt++) {
        if (kt + 1 < KT) { load_stage((kt + 1) & 1, kt + 1); cp_wait<1>(); }
        else             { cp_wait<0>(); }
        __syncthreads();
        uint32_t st = sb0 + (kt & 1)*STAGE;
        uint32_t ah_b = st, al_b = st + PLANE, bh_b = st + 2*PLANE, bl_b = st + 3*PLANE;
#pragma unroll
        for (int ks = 0; ks < 2; ks++) {
            int kb = ks*16;
            uint32_t aH[2][4], aL[2][4];
#pragma unroll
            for (int im = 0; im < 2; im++) {
                int row = warp_m*32 + im*16 + (lane & 15);
                uint32_t off = row*LDA + (kb + (lane >> 4)*8)*2;
                ldsm4(aH[im], ah_b + off);
                ldsm4(aL[im], al_b + off);
            }
#pragma unroll
            for (int nc = 0; nc < 4; nc++) {
                uint32_t bH[4], bL[4];
                int row = warp_n*64 + nc*16 + (lane & 15);
                uint32_t off = row*LDA + (kb + (lane >> 4)*8)*2;
                ldsm4(bH, bh_b + off);
                ldsm4(bL, bl_b + off);
#pragma unroll
                for (int im = 0; im < 2; im++) {
                    float* a0 = acc[im][nc*2];
                    float* a1 = acc[im][nc*2 + 1];
                    mma_bf(a0, aH[im], bH[0], bH[2]);
                    mma_bf(a0, aH[im], bL[0], bL[2]);
                    mma_bf(a0, aL[im], bH[0], bH[2]);
                    mma_bf(a1, aH[im], bH[1], bH[3]);
                    mma_bf(a1, aH[im], bL[1], bL[3]);
                    mma_bf(a1, aL[im], bH[1], bH[3]);
                }
            }
        }
        __syncthreads();
    }

    int rbase = m0 + warp_m*32 + (lane >> 2);
    int cbase = n0 + warp_n*64 + (lane & 3)*2;
#pragma unroll
    for (int im = 0; im < 2; im++) {
#pragma unroll
        for (int nf = 0; nf < 8; nf++) {
            int m = rbase + im*16;
            int n = cbase + nf*8;
            float v0 = acc[im][nf][0], v1 = acc[im][nf][1];
            float v2 = acc[im][nf][2], v3 = acc[im][nf][3];
            if (bias)   { float b0 = bias[n], b1 = bias[n+1]; v0 += b0; v1 += b1; v2 += b0; v3 += b1; }
            if (rowaux) {
                float r0 = rowaux[(size_t)(m >> 5)*N + n],     r1 = rowaux[(size_t)(m >> 5)*N + n + 1];
                float r2 = rowaux[(size_t)((m+8) >> 5)*N + n], r3 = rowaux[(size_t)((m+8) >> 5)*N + n + 1];
                v0 += r0; v1 += r1; v2 += r2; v3 += r3;
            }
            *(float2*)&C[(size_t)m*N + n]     = make_float2(v0, v1);
            *(float2*)&C[(size_t)(m+8)*N + n] = make_float2(v2, v3);
        }
    }
}

// =====================================================================
//   fp16 single-pass GEMM (NN) with fused per-row stats — pointwise conv
// =====================================================================
#define HKT 64
#define HLDA 144
#define HLDB 272
#define HPA (128*HLDA)
#define HPB (64*HLDB)
#define HSTAGE (HPA + HPB)
#define HSMEM_REQ (2*HSTAGE + 1024)

__global__ void __launch_bounds__(256) hgemm_nn(
        const __half* __restrict__ A, const __half* __restrict__ B,
        __half* __restrict__ C, double2* __restrict__ part,
        int M, int N, int K, int ldb, size_t strideB, size_t strideC) {
    extern __shared__ char dsm[];
    char* base = (char*)((((uintptr_t)dsm) + 1023) & ~(uintptr_t)1023);
    uint32_t sb0 = smem_u32(base);

    const __half* Bb = B + (size_t)blockIdx.z * strideB;
    __half* Cb = C + (size_t)blockIdx.z * strideC;
    int m0 = blockIdx.y * 128, n0 = blockIdx.x * 128;
    int tid = threadIdx.x;
    int lane = tid & 31, wid = tid >> 5;
    int warp_m = wid & 3, warp_n = wid >> 2;

    float acc[2][8][4];
#pragma unroll
    for (int i = 0; i < 2; i++)
#pragma unroll
        for (int j = 0; j < 8; j++)
#pragma unroll
            for (int q = 0; q < 4; q++) acc[i][j][q] = 0.f;

    int KT = K / HKT;   // 4

    auto load_stage = [&](int s, int kt) {
        uint32_t st = sb0 + s*HSTAGE;
        uint32_t as = st, bs = st + HPA;
        int k0 = kt * HKT;
#pragma unroll
        for (int i = 0; i < 4; i++) {
            int idx = tid + i*256;
            int row = idx >> 3, kc = idx & 7;
            cpa16(as + row*HLDA + kc*16, A + (size_t)(m0 + row)*K + k0 + kc*8);
        }
#pragma unroll
        for (int i = 0; i < 4; i++) {
            int idx = tid + i*256;
            int row = idx >> 4, c = idx & 15;
            cpa16(bs + row*HLDB + c*16, Bb + (size_t)(k0 + row)*ldb + n0 + c*8);
        }
        cp_commit();
    };

    load_stage(0, 0);
    for (int kt = 0; kt < KT; kt++) {
        if (kt + 1 < KT) { load_stage((kt + 1) & 1, kt + 1); cp_wait<1>(); }
        else             { cp_wait<0>(); }
        __syncthreads();
        uint32_t st = sb0 + (kt & 1)*HSTAGE;
        uint32_t as = st, bs = st + HPA;
#pragma unroll
        for (int ks = 0; ks < 4; ks++) {
            int kb = ks*16;
            uint32_t aF[2][4];
#pragma unroll
            for (int im = 0; im < 2; im++) {
                int row = warp_m*32 + im*16 + (lane & 15);
                uint32_t off = row*HLDA + (kb + (lane >> 4)*8)*2;
                ldsm4(aF[im], as + off);
            }
#pragma unroll
            for (int nc = 0; nc < 4; nc++) {
                uint32_t bF[4];
                int row = kb + (lane & 15);
                int col = warp_n*64 + nc*16 + (lane >> 4)*8;
                ldsm4t(bF, bs + row*HLDB + col*2);
#pragma unroll
                for (int im = 0; im < 2; im++) {
                    mma_fp(acc[im][nc*2],     aF[im], bF[0], bF[1]);
                    mma_fp(acc[im][nc*2 + 1], aF[im], bF[2], bF[3]);
                }
            }
        }
        __syncthreads();
    }

    // ---- epilogue: fp16 store + per-row (channel) sum/sumsq ----
    int rloc = warp_m*32 + (lane >> 2);
    int cbase = n0 + warp_n*64 + (lane & 3)*2;
    float s[4]  = {0.f, 0.f, 0.f, 0.f};
    float s2[4] = {0.f, 0.f, 0.f, 0.f};
#pragma unroll
    for (int im = 0; im < 2; im++) {
#pragma unroll
        for (int nf = 0; nf < 8; nf++) {
            int m = m0 + rloc + im*16;
            int n = cbase + nf*8;
            float v0 = acc[im][nf][0], v1 = acc[im][nf][1];
            float v2 = acc[im][nf][2], v3 = acc[im][nf][3];
            __half2 h01 = __floats2half2_rn(v0, v1);
            __half2 h23 = __floats2half2_rn(v2, v3);
            *(__half2*)&Cb[(size_t)m*N + n]     = h01;
            *(__half2*)&Cb[(size_t)(m+8)*N + n] = h23;
            s [im*2+0] += v0 + v1;    s2[im*2+0] += v0*v0 + v1*v1;
            s [im*2+1] += v2 + v3;    s2[im*2+1] += v2*v2 + v3*v3;
        }
    }
#pragma unroll
    for (int r = 0; r < 4; r++) {
        s [r] += __shfl_xor_sync(0xffffffffu, s [r], 1);
        s [r] += __shfl_xor_sync(0xffffffffu, s [r], 2);
        s2[r] += __shfl_xor_sync(0xffffffffu, s2[r], 1);
        s2[r] += __shfl_xor_sync(0xffffffffu, s2[r], 2);
    }
    float2* sst = (float2*)base;
    __syncthreads();
    if ((lane & 3) == 0) {
#pragma unroll
        for (int r = 0; r < 4; r++) {
            int row = rloc + (r >> 1)*16 + (r & 1)*8;
            sst[warp_n*128 + row] = make_float2(s[r], s2[r]);
        }
    }
    __syncthreads();
    if (tid < 128) {
        float2 a = sst[tid], b = sst[128 + tid];
        double2 p;
        p.x = (double)a.x + (double)b.x;
        p.y = (double)a.y + (double)b.y;
        part[(size_t)(m0 + tid)*(BSZ*98) + blockIdx.z*98 + blockIdx.x] = p;
    }
}

// finalize BN2 scale/shift from fused partials; warp per channel
__global__ void chan_finalize2(const double2* __restrict__ part,
                               const float* __restrict__ g, const float* __restrict__ bt,
                               float* __restrict__ scale, float* __restrict__ shift) {
    int warp = (blockIdx.x*256 + threadIdx.x) >> 5;
    int lane = threadIdx.x & 31;
    if (warp >= C2) return;
    double s = 0, s2 = 0;
    for (int i = lane; i < BSZ*98; i += 32) {
        double2 p = part[(size_t)warp*(BSZ*98) + i];
        s += p.x; s2 += p.y;
    }
#pragma unroll
    for (int o = 16; o; o >>= 1) {
        s  += __shfl_xor_sync(0xffffffffu, s,  o);
        s2 += __shfl_xor_sync(0xffffffffu, s2, o);
    }
    if (lane == 0) {
        double cnt = (double)BSZ * HW;
        double m = s / cnt;
        double var = s2 / cnt - m*m;
        float rs = (float)(1.0 / sqrt(var + 1e-5));
        float sc = g[warp] * rs;
        scale[warp] = sc;
        shift[warp] = bt[warp] - (float)m * sc;
    }
}

// ---------------- conv1: 3->256, 3x3 s2 p1; fp16 output ----------------
__global__ void conv1_kernel(const float* __restrict__ img, const float* __restrict__ w,
                             __half* __restrict__ out) {
    __shared__ float ws[27][256];
    int b = blockIdx.y;
    int tY = blockIdx.x / 7, tX = blockIdx.x % 7;
    for (int i = threadIdx.x; i < C1*27; i += 256) {
        int c = i / 27, k = i - c*27;
        ws[k][c] = w[i];
    }
    __syncthreads();
    int ty = threadIdx.x >> 4, tx = threadIdx.x & 15;
    int oy = tY*16 + ty, ox = tX*16 + tx;
    int iy0 = oy*2 - 1, ix0 = ox*2 - 1;
    const float* ip = img + (size_t)b*3*224*224;
    float v[27];
#pragma unroll
    for (int ci = 0; ci < 3; ci++)
#pragma unroll
        for (int ky = 0; ky < 3; ky++)
#pragma unroll
            for (int kx = 0; kx < 3; kx++) {
                int iy = iy0 + ky, ix = ix0 + kx;
                float t = 0.f;
                if (iy >= 0 && iy < 224 && ix >= 0 && ix < 224)
                    t = ip[(ci*224 + iy)*224 + ix];
                v[ci*9 + ky*3 + kx] = t;
            }
    size_t obase = (size_t)b*C1*HW + oy*112 + ox;
    for (int c4 = 0; c4 < 64; c4++) {
        float4 a = make_float4(0.f, 0.f, 0.f, 0.f);
#pragma unroll
        for (int k = 0; k < 27; k++) {
            float4 wv = *(const float4*)&ws[k][c4*4];
            a.x += v[k]*wv.x; a.y += v[k]*wv.y; a.z += v[k]*wv.z; a.w += v[k]*wv.w;
        }
        out[obase + (size_t)(c4*4+0)*HW] = __float2half_rn(a.x);
        out[obase + (size_t)(c4*4+1)*HW] = __float2half_rn(a.y);
        out[obase + (size_t)(c4*4+2)*HW] = __float2half_rn(a.z);
        out[obase + (size_t)(c4*4+3)*HW] = __float2half_rn(a.w);
    }
}

// ---------------- per-channel stats from fp16 (two-stage, double) ----------------
__global__ void chan_partial_h(const __half* __restrict__ x, int C, double* __restrict__ part) {
    int c = blockIdx.x, b = blockIdx.y;
    const __half2* p = (const __half2*)(x + ((size_t)b*C + c)*HW);
    double s = 0, s2 = 0;
    for (int i = threadIdx.x; i < HW/2; i += 256) {
        float2 v = __half22float2(p[i]);
        s += (double)v.x + (double)v.y;
        s2 += (double)v.x*v.x + (double)v.y*v.y;
    }
    __shared__ double sh[256], sh2[256];
    sh[threadIdx.x] = s; sh2[threadIdx.x] = s2; __syncthreads();
    for (int o = 128; o; o >>= 1) {
        if (threadIdx.x < o) { sh[threadIdx.x] += sh[threadIdx.x+o]; sh2[threadIdx.x] += sh2[threadIdx.x+o]; }
        __syncthreads();
    }
    if (threadIdx.x == 0) { part[(c*BSZ + b)*2] = sh[0]; part[(c*BSZ + b)*2 + 1] = sh2[0]; }
}
__global__ void chan_finalize(int C, const double* __restrict__ part,
                              const float* __restrict__ g, const float* __restrict__ bt,
                              float* __restrict__ scale, float* __restrict__ shift) {
    int c = blockIdx.x*blockDim.x + threadIdx.x;
    if (c >= C) return;
    double s = 0, s2 = 0;
    for (int b = 0; b < BSZ; b++) { s += part[(c*BSZ+b)*2]; s2 += part[(c*BSZ+b)*2 + 1]; }
    double cnt = (double)BSZ * HW;
    double m = s / cnt;
    double var = s2 / cnt - m*m;
    float rs = (float)(1.0 / sqrt(var + 1e-5));
    float sc = g[c] * rs;
    scale[c] = sc;
    shift[c] = bt[c] - (float)m * sc;
}

// ---------------- depthwise 3x3 s1 p1 (BN1+ReLU fused), fp16 in/out -------------
__global__ void dw_kernel(const __half* __restrict__ in, const float* __restrict__ w,
                          const float* __restrict__ scale, const float* __restrict__ shift,
                          __half* __restrict__ outh) {
    int warp = threadIdx.x >> 5, lane = threadIdx.x & 31;
    int y = blockIdx.x*8 + warp;
    int c = blockIdx.y, b = blockIdx.z;
    float sc = scale[c], sh = shift[c];
    const __half* ip = in + ((size_t)b*C1 + c)*HW;
    int x0 = lane*4;
    bool inx = (x0 < 112);

    float v[3][4];
    float lft[3], rgt[3];
#pragma unroll
    for (int r = 0; r < 3; r++) {
        int yy = y - 1 + r;
        float t0 = 0.f, t1 = 0.f, t2 = 0.f, t3 = 0.f;
        if (inx && yy >= 0 && yy < 112) {
            uint2 u = *(const uint2*)&ip[yy*112 + x0];
            float2 p0 = __half22float2(*(__half2*)&u.x);
            float2 p1 = __half22float2(*(__half2*)&u.y);
            t0 = p0.x; t1 = p0.y; t2 = p1.x; t3 = p1.y;
        }
        v[r][0] = fmaxf(t0*sc + sh, 0.f);
        v[r][1] = fmaxf(t1*sc + sh, 0.f);
        v[r][2] = fmaxf(t2*sc + sh, 0.f);
        v[r][3] = fmaxf(t3*sc + sh, 0.f);
        if (!inx || (y - 1 + r) < 0 || (y - 1 + r) >= 112) { v[r][0]=v[r][1]=v[r][2]=v[r][3]=0.f; }
        lft[r] = __shfl_up_sync(0xffffffffu, v[r][3], 1);
        if (lane == 0) lft[r] = 0.f;
        rgt[r] = __shfl_down_sync(0xffffffffu, v[r][0], 1);
        if (lane >= 27) rgt[r] = 0.f;
    }
    float wv[9];
#pragma unroll
    for (int k = 0; k < 9; k++) wv[k] = __ldg(&w[c*9 + k]);

    float o0 = 0.f, o1 = 0.f, o2 = 0.f, o3 = 0.f;
#pragma unroll
    for (int r = 0; r < 3; r++) {
        float e0 = lft[r], e1 = v[r][0], e2 = v[r][1], e3 = v[r][2], e4 = v[r][3], e5 = rgt[r];
        float w0 = wv[r*3+0], w1 = wv[r*3+1], w2 = wv[r*3+2];
        o0 += w0*e0 + w1*e1 + w2*e2;
        o1 += w0*e1 + w1*e2 + w2*e3;
        o2 += w0*e2 + w1*e3 + w2*e4;
        o3 += w0*e3 + w1*e4 + w2*e5;
    }
    if (inx) {
        __half2 h01 = __floats2half2_rn(o0, o1);
        __half2 h23 = __floats2half2_rn(o2, o3);
        size_t off = ((size_t)b*C1 + c)*HW + y*112 + x0;
        *(uint2*)&outh[off] = make_uint2(*(uint32_t*)&h01, *(uint32_t*)&h23);
    }
}

// ---------------- pooled[b][c] = mean_p relu(bn2(pw)), fp16 source ----------------
__global__ void pooled_kernel(const __half* __restrict__ x, const float* __restrict__ scale,
                              const float* __restrict__ shift, float* __restrict__ pooled) {
    int c = blockIdx.x, b = blockIdx.y;
    const __half2* p = (const __half2*)(x + ((size_t)b*C2 + c)*HW);
    float sc = scale[c], sh = shift[c];
    double s = 0;
    for (int i = threadIdx.x; i < HW/2; i += 256) {
        float2 v = __half22float2(p[i]);
        float a = v.x*sc + sh, bq = v.y*sc + sh;
        if (a > 0.f) s += a;
        if (bq > 0.f) s += bq;
    }
    __shared__ double shm[256];
    shm[threadIdx.x] = s; __syncthreads();
    for (int o = 128; o; o >>= 1) {
        if (threadIdx.x < o) shm[threadIdx.x] += shm[threadIdx.x+o];
        __syncthreads();
    }
    if (threadIdx.x == 0) pooled[b*C2 + c] = (float)(shm[0] / (double)HW);
}

// ---------------- small GEMM ----------------
__global__ void small_gemm(const float* __restrict__ in, int K,
                           const float* __restrict__ W, int ldw, int woff,
                           const float* __restrict__ bias, const float* __restrict__ aux,
                           int O, int act, float* __restrict__ out) {
    __shared__ float sin_s[BSZ*512];
    for (int i = threadIdx.x; i < BSZ*K; i += 256) sin_s[i] = in[i];
    __syncthreads();
    int warp = threadIdx.x >> 5, lane = threadIdx.x & 31;
    int o = blockIdx.x*8 + warp;
    float part[BSZ];
#pragma unroll
    for (int b = 0; b < BSZ; b++) part[b] = 0.f;
    for (int k = lane; k < K; k += 32) {
        float wv = W[(size_t)o*ldw + woff + k];
#pragma unroll
        for (int b = 0; b < BSZ; b++) part[b] += wv * sin_s[b*K + k];
    }
#pragma unroll
    for (int b = 0; b < BSZ; b++) {
        float v = part[b];
#pragma unroll
        for (int off = 16; off; off >>= 1) v += __shfl_xor_sync(0xffffffffu, v, off);
        if (lane == b) {
            if (bias) v += bias[o];
            if (act == 1) v = v > 0.f ? v : 0.f;
            else if (act == 2) v = (1.f/(1.f + expf(-v))) * aux[b*O + o];
            out[b*O + o] = v;
        }
    }
}

// ---------------- gather caption embeddings: split planes ----------------
__global__ void gather_embs(const int* __restrict__ cap, const float* __restrict__ embed,
                            __nv_bfloat16* __restrict__ eh, __nv_bfloat16* __restrict__ el) {
    int row = blockIdx.x;
    int b = row >> 5, t = row & 31;
    int tok = cap[b*33 + t];
    const float* src = embed + (size_t)tok*HID;
    int i = threadIdx.x*2;
    float2 v = *(const float2*)&src[i];
    float h0,l0,h1,l1;
    split2(v.x,h0,l0); split2(v.y,h1,l1);
    *(uint32_t*)&eh[(size_t)row*HID + i] = pack_bf2(h0,h1);
    *(uint32_t*)&el[(size_t)row*HID + i] = pack_bf2(l0,l1);
}

// ---------------- persistent GRU ----------------
__global__ void gru_reset() {
    if (threadIdx.x < TT) g_gbar[threadIdx.x] = 0;
}
#define GRU_BLKS 64
__global__ void __launch_bounds__(256) gru_persist(
        const float* __restrict__ gi, const float* __restrict__ whh,
        const float* __restrict__ bhh, float* __restrict__ hall,
        __nv_bfloat16* __restrict__ hallh, __nv_bfloat16* __restrict__ halll) {
    __shared__ float hs[BSZ*HID];
    int tid = threadIdx.x;
    int warp = tid >> 5, lane = tid & 31;
    int j = blockIdx.x*8 + warp;
    float w0[16], w1[16], w2[16];
#pragma unroll
    for (int i = 0; i < 16; i++) {
        int k = lane + 32*i;
        w0[i] = whh[(size_t)j*HID + k];
        w1[i] = whh[(size_t)(j + 512)*HID + k];
        w2[i] = whh[(size_t)(j + 1024)*HID + k];
    }
    float bhr = bhh[j], bhz = bhh[j + 512], bhn = bhh[j + 1024];

    for (int t = 0; t < TT; t++) {
        for (int i = tid; i < BSZ*HID; i += 256) {
            int b = i >> 9, jj = i & 511;
            hs[i] = (t == 0) ? 0.f : hall[((size_t)(b*TT + t - 1))*HID + jj];
        }
        __syncthreads();
        for (int b = 0; b < BSZ; b++) {
            float pr = 0.f, pz = 0.f, pn = 0.f;
#pragma unroll
            for (int i = 0; i < 16; i++) {
                float hv = hs[b*HID + lane + 32*i];
                pr += hv*w0[i]; pz += hv*w1[i]; pn += hv*w2[i];
            }
#pragma unroll
            for (int o = 16; o; o >>= 1) {
                pr += __shfl_xor_sync(0xffffffffu, pr, o);
                pz += __shfl_xor_sync(0xffffffffu, pz, o);
                pn += __shfl_xor_sync(0xffffffffu, pn, o);
            }
            if (lane == 0) {
                size_t gib = ((size_t)(b*TT + t))*1536;
                float ir = gi[gib + j], iz = gi[gib + 512 + j], inn = gi[gib + 1024 + j];
                float r = 1.f/(1.f + expf(-(ir + pr + bhr)));
                float z = 1.f/(1.f + expf(-(iz + pz + bhz)));
                float n = tanhf(inn + r*(pn + bhn));
                float hp = hs[b*HID + j];
                float hn2 = (1.f - z)*n + z*hp;
                size_t oidx = ((size_t)(b*TT + t))*HID + j;
                hall[oidx] = hn2;
                float hh, hl;
                split2(hn2, hh, hl);
                hallh[oidx] = __float2bfloat16(hh);
                halll[oidx] = __float2bfloat16(hl);
            }
        }
        __threadfence();
        __syncthreads();
        if (tid == 0) {
            atomicAdd(&g_gbar[t], 1);
            while (atomicAdd(&g_gbar[t], 0) < GRU_BLKS) __nanosleep(64);
        }
        __syncthreads();
    }
}

// =======================================================================
extern "C" void kernel_launch(void* const* d_in, const int* in_sizes, int n_in,
                              void* d_out, int out_size) {
    const float* images   = (const float*)d_in[0];
    const int*   captions = (const int*)  d_in[1];
    const float* conv1_w  = (const float*)d_in[2];
    const float* bn1_g    = (const float*)d_in[3];
    const float* bn1_b    = (const float*)d_in[4];
    const float* dw_w     = (const float*)d_in[5];
    const float* pw_w     = (const float*)d_in[6];
    const float* bn2_g    = (const float*)d_in[7];
    const float* bn2_b    = (const float*)d_in[8];
    const float* se_fc1_w = (const float*)d_in[9];
    const float* se_fc2_w = (const float*)d_in[10];
    const float* enc_fc_w = (const float*)d_in[11];
    const float* enc_fc_b = (const float*)d_in[12];
    const float* embed    = (const float*)d_in[13];
    // d_in[14] = q_w (unused), d_in[15] = k_w (unused)
    const float* v_w      = (const float*)d_in[16];
    const float* gru_w_ih = (const float*)d_in[17];
    const float* gru_w_hh = (const float*)d_in[18];
    const float* gru_b_ih = (const float*)d_in[19];
    const float* gru_b_hh = (const float*)d_in[20];
    const float* fc_w     = (const float*)d_in[21];
    const float* fc_b     = (const float*)d_in[22];

    __half *conv1buf;
    double *part;
    double2 *part2;
    float *scale1, *shift1, *scale2, *shift2;
    float *pooled, *t1, *fbuf, *feats, *ctx, *gctx, *gi, *hall;
    __half *dwh, *pwwh, *pwout;
    __nv_bfloat16 *fcwh, *fcwl, *wihh, *wihl, *embsh, *embsl, *hallh, *halll;
    cudaGetSymbolAddress((void**)&conv1buf, g_conv1);
    cudaGetSymbolAddress((void**)&part,     g_part);
    cudaGetSymbolAddress((void**)&part2,    g_part2);
    cudaGetSymbolAddress((void**)&scale1,   g_scale1);
    cudaGetSymbolAddress((void**)&shift1,   g_shift1);
    cudaGetSymbolAddress((void**)&scale2,   g_scale2);
    cudaGetSymbolAddress((void**)&shift2,   g_shift2);
    cudaGetSymbolAddress((void**)&pooled,   g_pooled);
    cudaGetSymbolAddress((void**)&t1,       g_t1);
    cudaGetSymbolAddress((void**)&fbuf,     g_f);
    cudaGetSymbolAddress((void**)&feats,    g_feats);
    cudaGetSymbolAddress((void**)&ctx,      g_ctx);
    cudaGetSymbolAddress((void**)&gctx,     g_gctx);
    cudaGetSymbolAddress((void**)&gi,       g_gi);
    cudaGetSymbolAddress((void**)&hall,     g_hall);
    cudaGetSymbolAddress((void**)&dwh,      g_dwh);
    cudaGetSymbolAddress((void**)&pwwh,     g_pwwh);
    cudaGetSymbolAddress((void**)&pwout,    g_pwout);
    cudaGetSymbolAddress((void**)&fcwh,     g_fcwh);
    cudaGetSymbolAddress((void**)&fcwl,     g_fcwl);
    cudaGetSymbolAddress((void**)&wihh,     g_wihh);
    cudaGetSymbolAddress((void**)&wihl,     g_wihl);
    cudaGetSymbolAddress((void**)&embsh,    g_embsh);
    cudaGetSymbolAddress((void**)&embsl,    g_embsl);
    cudaGetSymbolAddress((void**)&hallh,    g_hallh);
    cudaGetSymbolAddress((void**)&halll,    g_halll);

    cudaFuncSetAttribute(mma_gemm_nt, cudaFuncAttributeMaxDynamicSharedMemorySize, SMEM_REQ);
    cudaFuncSetAttribute(hgemm_nn,    cudaFuncAttributeMaxDynamicSharedMemorySize, HSMEM_REQ);

    // weight conversions (independent of encoder)
    to_half<<<(C2*C1)/1024, 256>>>(pw_w, pwwh, (size_t)C2*C1);
    split_mat<<<((size_t)VOC*HID)/1024, 256>>>(fc_w, fcwh, fcwl, (size_t)VOC*HID);
    split_strided<<<(1536*512)/1024, 256>>>(gru_w_ih, 1024, wihh, wihl);

    // encoder
    conv1_kernel<<<dim3(49, BSZ), 256>>>(images, conv1_w, conv1buf);
    chan_partial_h<<<dim3(C1, BSZ), 256>>>(conv1buf, C1, part);
    chan_finalize<<<1, 256>>>(C1, part, bn1_g, bn1_b, scale1, shift1);
    dw_kernel<<<dim3(14, C1, BSZ), 256>>>(conv1buf, dw_w, scale1, shift1, dwh);
    // pointwise conv (fp16 single-pass GEMM, fused BN2 stats)
    hgemm_nn<<<dim3(98, 4, BSZ), 256, HSMEM_REQ>>>(pwwh, dwh, pwout, part2,
                                                   C2, HW, C1, HW,
                                                   (size_t)C1*HW, (size_t)C2*HW);
    chan_finalize2<<<64, 256>>>(part2, bn2_g, bn2_b, scale2, shift2);
    pooled_kernel<<<dim3(C2, BSZ), 256>>>(pwout, scale2, shift2, pooled);

    // SE + encoder FC + ctx (tiny GEMMs)
    small_gemm<<<16, 256>>>(pooled, 512, se_fc1_w, 512, 0, nullptr, nullptr, 128, 1, t1);
    small_gemm<<<64, 256>>>(t1, 128, se_fc2_w, 128, 0, nullptr, pooled, 512, 2, fbuf);
    small_gemm<<<64, 256>>>(fbuf, 512, enc_fc_w, 512, 0, enc_fc_b, nullptr, 512, 0, feats);
    small_gemm<<<64, 256>>>(feats, 512, v_w, 512, 0, nullptr, nullptr, 512, 0, ctx);

    // decoder: precompute input gates
    small_gemm<<<192, 256>>>(ctx, 512, gru_w_ih, 1024, 512, gru_b_ih, nullptr, 1536, 0, gctx);
    gather_embs<<<512, 256>>>(captions, embed, embsh, embsl);
    mma_gemm_nt<<<dim3(4, 12, 1), 256, SMEM_REQ>>>(embsh, embsl, wihh, wihl, gi,
                                                   512, 1536, 512, 512, nullptr, gctx);

    // persistent GRU recurrence
    gru_reset<<<1, 32>>>();
    gru_persist<<<GRU_BLKS, 256>>>(gi, gru_w_hh, gru_b_hh, hall, hallh, halll);

    // logits: 3-pass bf16 (precision-critical, lands directly in output)
    mma_gemm_nt<<<dim3(4, 250, 1), 256, SMEM_REQ>>>(hallh, halll, fcwh, fcwl, (float*)d_out,
                                                    512, VOC, 512, 512, fc_b, nullptr);
}

// round 12
// speedup vs baseline: 1.0333x; 1.0333x over previous
#include <cuda_runtime.h>
#include <cuda_bf16.h>
#include <cuda_fp16.h>
#include <math.h>
#include <stdint.h>

#define BSZ 16
#define HW 12544
#define C1 256
#define C2 512
#define TT 32
#define HID 512
#define VOC 32000

// ---------------- scratch (static device arrays; no allocation) ----------------
__device__ __half  g_conv1[(size_t)BSZ*C1*HW];
__device__ double  g_part [C2*BSZ*2];
__device__ double2 g_part2[(size_t)C2*BSZ*98];
__device__ float   g_scale1[C1], g_shift1[C1];
__device__ float   g_scale2[C2], g_shift2[C2];
__device__ float   g_pooled[BSZ*C2], g_t1[BSZ*128], g_f[BSZ*C2], g_feats[BSZ*C2], g_ctx[BSZ*C2];
__device__ float   g_gctx[BSZ*1536];
__device__ float   g_gi  [(size_t)BSZ*TT*1536];
__device__ float   g_hall[(size_t)BSZ*TT*HID];
__device__ int     g_gbar[TT];

// fp16 planes for the pointwise-conv GEMM (single pass)
__device__ __half g_dwh[(size_t)BSZ*C1*HW];
__device__ __half g_pwwh[C2*C1];
__device__ __half g_pwout[(size_t)BSZ*C2*HW];
// bf16 hi/lo planes for precision-critical GEMMs (gi, logits)
__device__ __nv_bfloat16 g_fcwh[(size_t)VOC*HID],  g_fcwl[(size_t)VOC*HID];
__device__ __nv_bfloat16 g_wihh[1536*HID],         g_wihl[1536*HID];
__device__ __nv_bfloat16 g_embsh[512*HID],         g_embsl[512*HID];
__device__ __nv_bfloat16 g_hallh[512*HID],         g_halll[512*HID];

// =====================================================================
//                    helpers
// =====================================================================
__device__ __forceinline__ uint32_t smem_u32(const void* p) {
    uint32_t a;
    asm("{ .reg .u64 t; cvta.to.shared.u64 t, %1; cvt.u32.u64 %0, t; }" : "=r"(a) : "l"(p));
    return a;
}
__device__ __forceinline__ void ldsm4(uint32_t* r, uint32_t addr) {
    asm volatile("ldmatrix.sync.aligned.m8n8.x4.shared.b16 {%0,%1,%2,%3}, [%4];"
                 : "=r"(r[0]), "=r"(r[1]), "=r"(r[2]), "=r"(r[3]) : "r"(addr));
}
__device__ __forceinline__ void ldsm4t(uint32_t* r, uint32_t addr) {
    asm volatile("ldmatrix.sync.aligned.m8n8.x4.trans.shared.b16 {%0,%1,%2,%3}, [%4];"
                 : "=r"(r[0]), "=r"(r[1]), "=r"(r[2]), "=r"(r[3]) : "r"(addr));
}
__device__ __forceinline__ void mma_bf(float* d, const uint32_t* a, uint32_t b0, uint32_t b1) {
    asm volatile(
        "mma.sync.aligned.m16n8k16.row.col.f32.bf16.bf16.f32 "
        "{%0,%1,%2,%3}, {%4,%5,%6,%7}, {%8,%9}, {%0,%1,%2,%3};"
        : "+f"(d[0]), "+f"(d[1]), "+f"(d[2]), "+f"(d[3])
        : "r"(a[0]), "r"(a[1]), "r"(a[2]), "r"(a[3]), "r"(b0), "r"(b1));
}
__device__ __forceinline__ void mma_fp(float* d, const uint32_t* a, uint32_t b0, uint32_t b1) {
    asm volatile(
        "mma.sync.aligned.m16n8k16.row.col.f32.f16.f16.f32 "
        "{%0,%1,%2,%3}, {%4,%5,%6,%7}, {%8,%9}, {%0,%1,%2,%3};"
        : "+f"(d[0]), "+f"(d[1]), "+f"(d[2]), "+f"(d[3])
        : "r"(a[0]), "r"(a[1]), "r"(a[2]), "r"(a[3]), "r"(b0), "r"(b1));
}
__device__ __forceinline__ uint32_t pack_bf2(float lo, float hi) {
    uint32_t r;
    asm("cvt.rn.bf16x2.f32 %0, %1, %2;" : "=r"(r) : "f"(hi), "f"(lo));
    return r;
}
__device__ __forceinline__ void split2(float x, float& h, float& l) {
    h = __bfloat162float(__float2bfloat16(x));
    l = x - h;
}
__device__ __forceinline__ void cpa16(uint32_t dst, const void* src) {
    asm volatile("cp.async.cg.shared.global [%0], [%1], 16;" :: "r"(dst), "l"(src));
}
__device__ __forceinline__ void cp_commit() { asm volatile("cp.async.commit_group;"); }
template<int NW> __device__ __forceinline__ void cp_wait() {
    asm volatile("cp.async.wait_group %0;" :: "n"(NW));
}

// =====================================================================
//   split kernels
// =====================================================================
__global__ void split_mat(const float* __restrict__ src, __nv_bfloat16* __restrict__ dh,
                          __nv_bfloat16* __restrict__ dl, size_t n) {
    size_t i = ((size_t)blockIdx.x*256 + threadIdx.x)*4;
    if (i >= n) return;
    float4 v = *(const float4*)&src[i];
    float hx, lx, hy, ly, hz, lz, hw, lw;
    split2(v.x, hx, lx); split2(v.y, hy, ly); split2(v.z, hz, lz); split2(v.w, hw, lw);
    *(uint2*)&dh[i] = make_uint2(pack_bf2(hx, hy), pack_bf2(hz, hw));
    *(uint2*)&dl[i] = make_uint2(pack_bf2(lx, ly), pack_bf2(lz, lw));
}
__global__ void split_strided(const float* __restrict__ src, int ld,
                              __nv_bfloat16* __restrict__ dh, __nv_bfloat16* __restrict__ dl) {
    size_t i = ((size_t)blockIdx.x*256 + threadIdx.x)*4;
    int row = (int)(i >> 9), col = (int)(i & 511);
    float4 v = *(const float4*)&src[(size_t)row*ld + col];
    float hx, lx, hy, ly, hz, lz, hw, lw;
    split2(v.x, hx, lx); split2(v.y, hy, ly); split2(v.z, hz, lz); split2(v.w, hw, lw);
    *(uint2*)&dh[i] = make_uint2(pack_bf2(hx, hy), pack_bf2(hz, hw));
    *(uint2*)&dl[i] = make_uint2(pack_bf2(lx, ly), pack_bf2(lz, lw));
}
__global__ void to_half(const float* __restrict__ src, __half* __restrict__ dst, size_t n) {
    size_t i = ((size_t)blockIdx.x*256 + threadIdx.x)*4;
    if (i >= n) return;
    float4 v = *(const float4*)&src[i];
    __half2 a = __floats2half2_rn(v.x, v.y), b = __floats2half2_rn(v.z, v.w);
    *(uint2*)&dst[i] = make_uint2(*(uint32_t*)&a, *(uint32_t*)&b);
}

// =====================================================================
//   bf16 3-pass GEMM (NT), cp.async double-buffered — for gi + logits
//   (R10 block order: n0 <- blockIdx.x fast axis — measured best)
// =====================================================================
#define KTILE 32
#define LDA   80
#define PLANE 10240
#define STAGE (4*PLANE)
#define SMEM_REQ (2*STAGE + 1024)

__global__ void __launch_bounds__(256) mma_gemm_nt(
        const __nv_bfloat16* __restrict__ Ah, const __nv_bfloat16* __restrict__ Al,
        const __nv_bfloat16* __restrict__ Bh, const __nv_bfloat16* __restrict__ Bl,
        float* __restrict__ C, int M, int N, int K, int ldb,
        const float* __restrict__ bias, const float* __restrict__ rowaux) {
    extern __shared__ char dsm[];
    char* base = (char*)((((uintptr_t)dsm) + 1023) & ~(uintptr_t)1023);
    uint32_t sb0 = smem_u32(base);

    int m0 = blockIdx.y * 128, n0 = blockIdx.x * 128;
    int tid = threadIdx.x;
    int lane = tid & 31, wid = tid >> 5;
    int warp_m = wid & 3, warp_n = wid >> 2;

    float acc[2][8][4];
#pragma unroll
    for (int i = 0; i < 2; i++)
#pragma unroll
        for (int j = 0; j < 8; j++)
#pragma unroll
            for (int q = 0; q < 4; q++) acc[i][j][q] = 0.f;

    int KT = K / KTILE;

    auto load_stage = [&](int s, int kt) {
        uint32_t st = sb0 + s*STAGE;
        uint32_t ah_s = st, al_s = st + PLANE, bh_s = st + 2*PLANE, bl_s = st + 3*PLANE;
        int k0 = kt * KTILE;
#pragma unroll
        for (int i = 0; i < 2; i++) {
            int idx = tid + i*256;
            int row = idx >> 2, kc = idx & 3;
            uint32_t doff = row*LDA + kc*16;
            cpa16(ah_s + doff, Ah + (size_t)(m0 + row)*K + k0 + kc*8);
            cpa16(al_s + doff, Al + (size_t)(m0 + row)*K + k0 + kc*8);
            cpa16(bh_s + doff, Bh + (size_t)(n0 + row)*ldb + k0 + kc*8);
            cpa16(bl_s + doff, Bl + (size_t)(n0 + row)*ldb + k0 + kc*8);
        }
        cp_commit();
    };

    load_stage(0, 0);
    for (int kt = 0; kt < KT; kt++) {
        if (kt + 1 < KT) { load_stage((kt + 1) & 1, kt + 1); cp_wait<1>(); }
        else             { cp_wait<0>(); }
        __syncthreads();
        uint32_t st = sb0 + (kt & 1)*STAGE;
        uint32_t ah_b = st, al_b = st + PLANE, bh_b = st + 2*PLANE, bl_b = st + 3*PLANE;
#pragma unroll
        for (int ks = 0; ks < 2; ks++) {
            int kb = ks*16;
            uint32_t aH[2][4], aL[2][4];
#pragma unroll
            for (int im = 0; im < 2; im++) {
                int row = warp_m*32 + im*16 + (lane & 15);
                uint32_t off = row*LDA + (kb + (lane >> 4)*8)*2;
                ldsm4(aH[im], ah_b + off);
                ldsm4(aL[im], al_b + off);
            }
#pragma unroll
            for (int nc = 0; nc < 4; nc++) {
                uint32_t bH[4], bL[4];
                int row = warp_n*64 + nc*16 + (lane & 15);
                uint32_t off = row*LDA + (kb + (lane >> 4)*8)*2;
                ldsm4(bH, bh_b + off);
                ldsm4(bL, bl_b + off);
#pragma unroll
                for (int im = 0; im < 2; im++) {
                    float* a0 = acc[im][nc*2];
                    float* a1 = acc[im][nc*2 + 1];
                    mma_bf(a0, aH[im], bH[0], bH[2]);
                    mma_bf(a0, aH[im], bL[0], bL[2]);
                    mma_bf(a0, aL[im], bH[0], bH[2]);
                    mma_bf(a1, aH[im], bH[1], bH[3]);
                    mma_bf(a1, aH[im], bL[1], bL[3]);
                    mma_bf(a1, aL[im], bH[1], bH[3]);
                }
            }
        }
        __syncthreads();
    }

    int rbase = m0 + warp_m*32 + (lane >> 2);
    int cbase = n0 + warp_n*64 + (lane & 3)*2;
#pragma unroll
    for (int im = 0; im < 2; im++) {
#pragma unroll
        for (int nf = 0; nf < 8; nf++) {
            int m = rbase + im*16;
            int n = cbase + nf*8;
            float v0 = acc[im][nf][0], v1 = acc[im][nf][1];
            float v2 = acc[im][nf][2], v3 = acc[im][nf][3];
            if (bias)   { float b0 = bias[n], b1 = bias[n+1]; v0 += b0; v1 += b1; v2 += b0; v3 += b1; }
            if (rowaux) {
                float r0 = rowaux[(size_t)(m >> 5)*N + n],     r1 = rowaux[(size_t)(m >> 5)*N + n + 1];
                float r2 = rowaux[(size_t)((m+8) >> 5)*N + n], r3 = rowaux[(size_t)((m+8) >> 5)*N + n + 1];
                v0 += r0; v1 += r1; v2 += r2; v3 += r3;
            }
            *(float2*)&C[(size_t)m*N + n]     = make_float2(v0, v1);
            *(float2*)&C[(size_t)(m+8)*N + n] = make_float2(v2, v3);
        }
    }
}

// =====================================================================
//   fp16 single-pass GEMM (NN) with fused per-row stats — pointwise conv
// =====================================================================
#define HKT 64
#define HLDA 144
#define HLDB 272
#define HPA (128*HLDA)
#define HPB (64*HLDB)
#define HSTAGE (HPA + HPB)
#define HSMEM_REQ (2*HSTAGE + 1024)

__global__ void __launch_bounds__(256) hgemm_nn(
        const __half* __restrict__ A, const __half* __restrict__ B,
        __half* __restrict__ C, double2* __restrict__ part,
        int M, int N, int K, int ldb, size_t strideB, size_t strideC) {
    extern __shared__ char dsm[];
    char* base = (char*)((((uintptr_t)dsm) + 1023) & ~(uintptr_t)1023);
    uint32_t sb0 = smem_u32(base);

    const __half* Bb = B + (size_t)blockIdx.z * strideB;
    __half* Cb = C + (size_t)blockIdx.z * strideC;
    int m0 = blockIdx.y * 128, n0 = blockIdx.x * 128;
    int tid = threadIdx.x;
    int lane = tid & 31, wid = tid >> 5;
    int warp_m = wid & 3, warp_n = wid >> 2;

    float acc[2][8][4];
#pragma unroll
    for (int i = 0; i < 2; i++)
#pragma unroll
        for (int j = 0; j < 8; j++)
#pragma unroll
            for (int q = 0; q < 4; q++) acc[i][j][q] = 0.f;

    int KT = K / HKT;   // 4

    auto load_stage = [&](int s, int kt) {
        uint32_t st = sb0 + s*HSTAGE;
        uint32_t as = st, bs = st + HPA;
        int k0 = kt * HKT;
#pragma unroll
        for (int i = 0; i < 4; i++) {
            int idx = tid + i*256;
            int row = idx >> 3, kc = idx & 7;
            cpa16(as + row*HLDA + kc*16, A + (size_t)(m0 + row)*K + k0 + kc*8);
        }
#pragma unroll
        for (int i = 0; i < 4; i++) {
            int idx = tid + i*256;
            int row = idx >> 4, c = idx & 15;
            cpa16(bs + row*HLDB + c*16, Bb + (size_t)(k0 + row)*ldb + n0 + c*8);
        }
        cp_commit();
    };

    load_stage(0, 0);
    for (int kt = 0; kt < KT; kt++) {
        if (kt + 1 < KT) { load_stage((kt + 1) & 1, kt + 1); cp_wait<1>(); }
        else             { cp_wait<0>(); }
        __syncthreads();
        uint32_t st = sb0 + (kt & 1)*HSTAGE;
        uint32_t as = st, bs = st + HPA;
#pragma unroll
        for (int ks = 0; ks < 4; ks++) {
            int kb = ks*16;
            uint32_t aF[2][4];
#pragma unroll
            for (int im = 0; im < 2; im++) {
                int row = warp_m*32 + im*16 + (lane & 15);
                uint32_t off = row*HLDA + (kb + (lane >> 4)*8)*2;
                ldsm4(aF[im], as + off);
            }
#pragma unroll
            for (int nc = 0; nc < 4; nc++) {
                uint32_t bF[4];
                int row = kb + (lane & 15);
                int col = warp_n*64 + nc*16 + (lane >> 4)*8;
                ldsm4t(bF, bs + row*HLDB + col*2);
#pragma unroll
                for (int im = 0; im < 2; im++) {
                    mma_fp(acc[im][nc*2],     aF[im], bF[0], bF[1]);
                    mma_fp(acc[im][nc*2 + 1], aF[im], bF[2], bF[3]);
                }
            }
        }
        __syncthreads();
    }

    // ---- epilogue: fp16 store + per-row (channel) sum/sumsq ----
    int rloc = warp_m*32 + (lane >> 2);
    int cbase = n0 + warp_n*64 + (lane & 3)*2;
    float s[4]  = {0.f, 0.f, 0.f, 0.f};
    float s2[4] = {0.f, 0.f, 0.f, 0.f};
#pragma unroll
    for (int im = 0; im < 2; im++) {
#pragma unroll
        for (int nf = 0; nf < 8; nf++) {
            int m = m0 + rloc + im*16;
            int n = cbase + nf*8;
            float v0 = acc[im][nf][0], v1 = acc[im][nf][1];
            float v2 = acc[im][nf][2], v3 = acc[im][nf][3];
            __half2 h01 = __floats2half2_rn(v0, v1);
            __half2 h23 = __floats2half2_rn(v2, v3);
            *(__half2*)&Cb[(size_t)m*N + n]     = h01;
            *(__half2*)&Cb[(size_t)(m+8)*N + n] = h23;
            s [im*2+0] += v0 + v1;    s2[im*2+0] += v0*v0 + v1*v1;
            s [im*2+1] += v2 + v3;    s2[im*2+1] += v2*v2 + v3*v3;
        }
    }
#pragma unroll
    for (int r = 0; r < 4; r++) {
        s [r] += __shfl_xor_sync(0xffffffffu, s [r], 1);
        s [r] += __shfl_xor_sync(0xffffffffu, s [r], 2);
        s2[r] += __shfl_xor_sync(0xffffffffu, s2[r], 1);
        s2[r] += __shfl_xor_sync(0xffffffffu, s2[r], 2);
    }
    float2* sst = (float2*)base;
    __syncthreads();
    if ((lane & 3) == 0) {
#pragma unroll
        for (int r = 0; r < 4; r++) {
            int row = rloc + (r >> 1)*16 + (r & 1)*8;
            sst[warp_n*128 + row] = make_float2(s[r], s2[r]);
        }
    }
    __syncthreads();
    if (tid < 128) {
        float2 a = sst[tid], b = sst[128 + tid];
        double2 p;
        p.x = (double)a.x + (double)b.x;
        p.y = (double)a.y + (double)b.y;
        part[(size_t)(m0 + tid)*(BSZ*98) + blockIdx.z*98 + blockIdx.x] = p;
    }
}

// finalize BN2 scale/shift from fused partials; warp per channel
__global__ void chan_finalize2(const double2* __restrict__ part,
                               const float* __restrict__ g, const float* __restrict__ bt,
                               float* __restrict__ scale, float* __restrict__ shift) {
    int warp = (blockIdx.x*256 + threadIdx.x) >> 5;
    int lane = threadIdx.x & 31;
    if (warp >= C2) return;
    double s = 0, s2 = 0;
    for (int i = lane; i < BSZ*98; i += 32) {
        double2 p = part[(size_t)warp*(BSZ*98) + i];
        s += p.x; s2 += p.y;
    }
#pragma unroll
    for (int o = 16; o; o >>= 1) {
        s  += __shfl_xor_sync(0xffffffffu, s,  o);
        s2 += __shfl_xor_sync(0xffffffffu, s2, o);
    }
    if (lane == 0) {
        double cnt = (double)BSZ * HW;
        double m = s / cnt;
        double var = s2 / cnt - m*m;
        float rs = (float)(1.0 / sqrt(var + 1e-5));
        float sc = g[warp] * rs;
        scale[warp] = sc;
        shift[warp] = bt[warp] - (float)m * sc;
    }
}

// =====================================================================
//   conv1 as fp16 implicit GEMM: M=256 ch, K=27(pad 32), N=112 pixels/row
//   CTA = (output row, batch). Weights + im2col tile in smem, mma.sync.
// =====================================================================
__global__ void __launch_bounds__(256) conv1_igemm(
        const float* __restrict__ img, const float* __restrict__ w,
        __half* __restrict__ out) {
    __shared__ __half wt [256*40];    // [c][k], stride 40 halves (80B)
    __shared__ __half imt[128*40];    // [p][k]
    __shared__ float  inr[9*224];     // [ci*3+ky][x]
    int oy = blockIdx.x, b = blockIdx.y;
    int tid = threadIdx.x;
    int lane = tid & 31, wid = tid >> 5;

    // weights -> smem (k-major rows, zero-pad k 27..31)
    for (int i = tid; i < 256*32; i += 256) {
        int c = i >> 5, k = i & 31;
        float v = (k < 27) ? __ldg(&w[c*27 + k]) : 0.f;
        wt[c*40 + k] = __float2half_rn(v);
    }
    // input rows (3 ch x 3 rows x 224), zero-pad out-of-range rows
    const float* ip = img + (size_t)b*3*224*224;
    for (int i = tid; i < 9*224; i += 256) {
        int r = i / 224, x = i - r*224;
        int ci = r / 3, ky = r - ci*3;
        int iy = oy*2 - 1 + ky;
        inr[i] = (iy >= 0 && iy < 224) ? ip[(ci*224 + iy)*224 + x] : 0.f;
    }
    __syncthreads();
    // build im2col tile [p][k]
    for (int i = tid; i < 128*32; i += 256) {
        int p = i >> 5, k = i & 31;
        float v = 0.f;
        if (p < 112 && k < 27) {
            int ci = k / 9, r = k - ci*9;
            int ky = r / 3, kx = r - ky*3;
            int ix = p*2 - 1 + kx;
            if (ix >= 0 && ix < 224) v = inr[(ci*3 + ky)*224 + ix];
        }
        imt[p*40 + k] = __float2half_rn(v);
    }
    __syncthreads();

    uint32_t wt_b = smem_u32(wt), imt_b = smem_u32(imt);
    size_t obase = (size_t)b*C1*HW + (size_t)oy*112;
    // warp wid owns channels [wid*32, wid*32+32); two passes over 64 pixels
#pragma unroll
    for (int half = 0; half < 2; half++) {
        float acc[2][8][4];
#pragma unroll
        for (int i = 0; i < 2; i++)
#pragma unroll
            for (int j = 0; j < 8; j++)
#pragma unroll
                for (int q = 0; q < 4; q++) acc[i][j][q] = 0.f;
#pragma unroll
        for (int ks = 0; ks < 2; ks++) {
            int kb = ks*16;
            uint32_t aF[2][4];
#pragma unroll
            for (int im = 0; im < 2; im++) {
                int row = wid*32 + im*16 + (lane & 15);
                ldsm4(aF[im], wt_b + (row*40 + kb + (lane >> 4)*8)*2);
            }
#pragma unroll
            for (int nc = 0; nc < 4; nc++) {
                uint32_t bF[4];
                int row = half*64 + nc*16 + (lane & 15);
                ldsm4(bF, imt_b + (row*40 + kb + (lane >> 4)*8)*2);
#pragma unroll
                for (int im = 0; im < 2; im++) {
                    mma_fp(acc[im][nc*2],     aF[im], bF[0], bF[2]);
                    mma_fp(acc[im][nc*2 + 1], aF[im], bF[1], bF[3]);
                }
            }
        }
        // store: m = channel, n = pixel
#pragma unroll
        for (int im = 0; im < 2; im++) {
#pragma unroll
            for (int nf = 0; nf < 8; nf++) {
                int m = wid*32 + im*16 + (lane >> 2);
                int n = half*64 + nf*8 + (lane & 3)*2;
                if (n < 112) {
                    __half2 h01 = __floats2half2_rn(acc[im][nf][0], acc[im][nf][1]);
                    __half2 h23 = __floats2half2_rn(acc[im][nf][2], acc[im][nf][3]);
                    *(__half2*)&out[obase + (size_t)m*HW + n]     = h01;
                    *(__half2*)&out[obase + (size_t)(m+8)*HW + n] = h23;
                }
            }
        }
    }
}

// ---------------- per-channel stats from fp16 (two-stage, double) ----------------
__global__ void chan_partial_h(const __half* __restrict__ x, int C, double* __restrict__ part) {
    int c = blockIdx.x, b = blockIdx.y;
    const __half2* p = (const __half2*)(x + ((size_t)b*C + c)*HW);
    double s = 0, s2 = 0;
    for (int i = threadIdx.x; i < HW/2; i += 256) {
        float2 v = __half22float2(p[i]);
        s += (double)v.x + (double)v.y;
        s2 += (double)v.x*v.x + (double)v.y*v.y;
    }
    __shared__ double sh[256], sh2[256];
    sh[threadIdx.x] = s; sh2[threadIdx.x] = s2; __syncthreads();
    for (int o = 128; o; o >>= 1) {
        if (threadIdx.x < o) { sh[threadIdx.x] += sh[threadIdx.x+o]; sh2[threadIdx.x] += sh2[threadIdx.x+o]; }
        __syncthreads();
    }
    if (threadIdx.x == 0) { part[(c*BSZ + b)*2] = sh[0]; part[(c*BSZ + b)*2 + 1] = sh2[0]; }
}
__global__ void chan_finalize(int C, const double* __restrict__ part,
                              const float* __restrict__ g, const float* __restrict__ bt,
                              float* __restrict__ scale, float* __restrict__ shift) {
    int c = blockIdx.x*blockDim.x + threadIdx.x;
    if (c >= C) return;
    double s = 0, s2 = 0;
    for (int b = 0; b < BSZ; b++) { s += part[(c*BSZ+b)*2]; s2 += part[(c*BSZ+b)*2 + 1]; }
    double cnt = (double)BSZ * HW;
    double m = s / cnt;
    double var = s2 / cnt - m*m;
    float rs = (float)(1.0 / sqrt(var + 1e-5));
    float sc = g[c] * rs;
    scale[c] = sc;
    shift[c] = bt[c] - (float)m * sc;
}

// ---------------- depthwise 3x3 s1 p1 (BN1+ReLU fused), fp16 in/out -------------
__global__ void dw_kernel(const __half* __restrict__ in, const float* __restrict__ w,
                          const float* __restrict__ scale, const float* __restrict__ shift,
                          __half* __restrict__ outh) {
    int warp = threadIdx.x >> 5, lane = threadIdx.x & 31;
    int y = blockIdx.x*8 + warp;
    int c = blockIdx.y, b = blockIdx.z;
    float sc = scale[c], sh = shift[c];
    const __half* ip = in + ((size_t)b*C1 + c)*HW;
    int x0 = lane*4;
    bool inx = (x0 < 112);

    float v[3][4];
    float lft[3], rgt[3];
#pragma unroll
    for (int r = 0; r < 3; r++) {
        int yy = y - 1 + r;
        float t0 = 0.f, t1 = 0.f, t2 = 0.f, t3 = 0.f;
        if (inx && yy >= 0 && yy < 112) {
            uint2 u = *(const uint2*)&ip[yy*112 + x0];
            float2 p0 = __half22float2(*(__half2*)&u.x);
            float2 p1 = __half22float2(*(__half2*)&u.y);
            t0 = p0.x; t1 = p0.y; t2 = p1.x; t3 = p1.y;
        }
        v[r][0] = fmaxf(t0*sc + sh, 0.f);
        v[r][1] = fmaxf(t1*sc + sh, 0.f);
        v[r][2] = fmaxf(t2*sc + sh, 0.f);
        v[r][3] = fmaxf(t3*sc + sh, 0.f);
        if (!inx || yy < 0 || yy >= 112) { v[r][0]=v[r][1]=v[r][2]=v[r][3]=0.f; }
        lft[r] = __shfl_up_sync(0xffffffffu, v[r][3], 1);
        if (lane == 0) lft[r] = 0.f;
        rgt[r] = __shfl_down_sync(0xffffffffu, v[r][0], 1);
        if (lane >= 27) rgt[r] = 0.f;
    }
    float wv[9];
#pragma unroll
    for (int k = 0; k < 9; k++) wv[k] = __ldg(&w[c*9 + k]);

    float o0 = 0.f, o1 = 0.f, o2 = 0.f, o3 = 0.f;
#pragma unroll
    for (int r = 0; r < 3; r++) {
        float e0 = lft[r], e1 = v[r][0], e2 = v[r][1], e3 = v[r][2], e4 = v[r][3], e5 = rgt[r];
        float w0 = wv[r*3+0], w1 = wv[r*3+1], w2 = wv[r*3+2];
        o0 += w0*e0 + w1*e1 + w2*e2;
        o1 += w0*e1 + w1*e2 + w2*e3;
        o2 += w0*e2 + w1*e3 + w2*e4;
        o3 += w0*e3 + w1*e4 + w2*e5;
    }
    if (inx) {
        __half2 h01 = __floats2half2_rn(o0, o1);
        __half2 h23 = __floats2half2_rn(o2, o3);
        size_t off = ((size_t)b*C1 + c)*HW + y*112 + x0;
        *(uint2*)&outh[off] = make_uint2(*(uint32_t*)&h01, *(uint32_t*)&h23);
    }
}

// ---------------- pooled[b][c] = mean_p relu(bn2(pw)), fp16 source ----------------
__global__ void pooled_kernel(const __half* __restrict__ x, const float* __restrict__ scale,
                              const float* __restrict__ shift, float* __restrict__ pooled) {
    int c = blockIdx.x, b = blockIdx.y;
    const __half2* p = (const __half2*)(x + ((size_t)b*C2 + c)*HW);
    float sc = scale[c], sh = shift[c];
    double s = 0;
    for (int i = threadIdx.x; i < HW/2; i += 256) {
        float2 v = __half22float2(p[i]);
        float a = v.x*sc + sh, bq = v.y*sc + sh;
        if (a > 0.f) s += a;
        if (bq > 0.f) s += bq;
    }
    __shared__ double shm[256];
    shm[threadIdx.x] = s; __syncthreads();
    for (int o = 128; o; o >>= 1) {
        if (threadIdx.x < o) shm[threadIdx.x] += shm[threadIdx.x+o];
        __syncthreads();
    }
    if (threadIdx.x == 0) pooled[b*C2 + c] = (float)(shm[0] / (double)HW);
}

// ---------------- small GEMM ----------------
__global__ void small_gemm(const float* __restrict__ in, int K,
                           const float* __restrict__ W, int ldw, int woff,
                           const float* __restrict__ bias, const float* __restrict__ aux,
                           int O, int act, float* __restrict__ out) {
    __shared__ float sin_s[BSZ*512];
    for (int i = threadIdx.x; i < BSZ*K; i += 256) sin_s[i] = in[i];
    __syncthreads();
    int warp = threadIdx.x >> 5, lane = threadIdx.x & 31;
    int o = blockIdx.x*8 + warp;
    float part[BSZ];
#pragma unroll
    for (int b = 0; b < BSZ; b++) part[b] = 0.f;
    for (int k = lane; k < K; k += 32) {
        float wv = W[(size_t)o*ldw + woff + k];
#pragma unroll
        for (int b = 0; b < BSZ; b++) part[b] += wv * sin_s[b*K + k];
    }
#pragma unroll
    for (int b = 0; b < BSZ; b++) {
        float v = part[b];
#pragma unroll
        for (int off = 16; off; off >>= 1) v += __shfl_xor_sync(0xffffffffu, v, off);
        if (lane == b) {
            if (bias) v += bias[o];
            if (act == 1) v = v > 0.f ? v : 0.f;
            else if (act == 2) v = (1.f/(1.f + expf(-v))) * aux[b*O + o];
            out[b*O + o] = v;
        }
    }
}

// ---------------- gather caption embeddings: split planes ----------------
__global__ void gather_embs(const int* __restrict__ cap, const float* __restrict__ embed,
                            __nv_bfloat16* __restrict__ eh, __nv_bfloat16* __restrict__ el) {
    int row = blockIdx.x;
    int b = row >> 5, t = row & 31;
    int tok = cap[b*33 + t];
    const float* src = embed + (size_t)tok*HID;
    int i = threadIdx.x*2;
    float2 v = *(const float2*)&src[i];
    float h0,l0,h1,l1;
    split2(v.x,h0,l0); split2(v.y,h1,l1);
    *(uint32_t*)&eh[(size_t)row*HID + i] = pack_bf2(h0,h1);
    *(uint32_t*)&el[(size_t)row*HID + i] = pack_bf2(l0,l1);
}

// ---------------- persistent GRU ----------------
__global__ void gru_reset() {
    if (threadIdx.x < TT) g_gbar[threadIdx.x] = 0;
}
#define GRU_BLKS 64
__global__ void __launch_bounds__(256) gru_persist(
        const float* __restrict__ gi, const float* __restrict__ whh,
        const float* __restrict__ bhh, float* __restrict__ hall,
        __nv_bfloat16* __restrict__ hallh, __nv_bfloat16* __restrict__ halll) {
    __shared__ float hs[BSZ*HID];
    int tid = threadIdx.x;
    int warp = tid >> 5, lane = tid & 31;
    int j = blockIdx.x*8 + warp;
    float w0[16], w1[16], w2[16];
#pragma unroll
    for (int i = 0; i < 16; i++) {
        int k = lane + 32*i;
        w0[i] = whh[(size_t)j*HID + k];
        w1[i] = whh[(size_t)(j + 512)*HID + k];
        w2[i] = whh[(size_t)(j + 1024)*HID + k];
    }
    float bhr = bhh[j], bhz = bhh[j + 512], bhn = bhh[j + 1024];

    for (int t = 0; t < TT; t++) {
        for (int i = tid; i < BSZ*HID; i += 256) {
            int b = i >> 9, jj = i & 511;
            hs[i] = (t == 0) ? 0.f : hall[((size_t)(b*TT + t - 1))*HID + jj];
        }
        __syncthreads();
        for (int b = 0; b < BSZ; b++) {
            float pr = 0.f, pz = 0.f, pn = 0.f;
#pragma unroll
            for (int i = 0; i < 16; i++) {
                float hv = hs[b*HID + lane + 32*i];
                pr += hv*w0[i]; pz += hv*w1[i]; pn += hv*w2[i];
            }
#pragma unroll
            for (int o = 16; o; o >>= 1) {
                pr += __shfl_xor_sync(0xffffffffu, pr, o);
                pz += __shfl_xor_sync(0xffffffffu, pz, o);
                pn += __shfl_xor_sync(0xffffffffu, pn, o);
            }
            if (lane == 0) {
                size_t gib = ((size_t)(b*TT + t))*1536;
                float ir = gi[gib + j], iz = gi[gib + 512 + j], inn = gi[gib + 1024 + j];
                float r = 1.f/(1.f + expf(-(ir + pr + bhr)));
                float z = 1.f/(1.f + expf(-(iz + pz + bhz)));
                float n = tanhf(inn + r*(pn + bhn));
                float hp = hs[b*HID + j];
                float hn2 = (1.f - z)*n + z*hp;
                size_t oidx = ((size_t)(b*TT + t))*HID + j;
                hall[oidx] = hn2;
                float hh, hl;
                split2(hn2, hh, hl);
                hallh[oidx] = __float2bfloat16(hh);
                halll[oidx] = __float2bfloat16(hl);
            }
        }
        __threadfence();
        __syncthreads();
        if (tid == 0) {
            atomicAdd(&g_gbar[t], 1);
            while (atomicAdd(&g_gbar[t], 0) < GRU_BLKS) __nanosleep(64);
        }
        __syncthreads();
    }
}

// =======================================================================
extern "C" void kernel_launch(void* const* d_in, const int* in_sizes, int n_in,
                              void* d_out, int out_size) {
    const float* images   = (const float*)d_in[0];
    const int*   captions = (const int*)  d_in[1];
    const float* conv1_w  = (const float*)d_in[2];
    const float* bn1_g    = (const float*)d_in[3];
    const float* bn1_b    = (const float*)d_in[4];
    const float* dw_w     = (const float*)d_in[5];
    const float* pw_w     = (const float*)d_in[6];
    const float* bn2_g    = (const float*)d_in[7];
    const float* bn2_b    = (const float*)d_in[8];
    const float* se_fc1_w = (const float*)d_in[9];
    const float* se_fc2_w = (const float*)d_in[10];
    const float* enc_fc_w = (const float*)d_in[11];
    const float* enc_fc_b = (const float*)d_in[12];
    const float* embed    = (const float*)d_in[13];
    // d_in[14] = q_w (unused), d_in[15] = k_w (unused)
    const float* v_w      = (const float*)d_in[16];
    const float* gru_w_ih = (const float*)d_in[17];
    const float* gru_w_hh = (const float*)d_in[18];
    const float* gru_b_ih = (const float*)d_in[19];
    const float* gru_b_hh = (const float*)d_in[20];
    const float* fc_w     = (const float*)d_in[21];
    const float* fc_b     = (const float*)d_in[22];

    __half *conv1buf;
    double *part;
    double2 *part2;
    float *scale1, *shift1, *scale2, *shift2;
    float *pooled, *t1, *fbuf, *feats, *ctx, *gctx, *gi, *hall;
    __half *dwh, *pwwh, *pwout;
    __nv_bfloat16 *fcwh, *fcwl, *wihh, *wihl, *embsh, *embsl, *hallh, *halll;
    cudaGetSymbolAddress((void**)&conv1buf, g_conv1);
    cudaGetSymbolAddress((void**)&part,     g_part);
    cudaGetSymbolAddress((void**)&part2,    g_part2);
    cudaGetSymbolAddress((void**)&scale1,   g_scale1);
    cudaGetSymbolAddress((void**)&shift1,   g_shift1);
    cudaGetSymbolAddress((void**)&scale2,   g_scale2);
    cudaGetSymbolAddress((void**)&shift2,   g_shift2);
    cudaGetSymbolAddress((void**)&pooled,   g_pooled);
    cudaGetSymbolAddress((void**)&t1,       g_t1);
    cudaGetSymbolAddress((void**)&fbuf,     g_f);
    cudaGetSymbolAddress((void**)&feats,    g_feats);
    cudaGetSymbolAddress((void**)&ctx,      g_ctx);
    cudaGetSymbolAddress((void**)&gctx,     g_gctx);
    cudaGetSymbolAddress((void**)&gi,       g_gi);
    cudaGetSymbolAddress((void**)&hall,     g_hall);
    cudaGetSymbolAddress((void**)&dwh,      g_dwh);
    cudaGetSymbolAddress((void**)&pwwh,     g_pwwh);
    cudaGetSymbolAddress((void**)&pwout,    g_pwout);
    cudaGetSymbolAddress((void**)&fcwh,     g_fcwh);
    cudaGetSymbolAddress((void**)&fcwl,     g_fcwl);
    cudaGetSymbolAddress((void**)&wihh,     g_wihh);
    cudaGetSymbolAddress((void**)&wihl,     g_wihl);
    cudaGetSymbolAddress((void**)&embsh,    g_embsh);
    cudaGetSymbolAddress((void**)&embsl,    g_embsl);
    cudaGetSymbolAddress((void**)&hallh,    g_hallh);
    cudaGetSymbolAddress((void**)&halll,    g_halll);

    cudaFuncSetAttribute(mma_gemm_nt, cudaFuncAttributeMaxDynamicSharedMemorySize, SMEM_REQ);
    cudaFuncSetAttribute(hgemm_nn,    cudaFuncAttributeMaxDynamicSharedMemorySize, HSMEM_REQ);

    // weight conversions (independent of encoder)
    to_half<<<(C2*C1)/1024, 256>>>(pw_w, pwwh, (size_t)C2*C1);
    split_mat<<<((size_t)VOC*HID)/1024, 256>>>(fc_w, fcwh, fcwl, (size_t)VOC*HID);
    split_strided<<<(1536*512)/1024, 256>>>(gru_w_ih, 1024, wihh, wihl);

    // encoder
    conv1_igemm<<<dim3(112, BSZ), 256>>>(images, conv1_w, conv1buf);
    chan_partial_h<<<dim3(C1, BSZ), 256>>>(conv1buf, C1, part);
    chan_finalize<<<1, 256>>>(C1, part, bn1_g, bn1_b, scale1, shift1);
    dw_kernel<<<dim3(14, C1, BSZ), 256>>>(conv1buf, dw_w, scale1, shift1, dwh);
    // pointwise conv (fp16 single-pass GEMM, fused BN2 stats)
    hgemm_nn<<<dim3(98, 4, BSZ), 256, HSMEM_REQ>>>(pwwh, dwh, pwout, part2,
                                                   C2, HW, C1, HW,
                                                   (size_t)C1*HW, (size_t)C2*HW);
    chan_finalize2<<<64, 256>>>(part2, bn2_g, bn2_b, scale2, shift2);
    pooled_kernel<<<dim3(C2, BSZ), 256>>>(pwout, scale2, shift2, pooled);

    // SE + encoder FC + ctx (tiny GEMMs)
    small_gemm<<<16, 256>>>(pooled, 512, se_fc1_w, 512, 0, nullptr, nullptr, 128, 1, t1);
    small_gemm<<<64, 256>>>(t1, 128, se_fc2_w, 128, 0, nullptr, pooled, 512, 2, fbuf);
    small_gemm<<<64, 256>>>(fbuf, 512, enc_fc_w, 512, 0, enc_fc_b, nullptr, 512, 0, feats);
    small_gemm<<<64, 256>>>(feats, 512, v_w, 512, 0, nullptr, nullptr, 512, 0, ctx);

    // decoder: precompute input gates
    small_gemm<<<192, 256>>>(ctx, 512, gru_w_ih, 1024, 512, gru_b_ih, nullptr, 1536, 0, gctx);
    gather_embs<<<512, 256>>>(captions, embed, embsh, embsl);
    mma_gemm_nt<<<dim3(12, 4, 1), 256, SMEM_REQ>>>(embsh, embsl, wihh, wihl, gi,
                                                   512, 1536, 512, 512, nullptr, gctx);

    // persistent GRU recurrence
    gru_reset<<<1, 32>>>();
    gru_persist<<<GRU_BLKS, 256>>>(gi, gru_w_hh, gru_b_hh, hall, hallh, halll);

    // logits: 3-pass bf16 (precision-critical, lands directly in output)
    mma_gemm_nt<<<dim3(250, 4, 1), 256, SMEM_REQ>>>(hallh, halll, fcwh, fcwl, (float*)d_out,
                                                    512, VOC, 512, 512, fc_b, nullptr);
}

// round 13
// speedup vs baseline: 1.0517x; 1.0177x over previous
#include <cuda_runtime.h>
#include <cuda_bf16.h>
#include <cuda_fp16.h>
#include <math.h>
#include <stdint.h>

#define BSZ 16
#define HW 12544
#define C1 256
#define C2 512
#define TT 32
#define HID 512
#define VOC 32000

// ---------------- scratch (static device arrays; no allocation) ----------------
__device__ __half  g_conv1[(size_t)BSZ*C1*HW];
__device__ double  g_part [C2*BSZ*2];
__device__ double2 g_part2[(size_t)C2*BSZ*98];
__device__ float   g_scale1[C1], g_shift1[C1];
__device__ float   g_scale2[C2], g_shift2[C2];
__device__ float   g_pooled[BSZ*C2], g_t1[BSZ*128], g_f[BSZ*C2], g_feats[BSZ*C2], g_ctx[BSZ*C2];
__device__ float   g_gctx[BSZ*1536];
__device__ float   g_gi  [(size_t)BSZ*TT*1536];
__device__ float   g_hall[(size_t)BSZ*TT*HID];
__device__ int     g_gbar[TT];

// fp16 planes
__device__ __half g_dwh[(size_t)BSZ*C1*HW];
__device__ __half g_pwwh[C2*C1];
__device__ __half g_pwout[(size_t)BSZ*C2*HW];
__device__ __half g_fcwh[(size_t)VOC*HID];             // fc_w hi only (fp16 2-pass)
__device__ __half g_hallh[512*HID], g_halll[512*HID];  // hall fp16 hi/lo
// bf16 hi/lo planes for the gi GEMM (3-pass, precision-critical path kept)
__device__ __nv_bfloat16 g_wihh[1536*HID],  g_wihl[1536*HID];
__device__ __nv_bfloat16 g_embsh[512*HID],  g_embsl[512*HID];

// =====================================================================
//                    helpers
// =====================================================================
__device__ __forceinline__ uint32_t smem_u32(const void* p) {
    uint32_t a;
    asm("{ .reg .u64 t; cvta.to.shared.u64 t, %1; cvt.u32.u64 %0, t; }" : "=r"(a) : "l"(p));
    return a;
}
__device__ __forceinline__ void ldsm4(uint32_t* r, uint32_t addr) {
    asm volatile("ldmatrix.sync.aligned.m8n8.x4.shared.b16 {%0,%1,%2,%3}, [%4];"
                 : "=r"(r[0]), "=r"(r[1]), "=r"(r[2]), "=r"(r[3]) : "r"(addr));
}
__device__ __forceinline__ void ldsm4t(uint32_t* r, uint32_t addr) {
    asm volatile("ldmatrix.sync.aligned.m8n8.x4.trans.shared.b16 {%0,%1,%2,%3}, [%4];"
                 : "=r"(r[0]), "=r"(r[1]), "=r"(r[2]), "=r"(r[3]) : "r"(addr));
}
__device__ __forceinline__ void mma_bf(float* d, const uint32_t* a, uint32_t b0, uint32_t b1) {
    asm volatile(
        "mma.sync.aligned.m16n8k16.row.col.f32.bf16.bf16.f32 "
        "{%0,%1,%2,%3}, {%4,%5,%6,%7}, {%8,%9}, {%0,%1,%2,%3};"
        : "+f"(d[0]), "+f"(d[1]), "+f"(d[2]), "+f"(d[3])
        : "r"(a[0]), "r"(a[1]), "r"(a[2]), "r"(a[3]), "r"(b0), "r"(b1));
}
__device__ __forceinline__ void mma_fp(float* d, const uint32_t* a, uint32_t b0, uint32_t b1) {
    asm volatile(
        "mma.sync.aligned.m16n8k16.row.col.f32.f16.f16.f32 "
        "{%0,%1,%2,%3}, {%4,%5,%6,%7}, {%8,%9}, {%0,%1,%2,%3};"
        : "+f"(d[0]), "+f"(d[1]), "+f"(d[2]), "+f"(d[3])
        : "r"(a[0]), "r"(a[1]), "r"(a[2]), "r"(a[3]), "r"(b0), "r"(b1));
}
__device__ __forceinline__ uint32_t pack_bf2(float lo, float hi) {
    uint32_t r;
    asm("cvt.rn.bf16x2.f32 %0, %1, %2;" : "=r"(r) : "f"(hi), "f"(lo));
    return r;
}
__device__ __forceinline__ void split2(float x, float& h, float& l) {
    h = __bfloat162float(__float2bfloat16(x));
    l = x - h;
}
__device__ __forceinline__ void split2h(float x, float& h, float& l) {
    h = __half2float(__float2half_rn(x));
    l = x - h;
}
__device__ __forceinline__ void cpa16(uint32_t dst, const void* src) {
    asm volatile("cp.async.cg.shared.global [%0], [%1], 16;" :: "r"(dst), "l"(src));
}
__device__ __forceinline__ void cp_commit() { asm volatile("cp.async.commit_group;"); }
template<int NW> __device__ __forceinline__ void cp_wait() {
    asm volatile("cp.async.wait_group %0;" :: "n"(NW));
}

// =====================================================================
//   conversion kernels
// =====================================================================
__global__ void split_strided(const float* __restrict__ src, int ld,
                              __nv_bfloat16* __restrict__ dh, __nv_bfloat16* __restrict__ dl) {
    size_t i = ((size_t)blockIdx.x*256 + threadIdx.x)*4;
    int row = (int)(i >> 9), col = (int)(i & 511);
    float4 v = *(const float4*)&src[(size_t)row*ld + col];
    float hx, lx, hy, ly, hz, lz, hw, lw;
    split2(v.x, hx, lx); split2(v.y, hy, ly); split2(v.z, hz, lz); split2(v.w, hw, lw);
    *(uint2*)&dh[i] = make_uint2(pack_bf2(hx, hy), pack_bf2(hz, hw));
    *(uint2*)&dl[i] = make_uint2(pack_bf2(lx, ly), pack_bf2(lz, lw));
}
__global__ void to_half(const float* __restrict__ src, __half* __restrict__ dst, size_t n) {
    size_t i = ((size_t)blockIdx.x*256 + threadIdx.x)*4;
    if (i >= n) return;
    float4 v = *(const float4*)&src[i];
    __half2 a = __floats2half2_rn(v.x, v.y), b = __floats2half2_rn(v.z, v.w);
    *(uint2*)&dst[i] = make_uint2(*(uint32_t*)&a, *(uint32_t*)&b);
}

// =====================================================================
//   bf16 3-pass GEMM (NT) — gi only
// =====================================================================
#define KTILE 32
#define LDA   80
#define PLANE 10240
#define STAGE (4*PLANE)
#define SMEM_REQ (2*STAGE + 1024)

__global__ void __launch_bounds__(256) mma_gemm_nt(
        const __nv_bfloat16* __restrict__ Ah, const __nv_bfloat16* __restrict__ Al,
        const __nv_bfloat16* __restrict__ Bh, const __nv_bfloat16* __restrict__ Bl,
        float* __restrict__ C, int M, int N, int K, int ldb,
        const float* __restrict__ bias, const float* __restrict__ rowaux) {
    extern __shared__ char dsm[];
    char* base = (char*)((((uintptr_t)dsm) + 1023) & ~(uintptr_t)1023);
    uint32_t sb0 = smem_u32(base);

    int m0 = blockIdx.y * 128, n0 = blockIdx.x * 128;
    int tid = threadIdx.x;
    int lane = tid & 31, wid = tid >> 5;
    int warp_m = wid & 3, warp_n = wid >> 2;

    float acc[2][8][4];
#pragma unroll
    for (int i = 0; i < 2; i++)
#pragma unroll
        for (int j = 0; j < 8; j++)
#pragma unroll
            for (int q = 0; q < 4; q++) acc[i][j][q] = 0.f;

    int KT = K / KTILE;

    auto load_stage = [&](int s, int kt) {
        uint32_t st = sb0 + s*STAGE;
        uint32_t ah_s = st, al_s = st + PLANE, bh_s = st + 2*PLANE, bl_s = st + 3*PLANE;
        int k0 = kt * KTILE;
#pragma unroll
        for (int i = 0; i < 2; i++) {
            int idx = tid + i*256;
            int row = idx >> 2, kc = idx & 3;
            uint32_t doff = row*LDA + kc*16;
            cpa16(ah_s + doff, Ah + (size_t)(m0 + row)*K + k0 + kc*8);
            cpa16(al_s + doff, Al + (size_t)(m0 + row)*K + k0 + kc*8);
            cpa16(bh_s + doff, Bh + (size_t)(n0 + row)*ldb + k0 + kc*8);
            cpa16(bl_s + doff, Bl + (size_t)(n0 + row)*ldb + k0 + kc*8);
        }
        cp_commit();
    };

    load_stage(0, 0);
    for (int kt = 0; kt < KT; kt++) {
        if (kt + 1 < KT) { load_stage((kt + 1) & 1, kt + 1); cp_wait<1>(); }
        else             { cp_wait<0>(); }
        __syncthreads();
        uint32_t st = sb0 + (kt & 1)*STAGE;
        uint32_t ah_b = st, al_b = st + PLANE, bh_b = st + 2*PLANE, bl_b = st + 3*PLANE;
#pragma unroll
        for (int ks = 0; ks < 2; ks++) {
            int kb = ks*16;
            uint32_t aH[2][4], aL[2][4];
#pragma unroll
            for (int im = 0; im < 2; im++) {
                int row = warp_m*32 + im*16 + (lane & 15);
                uint32_t off = row*LDA + (kb + (lane >> 4)*8)*2;
                ldsm4(aH[im], ah_b + off);
                ldsm4(aL[im], al_b + off);
            }
#pragma unroll
            for (int nc = 0; nc < 4; nc++) {
                uint32_t bH[4], bL[4];
                int row = warp_n*64 + nc*16 + (lane & 15);
                uint32_t off = row*LDA + (kb + (lane >> 4)*8)*2;
                ldsm4(bH, bh_b + off);
                ldsm4(bL, bl_b + off);
#pragma unroll
                for (int im = 0; im < 2; im++) {
                    float* a0 = acc[im][nc*2];
                    float* a1 = acc[im][nc*2 + 1];
                    mma_bf(a0, aH[im], bH[0], bH[2]);
                    mma_bf(a0, aH[im], bL[0], bL[2]);
                    mma_bf(a0, aL[im], bH[0], bH[2]);
                    mma_bf(a1, aH[im], bH[1], bH[3]);
                    mma_bf(a1, aH[im], bL[1], bL[3]);
                    mma_bf(a1, aL[im], bH[1], bH[3]);
                }
            }
        }
        __syncthreads();
    }

    int rbase = m0 + warp_m*32 + (lane >> 2);
    int cbase = n0 + warp_n*64 + (lane & 3)*2;
#pragma unroll
    for (int im = 0; im < 2; im++) {
#pragma unroll
        for (int nf = 0; nf < 8; nf++) {
            int m = rbase + im*16;
            int n = cbase + nf*8;
            float v0 = acc[im][nf][0], v1 = acc[im][nf][1];
            float v2 = acc[im][nf][2], v3 = acc[im][nf][3];
            if (bias)   { float b0 = bias[n], b1 = bias[n+1]; v0 += b0; v1 += b1; v2 += b0; v3 += b1; }
            if (rowaux) {
                float r0 = rowaux[(size_t)(m >> 5)*N + n],     r1 = rowaux[(size_t)(m >> 5)*N + n + 1];
                float r2 = rowaux[(size_t)((m+8) >> 5)*N + n], r3 = rowaux[(size_t)((m+8) >> 5)*N + n + 1];
                v0 += r0; v1 += r1; v2 += r2; v3 += r3;
            }
            *(float2*)&C[(size_t)m*N + n]     = make_float2(v0, v1);
            *(float2*)&C[(size_t)(m+8)*N + n] = make_float2(v2, v3);
        }
    }
}

// =====================================================================
//   fp16 2-pass GEMM (NT): D = (Ah+Al) @ Bh^T  — logits
// =====================================================================
#define H2STAGE (3*PLANE)
#define H2SMEM_REQ (2*H2STAGE + 1024)

__global__ void __launch_bounds__(256) mma_gemm_nt_h2(
        const __half* __restrict__ Ah, const __half* __restrict__ Al,
        const __half* __restrict__ Bh,
        float* __restrict__ C, int M, int N, int K, int ldb,
        const float* __restrict__ bias) {
    extern __shared__ char dsm[];
    char* base = (char*)((((uintptr_t)dsm) + 1023) & ~(uintptr_t)1023);
    uint32_t sb0 = smem_u32(base);

    int m0 = blockIdx.y * 128, n0 = blockIdx.x * 128;
    int tid = threadIdx.x;
    int lane = tid & 31, wid = tid >> 5;
    int warp_m = wid & 3, warp_n = wid >> 2;

    float acc[2][8][4];
#pragma unroll
    for (int i = 0; i < 2; i++)
#pragma unroll
        for (int j = 0; j < 8; j++)
#pragma unroll
            for (int q = 0; q < 4; q++) acc[i][j][q] = 0.f;

    int KT = K / KTILE;

    auto load_stage = [&](int s, int kt) {
        uint32_t st = sb0 + s*H2STAGE;
        uint32_t ah_s = st, al_s = st + PLANE, bh_s = st + 2*PLANE;
        int k0 = kt * KTILE;
#pragma unroll
        for (int i = 0; i < 2; i++) {
            int idx = tid + i*256;
            int row = idx >> 2, kc = idx & 3;
            uint32_t doff = row*LDA + kc*16;
            cpa16(ah_s + doff, Ah + (size_t)(m0 + row)*K + k0 + kc*8);
            cpa16(al_s + doff, Al + (size_t)(m0 + row)*K + k0 + kc*8);
            cpa16(bh_s + doff, Bh + (size_t)(n0 + row)*ldb + k0 + kc*8);
        }
        cp_commit();
    };

    load_stage(0, 0);
    for (int kt = 0; kt < KT; kt++) {
        if (kt + 1 < KT) { load_stage((kt + 1) & 1, kt + 1); cp_wait<1>(); }
        else             { cp_wait<0>(); }
        __syncthreads();
        uint32_t st = sb0 + (kt & 1)*H2STAGE;
        uint32_t ah_b = st, al_b = st + PLANE, bh_b = st + 2*PLANE;
#pragma unroll
        for (int ks = 0; ks < 2; ks++) {
            int kb = ks*16;
            uint32_t aH[2][4], aL[2][4];
#pragma unroll
            for (int im = 0; im < 2; im++) {
                int row = warp_m*32 + im*16 + (lane & 15);
                uint32_t off = row*LDA + (kb + (lane >> 4)*8)*2;
                ldsm4(aH[im], ah_b + off);
                ldsm4(aL[im], al_b + off);
            }
#pragma unroll
            for (int nc = 0; nc < 4; nc++) {
                uint32_t bH[4];
                int row = warp_n*64 + nc*16 + (lane & 15);
                ldsm4(bH, bh_b + row*LDA + (kb + (lane >> 4)*8)*2);
#pragma unroll
                for (int im = 0; im < 2; im++) {
                    float* a0 = acc[im][nc*2];
                    float* a1 = acc[im][nc*2 + 1];
                    mma_fp(a0, aH[im], bH[0], bH[2]);
                    mma_fp(a0, aL[im], bH[0], bH[2]);
                    mma_fp(a1, aH[im], bH[1], bH[3]);
                    mma_fp(a1, aL[im], bH[1], bH[3]);
                }
            }
        }
        __syncthreads();
    }

    int rbase = m0 + warp_m*32 + (lane >> 2);
    int cbase = n0 + warp_n*64 + (lane & 3)*2;
#pragma unroll
    for (int im = 0; im < 2; im++) {
#pragma unroll
        for (int nf = 0; nf < 8; nf++) {
            int m = rbase + im*16;
            int n = cbase + nf*8;
            float v0 = acc[im][nf][0], v1 = acc[im][nf][1];
            float v2 = acc[im][nf][2], v3 = acc[im][nf][3];
            if (bias) { float b0 = bias[n], b1 = bias[n+1]; v0 += b0; v1 += b1; v2 += b0; v3 += b1; }
            *(float2*)&C[(size_t)m*N + n]     = make_float2(v0, v1);
            *(float2*)&C[(size_t)(m+8)*N + n] = make_float2(v2, v3);
        }
    }
}

// =====================================================================
//   fp16 single-pass GEMM (NN) with fused per-row stats — pointwise conv
//   Grid: (m-tiles fast, n-tiles, batch) so the 4 m-tiles sharing a B
//   slice are adjacent -> B read once from DRAM (was 4x).
// =====================================================================
#define HKT 64
#define HLDA 144
#define HLDB 272
#define HPA (128*HLDA)
#define HPB (64*HLDB)
#define HSTAGE (HPA + HPB)
#define HSMEM_REQ (2*HSTAGE + 1024)

__global__ void __launch_bounds__(256) hgemm_nn(
        const __half* __restrict__ A, const __half* __restrict__ B,
        __half* __restrict__ C, double2* __restrict__ part,
        int M, int N, int K, int ldb, size_t strideB, size_t strideC) {
    extern __shared__ char dsm[];
    char* base = (char*)((((uintptr_t)dsm) + 1023) & ~(uintptr_t)1023);
    uint32_t sb0 = smem_u32(base);

    const __half* Bb = B + (size_t)blockIdx.z * strideB;
    __half* Cb = C + (size_t)blockIdx.z * strideC;
    int m0 = blockIdx.x * 128, n0 = blockIdx.y * 128;   // m fast
    int nidx = blockIdx.y;
    int tid = threadIdx.x;
    int lane = tid & 31, wid = tid >> 5;
    int warp_m = wid & 3, warp_n = wid >> 2;

    float acc[2][8][4];
#pragma unroll
    for (int i = 0; i < 2; i++)
#pragma unroll
        for (int j = 0; j < 8; j++)
#pragma unroll
            for (int q = 0; q < 4; q++) acc[i][j][q] = 0.f;

    int KT = K / HKT;   // 4

    auto load_stage = [&](int s, int kt) {
        uint32_t st = sb0 + s*HSTAGE;
        uint32_t as = st, bs = st + HPA;
        int k0 = kt * HKT;
#pragma unroll
        for (int i = 0; i < 4; i++) {
            int idx = tid + i*256;
            int row = idx >> 3, kc = idx & 7;
            cpa16(as + row*HLDA + kc*16, A + (size_t)(m0 + row)*K + k0 + kc*8);
        }
#pragma unroll
        for (int i = 0; i < 4; i++) {
            int idx = tid + i*256;
            int row = idx >> 4, c = idx & 15;
            cpa16(bs + row*HLDB + c*16, Bb + (size_t)(k0 + row)*ldb + n0 + c*8);
        }
        cp_commit();
    };

    load_stage(0, 0);
    for (int kt = 0; kt < KT; kt++) {
        if (kt + 1 < KT) { load_stage((kt + 1) & 1, kt + 1); cp_wait<1>(); }
        else             { cp_wait<0>(); }
        __syncthreads();
        uint32_t st = sb0 + (kt & 1)*HSTAGE;
        uint32_t as = st, bs = st + HPA;
#pragma unroll
        for (int ks = 0; ks < 4; ks++) {
            int kb = ks*16;
            uint32_t aF[2][4];
#pragma unroll
            for (int im = 0; im < 2; im++) {
                int row = warp_m*32 + im*16 + (lane & 15);
                uint32_t off = row*HLDA + (kb + (lane >> 4)*8)*2;
                ldsm4(aF[im], as + off);
            }
#pragma unroll
            for (int nc = 0; nc < 4; nc++) {
                uint32_t bF[4];
                int row = kb + (lane & 15);
                int col = warp_n*64 + nc*16 + (lane >> 4)*8;
                ldsm4t(bF, bs + row*HLDB + col*2);
#pragma unroll
                for (int im = 0; im < 2; im++) {
                    mma_fp(acc[im][nc*2],     aF[im], bF[0], bF[1]);
                    mma_fp(acc[im][nc*2 + 1], aF[im], bF[2], bF[3]);
                }
            }
        }
        __syncthreads();
    }

    // ---- epilogue: fp16 store + per-row (channel) sum/sumsq ----
    int rloc = warp_m*32 + (lane >> 2);
    int cbase = n0 + warp_n*64 + (lane & 3)*2;
    float s[4]  = {0.f, 0.f, 0.f, 0.f};
    float s2[4] = {0.f, 0.f, 0.f, 0.f};
#pragma unroll
    for (int im = 0; im < 2; im++) {
#pragma unroll
        for (int nf = 0; nf < 8; nf++) {
            int m = m0 + rloc + im*16;
            int n = cbase + nf*8;
            float v0 = acc[im][nf][0], v1 = acc[im][nf][1];
            float v2 = acc[im][nf][2], v3 = acc[im][nf][3];
            __half2 h01 = __floats2half2_rn(v0, v1);
            __half2 h23 = __floats2half2_rn(v2, v3);
            *(__half2*)&Cb[(size_t)m*N + n]     = h01;
            *(__half2*)&Cb[(size_t)(m+8)*N + n] = h23;
            s [im*2+0] += v0 + v1;    s2[im*2+0] += v0*v0 + v1*v1;
            s [im*2+1] += v2 + v3;    s2[im*2+1] += v2*v2 + v3*v3;
        }
    }
#pragma unroll
    for (int r = 0; r < 4; r++) {
        s [r] += __shfl_xor_sync(0xffffffffu, s [r], 1);
        s [r] += __shfl_xor_sync(0xffffffffu, s [r], 2);
        s2[r] += __shfl_xor_sync(0xffffffffu, s2[r], 1);
        s2[r] += __shfl_xor_sync(0xffffffffu, s2[r], 2);
    }
    float2* sst = (float2*)base;
    __syncthreads();
    if ((lane & 3) == 0) {
#pragma unroll
        for (int r = 0; r < 4; r++) {
            int row = rloc + (r >> 1)*16 + (r & 1)*8;
            sst[warp_n*128 + row] = make_float2(s[r], s2[r]);
        }
    }
    __syncthreads();
    if (tid < 128) {
        float2 a = sst[tid], b = sst[128 + tid];
        double2 p;
        p.x = (double)a.x + (double)b.x;
        p.y = (double)a.y + (double)b.y;
        part[(size_t)(m0 + tid)*(BSZ*98) + blockIdx.z*98 + nidx] = p;
    }
}

// finalize BN2 scale/shift from fused partials; warp per channel
__global__ void chan_finalize2(const double2* __restrict__ part,
                               const float* __restrict__ g, const float* __restrict__ bt,
                               float* __restrict__ scale, float* __restrict__ shift) {
    int warp = (blockIdx.x*256 + threadIdx.x) >> 5;
    int lane = threadIdx.x & 31;
    if (warp >= C2) return;
    double s = 0, s2 = 0;
    for (int i = lane; i < BSZ*98; i += 32) {
        double2 p = part[(size_t)warp*(BSZ*98) + i];
        s += p.x; s2 += p.y;
    }
#pragma unroll
    for (int o = 16; o; o >>= 1) {
        s  += __shfl_xor_sync(0xffffffffu, s,  o);
        s2 += __shfl_xor_sync(0xffffffffu, s2, o);
    }
    if (lane == 0) {
        double cnt = (double)BSZ * HW;
        double m = s / cnt;
        double var = s2 / cnt - m*m;
        float rs = (float)(1.0 / sqrt(var + 1e-5));
        float sc = g[warp] * rs;
        scale[warp] = sc;
        shift[warp] = bt[warp] - (float)m * sc;
    }
}

// =====================================================================
//   conv1 as fp16 implicit GEMM
// =====================================================================
__global__ void __launch_bounds__(256) conv1_igemm(
        const float* __restrict__ img, const float* __restrict__ w,
        __half* __restrict__ out) {
    __shared__ __half wt [256*40];
    __shared__ __half imt[128*40];
    __shared__ float  inr[9*224];
    int oy = blockIdx.x, b = blockIdx.y;
    int tid = threadIdx.x;
    int lane = tid & 31, wid = tid >> 5;

    for (int i = tid; i < 256*32; i += 256) {
        int c = i >> 5, k = i & 31;
        float v = (k < 27) ? __ldg(&w[c*27 + k]) : 0.f;
        wt[c*40 + k] = __float2half_rn(v);
    }
    const float* ip = img + (size_t)b*3*224*224;
    for (int i = tid; i < 9*224; i += 256) {
        int r = i / 224, x = i - r*224;
        int ci = r / 3, ky = r - ci*3;
        int iy = oy*2 - 1 + ky;
        inr[i] = (iy >= 0 && iy < 224) ? ip[(ci*224 + iy)*224 + x] : 0.f;
    }
    __syncthreads();
    for (int i = tid; i < 128*32; i += 256) {
        int p = i >> 5, k = i & 31;
        float v = 0.f;
        if (p < 112 && k < 27) {
            int ci = k / 9, r = k - ci*9;
            int ky = r / 3, kx = r - ky*3;
            int ix = p*2 - 1 + kx;
            if (ix >= 0 && ix < 224) v = inr[(ci*3 + ky)*224 + ix];
        }
        imt[p*40 + k] = __float2half_rn(v);
    }
    __syncthreads();

    uint32_t wt_b = smem_u32(wt), imt_b = smem_u32(imt);
    size_t obase = (size_t)b*C1*HW + (size_t)oy*112;
#pragma unroll
    for (int half = 0; half < 2; half++) {
        float acc[2][8][4];
#pragma unroll
        for (int i = 0; i < 2; i++)
#pragma unroll
            for (int j = 0; j < 8; j++)
#pragma unroll
                for (int q = 0; q < 4; q++) acc[i][j][q] = 0.f;
#pragma unroll
        for (int ks = 0; ks < 2; ks++) {
            int kb = ks*16;
            uint32_t aF[2][4];
#pragma unroll
            for (int im = 0; im < 2; im++) {
                int row = wid*32 + im*16 + (lane & 15);
                ldsm4(aF[im], wt_b + (row*40 + kb + (lane >> 4)*8)*2);
            }
#pragma unroll
            for (int nc = 0; nc < 4; nc++) {
                uint32_t bF[4];
                int row = half*64 + nc*16 + (lane & 15);
                ldsm4(bF, imt_b + (row*40 + kb + (lane >> 4)*8)*2);
#pragma unroll
                for (int im = 0; im < 2; im++) {
                    mma_fp(acc[im][nc*2],     aF[im], bF[0], bF[2]);
                    mma_fp(acc[im][nc*2 + 1], aF[im], bF[1], bF[3]);
                }
            }
        }
#pragma unroll
        for (int im = 0; im < 2; im++) {
#pragma unroll
            for (int nf = 0; nf < 8; nf++) {
                int m = wid*32 + im*16 + (lane >> 2);
                int n = half*64 + nf*8 + (lane & 3)*2;
                if (n < 112) {
                    __half2 h01 = __floats2half2_rn(acc[im][nf][0], acc[im][nf][1]);
                    __half2 h23 = __floats2half2_rn(acc[im][nf][2], acc[im][nf][3]);
                    *(__half2*)&out[obase + (size_t)m*HW + n]     = h01;
                    *(__half2*)&out[obase + (size_t)(m+8)*HW + n] = h23;
                }
            }
        }
    }
}

// ---------------- per-channel stats from fp16 (two-stage, double) ----------------
__global__ void chan_partial_h(const __half* __restrict__ x, int C, double* __restrict__ part) {
    int c = blockIdx.x, b = blockIdx.y;
    const __half2* p = (const __half2*)(x + ((size_t)b*C + c)*HW);
    double s = 0, s2 = 0;
    for (int i = threadIdx.x; i < HW/2; i += 256) {
        float2 v = __half22float2(p[i]);
        s += (double)v.x + (double)v.y;
        s2 += (double)v.x*v.x + (double)v.y*v.y;
    }
    __shared__ double sh[256], sh2[256];
    sh[threadIdx.x] = s; sh2[threadIdx.x] = s2; __syncthreads();
    for (int o = 128; o; o >>= 1) {
        if (threadIdx.x < o) { sh[threadIdx.x] += sh[threadIdx.x+o]; sh2[threadIdx.x] += sh2[threadIdx.x+o]; }
        __syncthreads();
    }
    if (threadIdx.x == 0) { part[(c*BSZ + b)*2] = sh[0]; part[(c*BSZ + b)*2 + 1] = sh2[0]; }
}
__global__ void chan_finalize(int C, const double* __restrict__ part,
                              const float* __restrict__ g, const float* __restrict__ bt,
                              float* __restrict__ scale, float* __restrict__ shift) {
    int c = blockIdx.x*blockDim.x + threadIdx.x;
    if (c >= C) return;
    double s = 0, s2 = 0;
    for (int b = 0; b < BSZ; b++) { s += part[(c*BSZ+b)*2]; s2 += part[(c*BSZ+b)*2 + 1]; }
    double cnt = (double)BSZ * HW;
    double m = s / cnt;
    double var = s2 / cnt - m*m;
    float rs = (float)(1.0 / sqrt(var + 1e-5));
    float sc = g[c] * rs;
    scale[c] = sc;
    shift[c] = bt[c] - (float)m * sc;
}

// ---------------- depthwise 3x3 s1 p1 (BN1+ReLU fused), fp16 in/out -------------
__global__ void dw_kernel(const __half* __restrict__ in, const float* __restrict__ w,
                          const float* __restrict__ scale, const float* __restrict__ shift,
                          __half* __restrict__ outh) {
    int warp = threadIdx.x >> 5, lane = threadIdx.x & 31;
    int y = blockIdx.x*8 + warp;
    int c = blockIdx.y, b = blockIdx.z;
    float sc = scale[c], sh = shift[c];
    const __half* ip = in + ((size_t)b*C1 + c)*HW;
    int x0 = lane*4;
    bool inx = (x0 < 112);

    float v[3][4];
    float lft[3], rgt[3];
#pragma unroll
    for (int r = 0; r < 3; r++) {
        int yy = y - 1 + r;
        float t0 = 0.f, t1 = 0.f, t2 = 0.f, t3 = 0.f;
        if (inx && yy >= 0 && yy < 112) {
            uint2 u = *(const uint2*)&ip[yy*112 + x0];
            float2 p0 = __half22float2(*(__half2*)&u.x);
            float2 p1 = __half22float2(*(__half2*)&u.y);
            t0 = p0.x; t1 = p0.y; t2 = p1.x; t3 = p1.y;
        }
        v[r][0] = fmaxf(t0*sc + sh, 0.f);
        v[r][1] = fmaxf(t1*sc + sh, 0.f);
        v[r][2] = fmaxf(t2*sc + sh, 0.f);
        v[r][3] = fmaxf(t3*sc + sh, 0.f);
        if (!inx || yy < 0 || yy >= 112) { v[r][0]=v[r][1]=v[r][2]=v[r][3]=0.f; }
        lft[r] = __shfl_up_sync(0xffffffffu, v[r][3], 1);
        if (lane == 0) lft[r] = 0.f;
        rgt[r] = __shfl_down_sync(0xffffffffu, v[r][0], 1);
        if (lane >= 27) rgt[r] = 0.f;
    }
    float wv[9];
#pragma unroll
    for (int k = 0; k < 9; k++) wv[k] = __ldg(&w[c*9 + k]);

    float o0 = 0.f, o1 = 0.f, o2 = 0.f, o3 = 0.f;
#pragma unroll
    for (int r = 0; r < 3; r++) {
        float e0 = lft[r], e1 = v[r][0], e2 = v[r][1], e3 = v[r][2], e4 = v[r][3], e5 = rgt[r];
        float w0 = wv[r*3+0], w1 = wv[r*3+1], w2 = wv[r*3+2];
        o0 += w0*e0 + w1*e1 + w2*e2;
        o1 += w0*e1 + w1*e2 + w2*e3;
        o2 += w0*e2 + w1*e3 + w2*e4;
        o3 += w0*e3 + w1*e4 + w2*e5;
    }
    if (inx) {
        __half2 h01 = __floats2half2_rn(o0, o1);
        __half2 h23 = __floats2half2_rn(o2, o3);
        size_t off = ((size_t)b*C1 + c)*HW + y*112 + x0;
        *(uint2*)&outh[off] = make_uint2(*(uint32_t*)&h01, *(uint32_t*)&h23);
    }
}

// ---------------- pooled[b][c] = mean_p relu(bn2(pw)), fp16 source ----------------
__global__ void pooled_kernel(const __half* __restrict__ x, const float* __restrict__ scale,
                              const float* __restrict__ shift, float* __restrict__ pooled) {
    int c = blockIdx.x, b = blockIdx.y;
    const __half2* p = (const __half2*)(x + ((size_t)b*C2 + c)*HW);
    float sc = scale[c], sh = shift[c];
    double s = 0;
    for (int i = threadIdx.x; i < HW/2; i += 256) {
        float2 v = __half22float2(p[i]);
        float a = v.x*sc + sh, bq = v.y*sc + sh;
        if (a > 0.f) s += a;
        if (bq > 0.f) s += bq;
    }
    __shared__ double shm[256];
    shm[threadIdx.x] = s; __syncthreads();
    for (int o = 128; o; o >>= 1) {
        if (threadIdx.x < o) shm[threadIdx.x] += shm[threadIdx.x+o];
        __syncthreads();
    }
    if (threadIdx.x == 0) pooled[b*C2 + c] = (float)(shm[0] / (double)HW);
}

// ---------------- small GEMM ----------------
__global__ void small_gemm(const float* __restrict__ in, int K,
                           const float* __restrict__ W, int ldw, int woff,
                           const float* __restrict__ bias, const float* __restrict__ aux,
                           int O, int act, float* __restrict__ out) {
    __shared__ float sin_s[BSZ*512];
    for (int i = threadIdx.x; i < BSZ*K; i += 256) sin_s[i] = in[i];
    __syncthreads();
    int warp = threadIdx.x >> 5, lane = threadIdx.x & 31;
    int o = blockIdx.x*8 + warp;
    float part[BSZ];
#pragma unroll
    for (int b = 0; b < BSZ; b++) part[b] = 0.f;
    for (int k = lane; k < K; k += 32) {
        float wv = W[(size_t)o*ldw + woff + k];
#pragma unroll
        for (int b = 0; b < BSZ; b++) part[b] += wv * sin_s[b*K + k];
    }
#pragma unroll
    for (int b = 0; b < BSZ; b++) {
        float v = part[b];
#pragma unroll
        for (int off = 16; off; off >>= 1) v += __shfl_xor_sync(0xffffffffu, v, off);
        if (lane == b) {
            if (bias) v += bias[o];
            if (act == 1) v = v > 0.f ? v : 0.f;
            else if (act == 2) v = (1.f/(1.f + expf(-v))) * aux[b*O + o];
            out[b*O + o] = v;
        }
    }
}

// ---------------- gather caption embeddings: bf16 split planes ----------------
__global__ void gather_embs(const int* __restrict__ cap, const float* __restrict__ embed,
                            __nv_bfloat16* __restrict__ eh, __nv_bfloat16* __restrict__ el) {
    int row = blockIdx.x;
    int b = row >> 5, t = row & 31;
    int tok = cap[b*33 + t];
    const float* src = embed + (size_t)tok*HID;
    int i = threadIdx.x*2;
    float2 v = *(const float2*)&src[i];
    float h0,l0,h1,l1;
    split2(v.x,h0,l0); split2(v.y,h1,l1);
    *(uint32_t*)&eh[(size_t)row*HID + i] = pack_bf2(h0,h1);
    *(uint32_t*)&el[(size_t)row*HID + i] = pack_bf2(l0,l1);
}

// ---------------- persistent GRU (hall fp16 hi/lo for logits) ----------------
__global__ void gru_reset() {
    if (threadIdx.x < TT) g_gbar[threadIdx.x] = 0;
}
#define GRU_BLKS 64
__global__ void __launch_bounds__(256) gru_persist(
        const float* __restrict__ gi, const float* __restrict__ whh,
        const float* __restrict__ bhh, float* __restrict__ hall,
        __half* __restrict__ hallh, __half* __restrict__ halll) {
    __shared__ float hs[BSZ*HID];
    int tid = threadIdx.x;
    int warp = tid >> 5, lane = tid & 31;
    int j = blockIdx.x*8 + warp;
    float w0[16], w1[16], w2[16];
#pragma unroll
    for (int i = 0; i < 16; i++) {
        int k = lane + 32*i;
        w0[i] = whh[(size_t)j*HID + k];
        w1[i] = whh[(size_t)(j + 512)*HID + k];
        w2[i] = whh[(size_t)(j + 1024)*HID + k];
    }
    float bhr = bhh[j], bhz = bhh[j + 512], bhn = bhh[j + 1024];

    for (int t = 0; t < TT; t++) {
        for (int i = tid; i < BSZ*HID; i += 256) {
            int b = i >> 9, jj = i & 511;
            hs[i] = (t == 0) ? 0.f : hall[((size_t)(b*TT + t - 1))*HID + jj];
        }
        __syncthreads();
        for (int b = 0; b < BSZ; b++) {
            float pr = 0.f, pz = 0.f, pn = 0.f;
#pragma unroll
            for (int i = 0; i < 16; i++) {
                float hv = hs[b*HID + lane + 32*i];
                pr += hv*w0[i]; pz += hv*w1[i]; pn += hv*w2[i];
            }
#pragma unroll
            for (int o = 16; o; o >>= 1) {
                pr += __shfl_xor_sync(0xffffffffu, pr, o);
                pz += __shfl_xor_sync(0xffffffffu, pz, o);
                pn += __shfl_xor_sync(0xffffffffu, pn, o);
            }
            if (lane == 0) {
                size_t gib = ((size_t)(b*TT + t))*1536;
                float ir = gi[gib + j], iz = gi[gib + 512 + j], inn = gi[gib + 1024 + j];
                float r = 1.f/(1.f + expf(-(ir + pr + bhr)));
                float z = 1.f/(1.f + expf(-(iz + pz + bhz)));
                float n = tanhf(inn + r*(pn + bhn));
                float hp = hs[b*HID + j];
                float hn2 = (1.f - z)*n + z*hp;
                size_t oidx = ((size_t)(b*TT + t))*HID + j;
                hall[oidx] = hn2;
                float hh, hl;
                split2h(hn2, hh, hl);
                hallh[oidx] = __float2half_rn(hh);
                halll[oidx] = __float2half_rn(hl);
            }
        }
        __threadfence();
        __syncthreads();
        if (tid == 0) {
            atomicAdd(&g_gbar[t], 1);
            while (atomicAdd(&g_gbar[t], 0) < GRU_BLKS) __nanosleep(64);
        }
        __syncthreads();
    }
}

// =======================================================================
extern "C" void kernel_launch(void* const* d_in, const int* in_sizes, int n_in,
                              void* d_out, int out_size) {
    const float* images   = (const float*)d_in[0];
    const int*   captions = (const int*)  d_in[1];
    const float* conv1_w  = (const float*)d_in[2];
    const float* bn1_g    = (const float*)d_in[3];
    const float* bn1_b    = (const float*)d_in[4];
    const float* dw_w     = (const float*)d_in[5];
    const float* pw_w     = (const float*)d_in[6];
    const float* bn2_g    = (const float*)d_in[7];
    const float* bn2_b    = (const float*)d_in[8];
    const float* se_fc1_w = (const float*)d_in[9];
    const float* se_fc2_w = (const float*)d_in[10];
    const float* enc_fc_w = (const float*)d_in[11];
    const float* enc_fc_b = (const float*)d_in[12];
    const float* embed    = (const float*)d_in[13];
    // d_in[14] = q_w (unused), d_in[15] = k_w (unused)
    const float* v_w      = (const float*)d_in[16];
    const float* gru_w_ih = (const float*)d_in[17];
    const float* gru_w_hh = (const float*)d_in[18];
    const float* gru_b_ih = (const float*)d_in[19];
    const float* gru_b_hh = (const float*)d_in[20];
    const float* fc_w     = (const float*)d_in[21];
    const float* fc_b     = (const float*)d_in[22];

    __half *conv1buf;
    double *part;
    double2 *part2;
    float *scale1, *shift1, *scale2, *shift2;
    float *pooled, *t1, *fbuf, *feats, *ctx, *gctx, *gi, *hall;
    __half *dwh, *pwwh, *pwout, *fcwh, *hallh, *halll;
    __nv_bfloat16 *wihh, *wihl, *embsh, *embsl;
    cudaGetSymbolAddress((void**)&conv1buf, g_conv1);
    cudaGetSymbolAddress((void**)&part,     g_part);
    cudaGetSymbolAddress((void**)&part2,    g_part2);
    cudaGetSymbolAddress((void**)&scale1,   g_scale1);
    cudaGetSymbolAddress((void**)&shift1,   g_shift1);
    cudaGetSymbolAddress((void**)&scale2,   g_scale2);
    cudaGetSymbolAddress((void**)&shift2,   g_shift2);
    cudaGetSymbolAddress((void**)&pooled,   g_pooled);
    cudaGetSymbolAddress((void**)&t1,       g_t1);
    cudaGetSymbolAddress((void**)&fbuf,     g_f);
    cudaGetSymbolAddress((void**)&feats,    g_feats);
    cudaGetSymbolAddress((void**)&ctx,      g_ctx);
    cudaGetSymbolAddress((void**)&gctx,     g_gctx);
    cudaGetSymbolAddress((void**)&gi,       g_gi);
    cudaGetSymbolAddress((void**)&hall,     g_hall);
    cudaGetSymbolAddress((void**)&dwh,      g_dwh);
    cudaGetSymbolAddress((void**)&pwwh,     g_pwwh);
    cudaGetSymbolAddress((void**)&pwout,    g_pwout);
    cudaGetSymbolAddress((void**)&fcwh,     g_fcwh);
    cudaGetSymbolAddress((void**)&wihh,     g_wihh);
    cudaGetSymbolAddress((void**)&wihl,     g_wihl);
    cudaGetSymbolAddress((void**)&embsh,    g_embsh);
    cudaGetSymbolAddress((void**)&embsl,    g_embsl);
    cudaGetSymbolAddress((void**)&hallh,    g_hallh);
    cudaGetSymbolAddress((void**)&halll,    g_halll);

    cudaFuncSetAttribute(mma_gemm_nt,    cudaFuncAttributeMaxDynamicSharedMemorySize, SMEM_REQ);
    cudaFuncSetAttribute(mma_gemm_nt_h2, cudaFuncAttributeMaxDynamicSharedMemorySize, H2SMEM_REQ);
    cudaFuncSetAttribute(hgemm_nn,       cudaFuncAttributeMaxDynamicSharedMemorySize, HSMEM_REQ);

    // weight conversions (independent of encoder)
    to_half<<<(C2*C1)/1024, 256>>>(pw_w, pwwh, (size_t)C2*C1);
    to_half<<<((size_t)VOC*HID)/1024, 256>>>(fc_w, fcwh, (size_t)VOC*HID);
    split_strided<<<(1536*512)/1024, 256>>>(gru_w_ih, 1024, wihh, wihl);

    // encoder
    conv1_igemm<<<dim3(112, BSZ), 256>>>(images, conv1_w, conv1buf);
    chan_partial_h<<<dim3(C1, BSZ), 256>>>(conv1buf, C1, part);
    chan_finalize<<<1, 256>>>(C1, part, bn1_g, bn1_b, scale1, shift1);
    dw_kernel<<<dim3(14, C1, BSZ), 256>>>(conv1buf, dw_w, scale1, shift1, dwh);
    // pointwise conv (fp16 single-pass GEMM, fused BN2 stats, m-fast grid for B reuse)
    hgemm_nn<<<dim3(4, 98, BSZ), 256, HSMEM_REQ>>>(pwwh, dwh, pwout, part2,
                                                   C2, HW, C1, HW,
                                                   (size_t)C1*HW, (size_t)C2*HW);
    chan_finalize2<<<64, 256>>>(part2, bn2_g, bn2_b, scale2, shift2);
    pooled_kernel<<<dim3(C2, BSZ), 256>>>(pwout, scale2, shift2, pooled);

    // SE + encoder FC + ctx (tiny GEMMs)
    small_gemm<<<16, 256>>>(pooled, 512, se_fc1_w, 512, 0, nullptr, nullptr, 128, 1, t1);
    small_gemm<<<64, 256>>>(t1, 128, se_fc2_w, 128, 0, nullptr, pooled, 512, 2, fbuf);
    small_gemm<<<64, 256>>>(fbuf, 512, enc_fc_w, 512, 0, enc_fc_b, nullptr, 512, 0, feats);
    small_gemm<<<64, 256>>>(feats, 512, v_w, 512, 0, nullptr, nullptr, 512, 0, ctx);

    // decoder: precompute input gates (bf16 3-pass — precision-critical via GRU)
    small_gemm<<<192, 256>>>(ctx, 512, gru_w_ih, 1024, 512, gru_b_ih, nullptr, 1536, 0, gctx);
    gather_embs<<<512, 256>>>(captions, embed, embsh, embsl);
    mma_gemm_nt<<<dim3(12, 4, 1), 256, SMEM_REQ>>>(embsh, embsl, wihh, wihl, gi,
                                                   512, 1536, 512, 512, nullptr, gctx);

    // persistent GRU recurrence
    gru_reset<<<1, 32>>>();
    gru_persist<<<GRU_BLKS, 256>>>(gi, gru_w_hh, gru_b_hh, hall, hallh, halll);

    // logits: fp16 2-pass (A exact via hi+lo, B weight-rounding only ~2.4e-4)
    mma_gemm_nt_h2<<<dim3(250, 4, 1), 256, H2SMEM_REQ>>>(hallh, halll, fcwh, (float*)d_out,
                                                         512, VOC, 512, 512, fc_b);
}

// round 14
// speedup vs baseline: 1.3080x; 1.2438x over previous
#include <cuda_runtime.h>
#include <cuda_bf16.h>
#include <cuda_fp16.h>
#include <math.h>
#include <stdint.h>

#define BSZ 16
#define HW 12544
#define C1 256
#define C2 512
#define TT 32
#define HID 512
#define VOC 32000

// ---------------- scratch (static device arrays; no allocation) ----------------
__device__ __half  g_conv1[(size_t)BSZ*C1*HW];
__device__ float2  g_part1[(size_t)C1*BSZ*112];
__device__ double2 g_part2[(size_t)C2*BSZ*98];
__device__ float   g_scale1[C1], g_shift1[C1];
__device__ float   g_scale2[C2], g_shift2[C2];
__device__ float   g_pooled[BSZ*C2], g_t1[BSZ*128], g_f[BSZ*C2], g_feats[BSZ*C2], g_ctx[BSZ*C2];
__device__ float   g_gctx[BSZ*1536];
__device__ float   g_gi  [(size_t)BSZ*TT*1536];
__device__ float   g_hall[(size_t)BSZ*TT*HID];
__device__ int     g_gbar[TT];

// fp16 planes
__device__ __half g_dwh[(size_t)BSZ*C1*HW];
__device__ __half g_pwwh[C2*C1];
__device__ __half g_pwout[(size_t)BSZ*C2*HW];
__device__ __half g_fcwh[(size_t)VOC*HID];   // fc_w fp16
__device__ __half g_hallh[512*HID];          // hall fp16 (single plane)
// bf16 hi/lo planes for the gi GEMM (3-pass, precision-critical path kept)
__device__ __nv_bfloat16 g_wihh[1536*HID],  g_wihl[1536*HID];
__device__ __nv_bfloat16 g_embsh[512*HID],  g_embsl[512*HID];

// =====================================================================
//                    helpers
// =====================================================================
__device__ __forceinline__ uint32_t smem_u32(const void* p) {
    uint32_t a;
    asm("{ .reg .u64 t; cvta.to.shared.u64 t, %1; cvt.u32.u64 %0, t; }" : "=r"(a) : "l"(p));
    return a;
}
__device__ __forceinline__ void ldsm4(uint32_t* r, uint32_t addr) {
    asm volatile("ldmatrix.sync.aligned.m8n8.x4.shared.b16 {%0,%1,%2,%3}, [%4];"
                 : "=r"(r[0]), "=r"(r[1]), "=r"(r[2]), "=r"(r[3]) : "r"(addr));
}
__device__ __forceinline__ void ldsm4t(uint32_t* r, uint32_t addr) {
    asm volatile("ldmatrix.sync.aligned.m8n8.x4.trans.shared.b16 {%0,%1,%2,%3}, [%4];"
                 : "=r"(r[0]), "=r"(r[1]), "=r"(r[2]), "=r"(r[3]) : "r"(addr));
}
__device__ __forceinline__ void mma_bf(float* d, const uint32_t* a, uint32_t b0, uint32_t b1) {
    asm volatile(
        "mma.sync.aligned.m16n8k16.row.col.f32.bf16.bf16.f32 "
        "{%0,%1,%2,%3}, {%4,%5,%6,%7}, {%8,%9}, {%0,%1,%2,%3};"
        : "+f"(d[0]), "+f"(d[1]), "+f"(d[2]), "+f"(d[3])
        : "r"(a[0]), "r"(a[1]), "r"(a[2]), "r"(a[3]), "r"(b0), "r"(b1));
}
__device__ __forceinline__ void mma_fp(float* d, const uint32_t* a, uint32_t b0, uint32_t b1) {
    asm volatile(
        "mma.sync.aligned.m16n8k16.row.col.f32.f16.f16.f32 "
        "{%0,%1,%2,%3}, {%4,%5,%6,%7}, {%8,%9}, {%0,%1,%2,%3};"
        : "+f"(d[0]), "+f"(d[1]), "+f"(d[2]), "+f"(d[3])
        : "r"(a[0]), "r"(a[1]), "r"(a[2]), "r"(a[3]), "r"(b0), "r"(b1));
}
__device__ __forceinline__ uint32_t pack_bf2(float lo, float hi) {
    uint32_t r;
    asm("cvt.rn.bf16x2.f32 %0, %1, %2;" : "=r"(r) : "f"(hi), "f"(lo));
    return r;
}
__device__ __forceinline__ void split2(float x, float& h, float& l) {
    h = __bfloat162float(__float2bfloat16(x));
    l = x - h;
}
__device__ __forceinline__ void cpa16(uint32_t dst, const void* src) {
    asm volatile("cp.async.cg.shared.global [%0], [%1], 16;" :: "r"(dst), "l"(src));
}
__device__ __forceinline__ void cp_commit() { asm volatile("cp.async.commit_group;"); }
template<int NW> __device__ __forceinline__ void cp_wait() {
    asm volatile("cp.async.wait_group %0;" :: "n"(NW));
}

// =====================================================================
//   conversion kernels
// =====================================================================
__global__ void split_strided(const float* __restrict__ src, int ld,
                              __nv_bfloat16* __restrict__ dh, __nv_bfloat16* __restrict__ dl) {
    size_t i = ((size_t)blockIdx.x*256 + threadIdx.x)*4;
    int row = (int)(i >> 9), col = (int)(i & 511);
    float4 v = *(const float4*)&src[(size_t)row*ld + col];
    float hx, lx, hy, ly, hz, lz, hw, lw;
    split2(v.x, hx, lx); split2(v.y, hy, ly); split2(v.z, hz, lz); split2(v.w, hw, lw);
    *(uint2*)&dh[i] = make_uint2(pack_bf2(hx, hy), pack_bf2(hz, hw));
    *(uint2*)&dl[i] = make_uint2(pack_bf2(lx, ly), pack_bf2(lz, lw));
}
__global__ void to_half(const float* __restrict__ src, __half* __restrict__ dst, size_t n) {
    size_t i = ((size_t)blockIdx.x*256 + threadIdx.x)*4;
    if (i >= n) return;
    float4 v = *(const float4*)&src[i];
    __half2 a = __floats2half2_rn(v.x, v.y), b = __floats2half2_rn(v.z, v.w);
    *(uint2*)&dst[i] = make_uint2(*(uint32_t*)&a, *(uint32_t*)&b);
}

// =====================================================================
//   bf16 3-pass GEMM (NT) — gi only
// =====================================================================
#define KTILE 32
#define LDA   80
#define PLANE 10240
#define STAGE (4*PLANE)
#define SMEM_REQ (2*STAGE + 1024)

__global__ void __launch_bounds__(256) mma_gemm_nt(
        const __nv_bfloat16* __restrict__ Ah, const __nv_bfloat16* __restrict__ Al,
        const __nv_bfloat16* __restrict__ Bh, const __nv_bfloat16* __restrict__ Bl,
        float* __restrict__ C, int M, int N, int K, int ldb,
        const float* __restrict__ bias, const float* __restrict__ rowaux) {
    extern __shared__ char dsm[];
    char* base = (char*)((((uintptr_t)dsm) + 1023) & ~(uintptr_t)1023);
    uint32_t sb0 = smem_u32(base);

    int m0 = blockIdx.y * 128, n0 = blockIdx.x * 128;
    int tid = threadIdx.x;
    int lane = tid & 31, wid = tid >> 5;
    int warp_m = wid & 3, warp_n = wid >> 2;

    float acc[2][8][4];
#pragma unroll
    for (int i = 0; i < 2; i++)
#pragma unroll
        for (int j = 0; j < 8; j++)
#pragma unroll
            for (int q = 0; q < 4; q++) acc[i][j][q] = 0.f;

    int KT = K / KTILE;

    auto load_stage = [&](int s, int kt) {
        uint32_t st = sb0 + s*STAGE;
        uint32_t ah_s = st, al_s = st + PLANE, bh_s = st + 2*PLANE, bl_s = st + 3*PLANE;
        int k0 = kt * KTILE;
#pragma unroll
        for (int i = 0; i < 2; i++) {
            int idx = tid + i*256;
            int row = idx >> 2, kc = idx & 3;
            uint32_t doff = row*LDA + kc*16;
            cpa16(ah_s + doff, Ah + (size_t)(m0 + row)*K + k0 + kc*8);
            cpa16(al_s + doff, Al + (size_t)(m0 + row)*K + k0 + kc*8);
            cpa16(bh_s + doff, Bh + (size_t)(n0 + row)*ldb + k0 + kc*8);
            cpa16(bl_s + doff, Bl + (size_t)(n0 + row)*ldb + k0 + kc*8);
        }
        cp_commit();
    };

    load_stage(0, 0);
    for (int kt = 0; kt < KT; kt++) {
        if (kt + 1 < KT) { load_stage((kt + 1) & 1, kt + 1); cp_wait<1>(); }
        else             { cp_wait<0>(); }
        __syncthreads();
        uint32_t st = sb0 + (kt & 1)*STAGE;
        uint32_t ah_b = st, al_b = st + PLANE, bh_b = st + 2*PLANE, bl_b = st + 3*PLANE;
#pragma unroll
        for (int ks = 0; ks < 2; ks++) {
            int kb = ks*16;
            uint32_t aH[2][4], aL[2][4];
#pragma unroll
            for (int im = 0; im < 2; im++) {
                int row = warp_m*32 + im*16 + (lane & 15);
                uint32_t off = row*LDA + (kb + (lane >> 4)*8)*2;
                ldsm4(aH[im], ah_b + off);
                ldsm4(aL[im], al_b + off);
            }
#pragma unroll
            for (int nc = 0; nc < 4; nc++) {
                uint32_t bH[4], bL[4];
                int row = warp_n*64 + nc*16 + (lane & 15);
                uint32_t off = row*LDA + (kb + (lane >> 4)*8)*2;
                ldsm4(bH, bh_b + off);
                ldsm4(bL, bl_b + off);
#pragma unroll
                for (int im = 0; im < 2; im++) {
                    float* a0 = acc[im][nc*2];
                    float* a1 = acc[im][nc*2 + 1];
                    mma_bf(a0, aH[im], bH[0], bH[2]);
                    mma_bf(a0, aH[im], bL[0], bL[2]);
                    mma_bf(a0, aL[im], bH[0], bH[2]);
                    mma_bf(a1, aH[im], bH[1], bH[3]);
                    mma_bf(a1, aH[im], bL[1], bL[3]);
                    mma_bf(a1, aL[im], bH[1], bH[3]);
                }
            }
        }
        __syncthreads();
    }

    int rbase = m0 + warp_m*32 + (lane >> 2);
    int cbase = n0 + warp_n*64 + (lane & 3)*2;
#pragma unroll
    for (int im = 0; im < 2; im++) {
#pragma unroll
        for (int nf = 0; nf < 8; nf++) {
            int m = rbase + im*16;
            int n = cbase + nf*8;
            float v0 = acc[im][nf][0], v1 = acc[im][nf][1];
            float v2 = acc[im][nf][2], v3 = acc[im][nf][3];
            if (bias)   { float b0 = bias[n], b1 = bias[n+1]; v0 += b0; v1 += b1; v2 += b0; v3 += b1; }
            if (rowaux) {
                float r0 = rowaux[(size_t)(m >> 5)*N + n],     r1 = rowaux[(size_t)(m >> 5)*N + n + 1];
                float r2 = rowaux[(size_t)((m+8) >> 5)*N + n], r3 = rowaux[(size_t)((m+8) >> 5)*N + n + 1];
                v0 += r0; v1 += r1; v2 += r2; v3 += r3;
            }
            *(float2*)&C[(size_t)m*N + n]     = make_float2(v0, v1);
            *(float2*)&C[(size_t)(m+8)*N + n] = make_float2(v2, v3);
        }
    }
}

// =====================================================================
//   fp16 single-pass GEMM (NT): D = Ah @ Bh^T  — logits
// =====================================================================
#define H1STAGE (2*PLANE)
#define H1SMEM_REQ (2*H1STAGE + 1024)

__global__ void __launch_bounds__(256) mma_gemm_nt_h1(
        const __half* __restrict__ Ah, const __half* __restrict__ Bh,
        float* __restrict__ C, int M, int N, int K, int ldb,
        const float* __restrict__ bias) {
    extern __shared__ char dsm[];
    char* base = (char*)((((uintptr_t)dsm) + 1023) & ~(uintptr_t)1023);
    uint32_t sb0 = smem_u32(base);

    int m0 = blockIdx.y * 128, n0 = blockIdx.x * 128;
    int tid = threadIdx.x;
    int lane = tid & 31, wid = tid >> 5;
    int warp_m = wid & 3, warp_n = wid >> 2;

    float acc[2][8][4];
#pragma unroll
    for (int i = 0; i < 2; i++)
#pragma unroll
        for (int j = 0; j < 8; j++)
#pragma unroll
            for (int q = 0; q < 4; q++) acc[i][j][q] = 0.f;

    int KT = K / KTILE;

    auto load_stage = [&](int s, int kt) {
        uint32_t st = sb0 + s*H1STAGE;
        uint32_t ah_s = st, bh_s = st + PLANE;
        int k0 = kt * KTILE;
#pragma unroll
        for (int i = 0; i < 2; i++) {
            int idx = tid + i*256;
            int row = idx >> 2, kc = idx & 3;
            uint32_t doff = row*LDA + kc*16;
            cpa16(ah_s + doff, Ah + (size_t)(m0 + row)*K + k0 + kc*8);
            cpa16(bh_s + doff, Bh + (size_t)(n0 + row)*ldb + k0 + kc*8);
        }
        cp_commit();
    };

    load_stage(0, 0);
    for (int kt = 0; kt < KT; kt++) {
        if (kt + 1 < KT) { load_stage((kt + 1) & 1, kt + 1); cp_wait<1>(); }
        else             { cp_wait<0>(); }
        __syncthreads();
        uint32_t st = sb0 + (kt & 1)*H1STAGE;
        uint32_t ah_b = st, bh_b = st + PLANE;
#pragma unroll
        for (int ks = 0; ks < 2; ks++) {
            int kb = ks*16;
            uint32_t aH[2][4];
#pragma unroll
            for (int im = 0; im < 2; im++) {
                int row = warp_m*32 + im*16 + (lane & 15);
                ldsm4(aH[im], ah_b + row*LDA + (kb + (lane >> 4)*8)*2);
            }
#pragma unroll
            for (int nc = 0; nc < 4; nc++) {
                uint32_t bH[4];
                int row = warp_n*64 + nc*16 + (lane & 15);
                ldsm4(bH, bh_b + row*LDA + (kb + (lane >> 4)*8)*2);
#pragma unroll
                for (int im = 0; im < 2; im++) {
                    mma_fp(acc[im][nc*2],     aH[im], bH[0], bH[2]);
                    mma_fp(acc[im][nc*2 + 1], aH[im], bH[1], bH[3]);
                }
            }
        }
        __syncthreads();
    }

    int rbase = m0 + warp_m*32 + (lane >> 2);
    int cbase = n0 + warp_n*64 + (lane & 3)*2;
#pragma unroll
    for (int im = 0; im < 2; im++) {
#pragma unroll
        for (int nf = 0; nf < 8; nf++) {
            int m = rbase + im*16;
            int n = cbase + nf*8;
            float v0 = acc[im][nf][0], v1 = acc[im][nf][1];
            float v2 = acc[im][nf][2], v3 = acc[im][nf][3];
            if (bias) { float b0 = bias[n], b1 = bias[n+1]; v0 += b0; v1 += b1; v2 += b0; v3 += b1; }
            *(float2*)&C[(size_t)m*N + n]     = make_float2(v0, v1);
            *(float2*)&C[(size_t)(m+8)*N + n] = make_float2(v2, v3);
        }
    }
}

// =====================================================================
//   fp16 single-pass GEMM (NN) with fused per-row stats — pointwise conv
// =====================================================================
#define HKT 64
#define HLDA 144
#define HLDB 272
#define HPA (128*HLDA)
#define HPB (64*HLDB)
#define HSTAGE (HPA + HPB)
#define HSMEM_REQ (2*HSTAGE + 1024)

__global__ void __launch_bounds__(256) hgemm_nn(
        const __half* __restrict__ A, const __half* __restrict__ B,
        __half* __restrict__ C, double2* __restrict__ part,
        int M, int N, int K, int ldb, size_t strideB, size_t strideC) {
    extern __shared__ char dsm[];
    char* base = (char*)((((uintptr_t)dsm) + 1023) & ~(uintptr_t)1023);
    uint32_t sb0 = smem_u32(base);

    const __half* Bb = B + (size_t)blockIdx.z * strideB;
    __half* Cb = C + (size_t)blockIdx.z * strideC;
    int m0 = blockIdx.x * 128, n0 = blockIdx.y * 128;   // m fast
    int nidx = blockIdx.y;
    int tid = threadIdx.x;
    int lane = tid & 31, wid = tid >> 5;
    int warp_m = wid & 3, warp_n = wid >> 2;

    float acc[2][8][4];
#pragma unroll
    for (int i = 0; i < 2; i++)
#pragma unroll
        for (int j = 0; j < 8; j++)
#pragma unroll
            for (int q = 0; q < 4; q++) acc[i][j][q] = 0.f;

    int KT = K / HKT;   // 4

    auto load_stage = [&](int s, int kt) {
        uint32_t st = sb0 + s*HSTAGE;
        uint32_t as = st, bs = st + HPA;
        int k0 = kt * HKT;
#pragma unroll
        for (int i = 0; i < 4; i++) {
            int idx = tid + i*256;
            int row = idx >> 3, kc = idx & 7;
            cpa16(as + row*HLDA + kc*16, A + (size_t)(m0 + row)*K + k0 + kc*8);
        }
#pragma unroll
        for (int i = 0; i < 4; i++) {
            int idx = tid + i*256;
            int row = idx >> 4, c = idx & 15;
            cpa16(bs + row*HLDB + c*16, Bb + (size_t)(k0 + row)*ldb + n0 + c*8);
        }
        cp_commit();
    };

    load_stage(0, 0);
    for (int kt = 0; kt < KT; kt++) {
        if (kt + 1 < KT) { load_stage((kt + 1) & 1, kt + 1); cp_wait<1>(); }
        else             { cp_wait<0>(); }
        __syncthreads();
        uint32_t st = sb0 + (kt & 1)*HSTAGE;
        uint32_t as = st, bs = st + HPA;
#pragma unroll
        for (int ks = 0; ks < 4; ks++) {
            int kb = ks*16;
            uint32_t aF[2][4];
#pragma unroll
            for (int im = 0; im < 2; im++) {
                int row = warp_m*32 + im*16 + (lane & 15);
                uint32_t off = row*HLDA + (kb + (lane >> 4)*8)*2;
                ldsm4(aF[im], as + off);
            }
#pragma unroll
            for (int nc = 0; nc < 4; nc++) {
                uint32_t bF[4];
                int row = kb + (lane & 15);
                int col = warp_n*64 + nc*16 + (lane >> 4)*8;
                ldsm4t(bF, bs + row*HLDB + col*2);
#pragma unroll
                for (int im = 0; im < 2; im++) {
                    mma_fp(acc[im][nc*2],     aF[im], bF[0], bF[1]);
                    mma_fp(acc[im][nc*2 + 1], aF[im], bF[2], bF[3]);
                }
            }
        }
        __syncthreads();
    }

    // ---- epilogue: fp16 store + per-row (channel) sum/sumsq ----
    int rloc = warp_m*32 + (lane >> 2);
    int cbase = n0 + warp_n*64 + (lane & 3)*2;
    float s[4]  = {0.f, 0.f, 0.f, 0.f};
    float s2[4] = {0.f, 0.f, 0.f, 0.f};
#pragma unroll
    for (int im = 0; im < 2; im++) {
#pragma unroll
        for (int nf = 0; nf < 8; nf++) {
            int m = m0 + rloc + im*16;
            int n = cbase + nf*8;
            float v0 = acc[im][nf][0], v1 = acc[im][nf][1];
            float v2 = acc[im][nf][2], v3 = acc[im][nf][3];
            __half2 h01 = __floats2half2_rn(v0, v1);
            __half2 h23 = __floats2half2_rn(v2, v3);
            *(__half2*)&Cb[(size_t)m*N + n]     = h01;
            *(__half2*)&Cb[(size_t)(m+8)*N + n] = h23;
            s [im*2+0] += v0 + v1;    s2[im*2+0] += v0*v0 + v1*v1;
            s [im*2+1] += v2 + v3;    s2[im*2+1] += v2*v2 + v3*v3;
        }
    }
#pragma unroll
    for (int r = 0; r < 4; r++) {
        s [r] += __shfl_xor_sync(0xffffffffu, s [r], 1);
        s [r] += __shfl_xor_sync(0xffffffffu, s [r], 2);
        s2[r] += __shfl_xor_sync(0xffffffffu, s2[r], 1);
        s2[r] += __shfl_xor_sync(0xffffffffu, s2[r], 2);
    }
    float2* sst = (float2*)base;
    __syncthreads();
    if ((lane & 3) == 0) {
#pragma unroll
        for (int r = 0; r < 4; r++) {
            int row = rloc + (r >> 1)*16 + (r & 1)*8;
            sst[warp_n*128 + row] = make_float2(s[r], s2[r]);
        }
    }
    __syncthreads();
    if (tid < 128) {
        float2 a = sst[tid], b = sst[128 + tid];
        double2 p;
        p.x = (double)a.x + (double)b.x;
        p.y = (double)a.y + (double)b.y;
        part[(size_t)(m0 + tid)*(BSZ*98) + blockIdx.z*98 + nidx] = p;
    }
}

// finalize BN2 scale/shift from fused partials; warp per channel
__global__ void chan_finalize2(const double2* __restrict__ part,
                               const float* __restrict__ g, const float* __restrict__ bt,
                               float* __restrict__ scale, float* __restrict__ shift) {
    int warp = (blockIdx.x*256 + threadIdx.x) >> 5;
    int lane = threadIdx.x & 31;
    if (warp >= C2) return;
    double s = 0, s2 = 0;
    for (int i = lane; i < BSZ*98; i += 32) {
        double2 p = part[(size_t)warp*(BSZ*98) + i];
        s += p.x; s2 += p.y;
    }
#pragma unroll
    for (int o = 16; o; o >>= 1) {
        s  += __shfl_xor_sync(0xffffffffu, s,  o);
        s2 += __shfl_xor_sync(0xffffffffu, s2, o);
    }
    if (lane == 0) {
        double cnt = (double)BSZ * HW;
        double m = s / cnt;
        double var = s2 / cnt - m*m;
        float rs = (float)(1.0 / sqrt(var + 1e-5));
        float sc = g[warp] * rs;
        scale[warp] = sc;
        shift[warp] = bt[warp] - (float)m * sc;
    }
}

// =====================================================================
//   conv1 as fp16 implicit GEMM + fused BN1 stats
// =====================================================================
__global__ void __launch_bounds__(256) conv1_igemm(
        const float* __restrict__ img, const float* __restrict__ w,
        __half* __restrict__ out, float2* __restrict__ part1) {
    __shared__ __half wt [256*40];
    __shared__ __half imt[128*40];
    __shared__ float  inr[9*224];
    __shared__ float2 sst[256];
    int oy = blockIdx.x, b = blockIdx.y;
    int tid = threadIdx.x;
    int lane = tid & 31, wid = tid >> 5;

    for (int i = tid; i < 256*32; i += 256) {
        int c = i >> 5, k = i & 31;
        float v = (k < 27) ? __ldg(&w[c*27 + k]) : 0.f;
        wt[c*40 + k] = __float2half_rn(v);
    }
    const float* ip = img + (size_t)b*3*224*224;
    for (int i = tid; i < 9*224; i += 256) {
        int r = i / 224, x = i - r*224;
        int ci = r / 3, ky = r - ci*3;
        int iy = oy*2 - 1 + ky;
        inr[i] = (iy >= 0 && iy < 224) ? ip[(ci*224 + iy)*224 + x] : 0.f;
    }
    __syncthreads();
    for (int i = tid; i < 128*32; i += 256) {
        int p = i >> 5, k = i & 31;
        float v = 0.f;
        if (p < 112 && k < 27) {
            int ci = k / 9, r = k - ci*9;
            int ky = r / 3, kx = r - ky*3;
            int ix = p*2 - 1 + kx;
            if (ix >= 0 && ix < 224) v = inr[(ci*3 + ky)*224 + ix];
        }
        imt[p*40 + k] = __float2half_rn(v);
    }
    __syncthreads();

    uint32_t wt_b = smem_u32(wt), imt_b = smem_u32(imt);
    size_t obase = (size_t)b*C1*HW + (size_t)oy*112;
    float s[4]  = {0.f, 0.f, 0.f, 0.f};   // [im][rowhalf]
    float s2[4] = {0.f, 0.f, 0.f, 0.f};
#pragma unroll
    for (int half = 0; half < 2; half++) {
        float acc[2][8][4];
#pragma unroll
        for (int i = 0; i < 2; i++)
#pragma unroll
            for (int j = 0; j < 8; j++)
#pragma unroll
                for (int q = 0; q < 4; q++) acc[i][j][q] = 0.f;
#pragma unroll
        for (int ks = 0; ks < 2; ks++) {
            int kb = ks*16;
            uint32_t aF[2][4];
#pragma unroll
            for (int im = 0; im < 2; im++) {
                int row = wid*32 + im*16 + (lane & 15);
                ldsm4(aF[im], wt_b + (row*40 + kb + (lane >> 4)*8)*2);
            }
#pragma unroll
            for (int nc = 0; nc < 4; nc++) {
                uint32_t bF[4];
                int row = half*64 + nc*16 + (lane & 15);
                ldsm4(bF, imt_b + (row*40 + kb + (lane >> 4)*8)*2);
#pragma unroll
                for (int im = 0; im < 2; im++) {
                    mma_fp(acc[im][nc*2],     aF[im], bF[0], bF[2]);
                    mma_fp(acc[im][nc*2 + 1], aF[im], bF[1], bF[3]);
                }
            }
        }
#pragma unroll
        for (int im = 0; im < 2; im++) {
#pragma unroll
            for (int nf = 0; nf < 8; nf++) {
                int m = wid*32 + im*16 + (lane >> 2);
                int n = half*64 + nf*8 + (lane & 3)*2;
                if (n < 112) {
                    float v0 = acc[im][nf][0], v1 = acc[im][nf][1];
                    float v2 = acc[im][nf][2], v3 = acc[im][nf][3];
                    __half2 h01 = __floats2half2_rn(v0, v1);
                    __half2 h23 = __floats2half2_rn(v2, v3);
                    *(__half2*)&out[obase + (size_t)m*HW + n]     = h01;
                    *(__half2*)&out[obase + (size_t)(m+8)*HW + n] = h23;
                    s [im*2+0] += v0 + v1;   s2[im*2+0] += v0*v0 + v1*v1;
                    s [im*2+1] += v2 + v3;   s2[im*2+1] += v2*v2 + v3*v3;
                }
            }
        }
    }
    // quad reduce (4 lanes sharing each channel row), store per-CTA partials
#pragma unroll
    for (int r = 0; r < 4; r++) {
        s [r] += __shfl_xor_sync(0xffffffffu, s [r], 1);
        s [r] += __shfl_xor_sync(0xffffffffu, s [r], 2);
        s2[r] += __shfl_xor_sync(0xffffffffu, s2[r], 1);
        s2[r] += __shfl_xor_sync(0xffffffffu, s2[r], 2);
    }
    __syncthreads();
    if ((lane & 3) == 0) {
#pragma unroll
        for (int r = 0; r < 4; r++) {
            int row = wid*32 + (r >> 1)*16 + (r & 1)*8 + (lane >> 2);
            sst[row] = make_float2(s[r], s2[r]);
        }
    }
    __syncthreads();
    {
        float2 p = sst[tid];
        part1[(size_t)tid*(BSZ*112) + b*112 + oy] = p;
    }
}

// finalize BN1 from fused float2 partials (1792 per channel); warp per channel
__global__ void chan_finalize1(const float2* __restrict__ part,
                               const float* __restrict__ g, const float* __restrict__ bt,
                               float* __restrict__ scale, float* __restrict__ shift) {
    int warp = (blockIdx.x*256 + threadIdx.x) >> 5;
    int lane = threadIdx.x & 31;
    if (warp >= C1) return;
    double s = 0, s2 = 0;
    for (int i = lane; i < BSZ*112; i += 32) {
        float2 p = part[(size_t)warp*(BSZ*112) + i];
        s += (double)p.x; s2 += (double)p.y;
    }
#pragma unroll
    for (int o = 16; o; o >>= 1) {
        s  += __shfl_xor_sync(0xffffffffu, s,  o);
        s2 += __shfl_xor_sync(0xffffffffu, s2, o);
    }
    if (lane == 0) {
        double cnt = (double)BSZ * HW;
        double m = s / cnt;
        double var = s2 / cnt - m*m;
        float rs = (float)(1.0 / sqrt(var + 1e-5));
        float sc = g[warp] * rs;
        scale[warp] = sc;
        shift[warp] = bt[warp] - (float)m * sc;
    }
}

// ---------------- depthwise 3x3 s1 p1 (BN1+ReLU fused), fp16 in/out -------------
__global__ void dw_kernel(const __half* __restrict__ in, const float* __restrict__ w,
                          const float* __restrict__ scale, const float* __restrict__ shift,
                          __half* __restrict__ outh) {
    int warp = threadIdx.x >> 5, lane = threadIdx.x & 31;
    int y = blockIdx.x*8 + warp;
    int c = blockIdx.y, b = blockIdx.z;
    float sc = scale[c], sh = shift[c];
    const __half* ip = in + ((size_t)b*C1 + c)*HW;
    int x0 = lane*4;
    bool inx = (x0 < 112);

    float v[3][4];
    float lft[3], rgt[3];
#pragma unroll
    for (int r = 0; r < 3; r++) {
        int yy = y - 1 + r;
        float t0 = 0.f, t1 = 0.f, t2 = 0.f, t3 = 0.f;
        if (inx && yy >= 0 && yy < 112) {
            uint2 u = *(const uint2*)&ip[yy*112 + x0];
            float2 p0 = __half22float2(*(__half2*)&u.x);
            float2 p1 = __half22float2(*(__half2*)&u.y);
            t0 = p0.x; t1 = p0.y; t2 = p1.x; t3 = p1.y;
        }
        v[r][0] = fmaxf(t0*sc + sh, 0.f);
        v[r][1] = fmaxf(t1*sc + sh, 0.f);
        v[r][2] = fmaxf(t2*sc + sh, 0.f);
        v[r][3] = fmaxf(t3*sc + sh, 0.f);
        if (!inx || yy < 0 || yy >= 112) { v[r][0]=v[r][1]=v[r][2]=v[r][3]=0.f; }
        lft[r] = __shfl_up_sync(0xffffffffu, v[r][3], 1);
        if (lane == 0) lft[r] = 0.f;
        rgt[r] = __shfl_down_sync(0xffffffffu, v[r][0], 1);
        if (lane >= 27) rgt[r] = 0.f;
    }
    float wv[9];
#pragma unroll
    for (int k = 0; k < 9; k++) wv[k] = __ldg(&w[c*9 + k]);

    float o0 = 0.f, o1 = 0.f, o2 = 0.f, o3 = 0.f;
#pragma unroll
    for (int r = 0; r < 3; r++) {
        float e0 = lft[r], e1 = v[r][0], e2 = v[r][1], e3 = v[r][2], e4 = v[r][3], e5 = rgt[r];
        float w0 = wv[r*3+0], w1 = wv[r*3+1], w2 = wv[r*3+2];
        o0 += w0*e0 + w1*e1 + w2*e2;
        o1 += w0*e1 + w1*e2 + w2*e3;
        o2 += w0*e2 + w1*e3 + w2*e4;
        o3 += w0*e3 + w1*e4 + w2*e5;
    }
    if (inx) {
        __half2 h01 = __floats2half2_rn(o0, o1);
        __half2 h23 = __floats2half2_rn(o2, o3);
        size_t off = ((size_t)b*C1 + c)*HW + y*112 + x0;
        *(uint2*)&outh[off] = make_uint2(*(uint32_t*)&h01, *(uint32_t*)&h23);
    }
}

// ---------------- pooled[b][c] = mean_p relu(bn2(pw)), fp16 source ----------------
__global__ void pooled_kernel(const __half* __restrict__ x, const float* __restrict__ scale,
                              const float* __restrict__ shift, float* __restrict__ pooled) {
    int c = blockIdx.x, b = blockIdx.y;
    const __half2* p = (const __half2*)(x + ((size_t)b*C2 + c)*HW);
    float sc = scale[c], sh = shift[c];
    double s = 0;
    for (int i = threadIdx.x; i < HW/2; i += 256) {
        float2 v = __half22float2(p[i]);
        float a = v.x*sc + sh, bq = v.y*sc + sh;
        if (a > 0.f) s += a;
        if (bq > 0.f) s += bq;
    }
    __shared__ double shm[256];
    shm[threadIdx.x] = s; __syncthreads();
    for (int o = 128; o; o >>= 1) {
        if (threadIdx.x < o) shm[threadIdx.x] += shm[threadIdx.x+o];
        __syncthreads();
    }
    if (threadIdx.x == 0) pooled[b*C2 + c] = (float)(shm[0] / (double)HW);
}

// ---------------- small GEMM ----------------
__global__ void small_gemm(const float* __restrict__ in, int K,
                           const float* __restrict__ W, int ldw, int woff,
                           const float* __restrict__ bias, const float* __restrict__ aux,
                           int O, int act, float* __restrict__ out) {
    __shared__ float sin_s[BSZ*512];
    for (int i = threadIdx.x; i < BSZ*K; i += 256) sin_s[i] = in[i];
    __syncthreads();
    int warp = threadIdx.x >> 5, lane = threadIdx.x & 31;
    int o = blockIdx.x*8 + warp;
    float part[BSZ];
#pragma unroll
    for (int b = 0; b < BSZ; b++) part[b] = 0.f;
    for (int k = lane; k < K; k += 32) {
        float wv = W[(size_t)o*ldw + woff + k];
#pragma unroll
        for (int b = 0; b < BSZ; b++) part[b] += wv * sin_s[b*K + k];
    }
#pragma unroll
    for (int b = 0; b < BSZ; b++) {
        float v = part[b];
#pragma unroll
        for (int off = 16; off; off >>= 1) v += __shfl_xor_sync(0xffffffffu, v, off);
        if (lane == b) {
            if (bias) v += bias[o];
            if (act == 1) v = v > 0.f ? v : 0.f;
            else if (act == 2) v = (1.f/(1.f + expf(-v))) * aux[b*O + o];
            out[b*O + o] = v;
        }
    }
}

// ---------------- gather caption embeddings: bf16 split planes ----------------
__global__ void gather_embs(const int* __restrict__ cap, const float* __restrict__ embed,
                            __nv_bfloat16* __restrict__ eh, __nv_bfloat16* __restrict__ el) {
    int row = blockIdx.x;
    int b = row >> 5, t = row & 31;
    int tok = cap[b*33 + t];
    const float* src = embed + (size_t)tok*HID;
    int i = threadIdx.x*2;
    float2 v = *(const float2*)&src[i];
    float h0,l0,h1,l1;
    split2(v.x,h0,l0); split2(v.y,h1,l1);
    *(uint32_t*)&eh[(size_t)row*HID + i] = pack_bf2(h0,h1);
    *(uint32_t*)&el[(size_t)row*HID + i] = pack_bf2(l0,l1);
}

// ---------------- persistent GRU (hall fp16 for logits) ----------------
__global__ void gru_reset() {
    if (threadIdx.x < TT) g_gbar[threadIdx.x] = 0;
}
#define GRU_BLKS 64
__global__ void __launch_bounds__(256) gru_persist(
        const float* __restrict__ gi, const float* __restrict__ whh,
        const float* __restrict__ bhh, float* __restrict__ hall,
        __half* __restrict__ hallh) {
    __shared__ float hs[BSZ*HID];
    int tid = threadIdx.x;
    int warp = tid >> 5, lane = tid & 31;
    int j = blockIdx.x*8 + warp;
    float w0[16], w1[16], w2[16];
#pragma unroll
    for (int i = 0; i < 16; i++) {
        int k = lane + 32*i;
        w0[i] = whh[(size_t)j*HID + k];
        w1[i] = whh[(size_t)(j + 512)*HID + k];
        w2[i] = whh[(size_t)(j + 1024)*HID + k];
    }
    float bhr = bhh[j], bhz = bhh[j + 512], bhn = bhh[j + 1024];

    for (int t = 0; t < TT; t++) {
        for (int i = tid; i < BSZ*HID; i += 256) {
            int b = i >> 9, jj = i & 511;
            hs[i] = (t == 0) ? 0.f : hall[((size_t)(b*TT + t - 1))*HID + jj];
        }
        __syncthreads();
        for (int b = 0; b < BSZ; b++) {
            float pr = 0.f, pz = 0.f, pn = 0.f;
#pragma unroll
            for (int i = 0; i < 16; i++) {
                float hv = hs[b*HID + lane + 32*i];
                pr += hv*w0[i]; pz += hv*w1[i]; pn += hv*w2[i];
            }
#pragma unroll
            for (int o = 16; o; o >>= 1) {
                pr += __shfl_xor_sync(0xffffffffu, pr, o);
                pz += __shfl_xor_sync(0xffffffffu, pz, o);
                pn += __shfl_xor_sync(0xffffffffu, pn, o);
            }
            if (lane == 0) {
                size_t gib = ((size_t)(b*TT + t))*1536;
                float ir = gi[gib + j], iz = gi[gib + 512 + j], inn = gi[gib + 1024 + j];
                float r = 1.f/(1.f + expf(-(ir + pr + bhr)));
                float z = 1.f/(1.f + expf(-(iz + pz + bhz)));
                float n = tanhf(inn + r*(pn + bhn));
                float hp = hs[b*HID + j];
                float hn2 = (1.f - z)*n + z*hp;
                size_t oidx = ((size_t)(b*TT + t))*HID + j;
                hall[oidx] = hn2;
                hallh[oidx] = __float2half_rn(hn2);
            }
        }
        __threadfence();
        __syncthreads();
        if (tid == 0) {
            atomicAdd(&g_gbar[t], 1);
            while (atomicAdd(&g_gbar[t], 0) < GRU_BLKS) __nanosleep(64);
        }
        __syncthreads();
    }
}

// =======================================================================
extern "C" void kernel_launch(void* const* d_in, const int* in_sizes, int n_in,
                              void* d_out, int out_size) {
    const float* images   = (const float*)d_in[0];
    const int*   captions = (const int*)  d_in[1];
    const float* conv1_w  = (const float*)d_in[2];
    const float* bn1_g    = (const float*)d_in[3];
    const float* bn1_b    = (const float*)d_in[4];
    const float* dw_w     = (const float*)d_in[5];
    const float* pw_w     = (const float*)d_in[6];
    const float* bn2_g    = (const float*)d_in[7];
    const float* bn2_b    = (const float*)d_in[8];
    const float* se_fc1_w = (const float*)d_in[9];
    const float* se_fc2_w = (const float*)d_in[10];
    const float* enc_fc_w = (const float*)d_in[11];
    const float* enc_fc_b = (const float*)d_in[12];
    const float* embed    = (const float*)d_in[13];
    // d_in[14] = q_w (unused), d_in[15] = k_w (unused)
    const float* v_w      = (const float*)d_in[16];
    const float* gru_w_ih = (const float*)d_in[17];
    const float* gru_w_hh = (const float*)d_in[18];
    const float* gru_b_ih = (const float*)d_in[19];
    const float* gru_b_hh = (const float*)d_in[20];
    const float* fc_w     = (const float*)d_in[21];
    const float* fc_b     = (const float*)d_in[22];

    __half *conv1buf;
    float2 *part1;
    double2 *part2;
    float *scale1, *shift1, *scale2, *shift2;
    float *pooled, *t1, *fbuf, *feats, *ctx, *gctx, *gi, *hall;
    __half *dwh, *pwwh, *pwout, *fcwh, *hallh;
    __nv_bfloat16 *wihh, *wihl, *embsh, *embsl;
    cudaGetSymbolAddress((void**)&conv1buf, g_conv1);
    cudaGetSymbolAddress((void**)&part1,    g_part1);
    cudaGetSymbolAddress((void**)&part2,    g_part2);
    cudaGetSymbolAddress((void**)&scale1,   g_scale1);
    cudaGetSymbolAddress((void**)&shift1,   g_shift1);
    cudaGetSymbolAddress((void**)&scale2,   g_scale2);
    cudaGetSymbolAddress((void**)&shift2,   g_shift2);
    cudaGetSymbolAddress((void**)&pooled,   g_pooled);
    cudaGetSymbolAddress((void**)&t1,       g_t1);
    cudaGetSymbolAddress((void**)&fbuf,     g_f);
    cudaGetSymbolAddress((void**)&feats,    g_feats);
    cudaGetSymbolAddress((void**)&ctx,      g_ctx);
    cudaGetSymbolAddress((void**)&gctx,     g_gctx);
    cudaGetSymbolAddress((void**)&gi,       g_gi);
    cudaGetSymbolAddress((void**)&hall,     g_hall);
    cudaGetSymbolAddress((void**)&dwh,      g_dwh);
    cudaGetSymbolAddress((void**)&pwwh,     g_pwwh);
    cudaGetSymbolAddress((void**)&pwout,    g_pwout);
    cudaGetSymbolAddress((void**)&fcwh,     g_fcwh);
    cudaGetSymbolAddress((void**)&wihh,     g_wihh);
    cudaGetSymbolAddress((void**)&wihl,     g_wihl);
    cudaGetSymbolAddress((void**)&embsh,    g_embsh);
    cudaGetSymbolAddress((void**)&embsl,    g_embsl);
    cudaGetSymbolAddress((void**)&hallh,    g_hallh);

    cudaFuncSetAttribute(mma_gemm_nt,    cudaFuncAttributeMaxDynamicSharedMemorySize, SMEM_REQ);
    cudaFuncSetAttribute(mma_gemm_nt_h1, cudaFuncAttributeMaxDynamicSharedMemorySize, H1SMEM_REQ);
    cudaFuncSetAttribute(hgemm_nn,       cudaFuncAttributeMaxDynamicSharedMemorySize, HSMEM_REQ);

    // weight conversions (independent of encoder)
    to_half<<<(C2*C1)/1024, 256>>>(pw_w, pwwh, (size_t)C2*C1);
    to_half<<<((size_t)VOC*HID)/1024, 256>>>(fc_w, fcwh, (size_t)VOC*HID);
    split_strided<<<(1536*512)/1024, 256>>>(gru_w_ih, 1024, wihh, wihl);

    // encoder
    conv1_igemm<<<dim3(112, BSZ), 256>>>(images, conv1_w, conv1buf, part1);
    chan_finalize1<<<32, 256>>>(part1, bn1_g, bn1_b, scale1, shift1);
    dw_kernel<<<dim3(14, C1, BSZ), 256>>>(conv1buf, dw_w, scale1, shift1, dwh);
    // pointwise conv (fp16 single-pass GEMM, fused BN2 stats)
    hgemm_nn<<<dim3(4, 98, BSZ), 256, HSMEM_REQ>>>(pwwh, dwh, pwout, part2,
                                                   C2, HW, C1, HW,
                                                   (size_t)C1*HW, (size_t)C2*HW);
    chan_finalize2<<<64, 256>>>(part2, bn2_g, bn2_b, scale2, shift2);
    pooled_kernel<<<dim3(C2, BSZ), 256>>>(pwout, scale2, shift2, pooled);

    // SE + encoder FC + ctx (tiny GEMMs)
    small_gemm<<<16, 256>>>(pooled, 512, se_fc1_w, 512, 0, nullptr, nullptr, 128, 1, t1);
    small_gemm<<<64, 256>>>(t1, 128, se_fc2_w, 128, 0, nullptr, pooled, 512, 2, fbuf);
    small_gemm<<<64, 256>>>(fbuf, 512, enc_fc_w, 512, 0, enc_fc_b, nullptr, 512, 0, feats);
    small_gemm<<<64, 256>>>(feats, 512, v_w, 512, 0, nullptr, nullptr, 512, 0, ctx);

    // decoder: precompute input gates (bf16 3-pass — precision-critical via GRU)
    small_gemm<<<192, 256>>>(ctx, 512, gru_w_ih, 1024, 512, gru_b_ih, nullptr, 1536, 0, gctx);
    gather_embs<<<512, 256>>>(captions, embed, embsh, embsl);
    mma_gemm_nt<<<dim3(12, 4, 1), 256, SMEM_REQ>>>(embsh, embsl, wihh, wihl, gi,
                                                   512, 1536, 512, 512, nullptr, gctx);

    // persistent GRU recurrence
    gru_reset<<<1, 32>>>();
    gru_persist<<<GRU_BLKS, 256>>>(gi, gru_w_hh, gru_b_hh, hall, hallh);

    // logits: fp16 single-pass (A,B rounding ~3e-4 combined, 3x under 1e-3 gate)
    mma_gemm_nt_h1<<<dim3(250, 4, 1), 256, H1SMEM_REQ>>>(hallh, fcwh, (float*)d_out,
                                                         512, VOC, 512, 512, fc_b);
}

// round 15
// speedup vs baseline: 1.3321x; 1.0184x over previous
#include <cuda_runtime.h>
#include <cuda_bf16.h>
#include <cuda_fp16.h>
#include <math.h>
#include <stdint.h>

#define BSZ 16
#define HW 12544
#define C1 256
#define C2 512
#define TT 32
#define HID 512
#define VOC 32000

// ---------------- scratch (static device arrays; no allocation) ----------------
__device__ __half  g_conv1[(size_t)BSZ*C1*HW];
__device__ float2  g_part1[(size_t)C1*BSZ*112];
__device__ double2 g_part2[(size_t)C2*BSZ*98];
__device__ float   g_scale1[C1], g_shift1[C1];
__device__ float   g_scale2[C2], g_shift2[C2];
__device__ float   g_pooled[BSZ*C2], g_t1[BSZ*128], g_f[BSZ*C2], g_feats[BSZ*C2], g_ctx[BSZ*C2];
__device__ float   g_gctx[BSZ*1536];
__device__ float   g_gi  [(size_t)BSZ*TT*1536];
__device__ float   g_hall[(size_t)BSZ*TT*HID];
__device__ int     g_gbar[TT];

// fp16 planes
__device__ __half g_dwh[(size_t)BSZ*C1*HW];
__device__ __half g_pwwh[C2*C1];
__device__ __half g_pwout[(size_t)BSZ*C2*HW];
__device__ __half g_fcwh[(size_t)VOC*HID];   // fc_w fp16
__device__ __half g_hallh[512*HID];          // hall fp16 (single plane)
// bf16 hi/lo planes for the gi GEMM (3-pass, precision-critical path kept)
__device__ __nv_bfloat16 g_wihh[1536*HID],  g_wihl[1536*HID];
__device__ __nv_bfloat16 g_embsh[512*HID],  g_embsl[512*HID];

// =====================================================================
//                    helpers
// =====================================================================
__device__ __forceinline__ uint32_t smem_u32(const void* p) {
    uint32_t a;
    asm("{ .reg .u64 t; cvta.to.shared.u64 t, %1; cvt.u32.u64 %0, t; }" : "=r"(a) : "l"(p));
    return a;
}
__device__ __forceinline__ void ldsm4(uint32_t* r, uint32_t addr) {
    asm volatile("ldmatrix.sync.aligned.m8n8.x4.shared.b16 {%0,%1,%2,%3}, [%4];"
                 : "=r"(r[0]), "=r"(r[1]), "=r"(r[2]), "=r"(r[3]) : "r"(addr));
}
__device__ __forceinline__ void ldsm4t(uint32_t* r, uint32_t addr) {
    asm volatile("ldmatrix.sync.aligned.m8n8.x4.trans.shared.b16 {%0,%1,%2,%3}, [%4];"
                 : "=r"(r[0]), "=r"(r[1]), "=r"(r[2]), "=r"(r[3]) : "r"(addr));
}
__device__ __forceinline__ void mma_bf(float* d, const uint32_t* a, uint32_t b0, uint32_t b1) {
    asm volatile(
        "mma.sync.aligned.m16n8k16.row.col.f32.bf16.bf16.f32 "
        "{%0,%1,%2,%3}, {%4,%5,%6,%7}, {%8,%9}, {%0,%1,%2,%3};"
        : "+f"(d[0]), "+f"(d[1]), "+f"(d[2]), "+f"(d[3])
        : "r"(a[0]), "r"(a[1]), "r"(a[2]), "r"(a[3]), "r"(b0), "r"(b1));
}
__device__ __forceinline__ void mma_fp(float* d, const uint32_t* a, uint32_t b0, uint32_t b1) {
    asm volatile(
        "mma.sync.aligned.m16n8k16.row.col.f32.f16.f16.f32 "
        "{%0,%1,%2,%3}, {%4,%5,%6,%7}, {%8,%9}, {%0,%1,%2,%3};"
        : "+f"(d[0]), "+f"(d[1]), "+f"(d[2]), "+f"(d[3])
        : "r"(a[0]), "r"(a[1]), "r"(a[2]), "r"(a[3]), "r"(b0), "r"(b1));
}
__device__ __forceinline__ uint32_t pack_bf2(float lo, float hi) {
    uint32_t r;
    asm("cvt.rn.bf16x2.f32 %0, %1, %2;" : "=r"(r) : "f"(hi), "f"(lo));
    return r;
}
__device__ __forceinline__ void split2(float x, float& h, float& l) {
    h = __bfloat162float(__float2bfloat16(x));
    l = x - h;
}
__device__ __forceinline__ void cpa16(uint32_t dst, const void* src) {
    asm volatile("cp.async.cg.shared.global [%0], [%1], 16;" :: "r"(dst), "l"(src));
}
__device__ __forceinline__ void cp_commit() { asm volatile("cp.async.commit_group;"); }
template<int NW> __device__ __forceinline__ void cp_wait() {
    asm volatile("cp.async.wait_group %0;" :: "n"(NW));
}

// =====================================================================
//   conversion kernels
// =====================================================================
__global__ void split_strided(const float* __restrict__ src, int ld,
                              __nv_bfloat16* __restrict__ dh, __nv_bfloat16* __restrict__ dl) {
    size_t i = ((size_t)blockIdx.x*256 + threadIdx.x)*4;
    int row = (int)(i >> 9), col = (int)(i & 511);
    float4 v = *(const float4*)&src[(size_t)row*ld + col];
    float hx, lx, hy, ly, hz, lz, hw, lw;
    split2(v.x, hx, lx); split2(v.y, hy, ly); split2(v.z, hz, lz); split2(v.w, hw, lw);
    *(uint2*)&dh[i] = make_uint2(pack_bf2(hx, hy), pack_bf2(hz, hw));
    *(uint2*)&dl[i] = make_uint2(pack_bf2(lx, ly), pack_bf2(lz, lw));
}
__global__ void to_half(const float* __restrict__ src, __half* __restrict__ dst, size_t n) {
    size_t i = ((size_t)blockIdx.x*256 + threadIdx.x)*4;
    if (i >= n) return;
    float4 v = *(const float4*)&src[i];
    __half2 a = __floats2half2_rn(v.x, v.y), b = __floats2half2_rn(v.z, v.w);
    *(uint2*)&dst[i] = make_uint2(*(uint32_t*)&a, *(uint32_t*)&b);
}

// =====================================================================
//   bf16 3-pass GEMM (NT) — gi only
// =====================================================================
#define KTILE 32
#define LDA   80
#define PLANE 10240
#define STAGE (4*PLANE)
#define SMEM_REQ (2*STAGE + 1024)

__global__ void __launch_bounds__(256) mma_gemm_nt(
        const __nv_bfloat16* __restrict__ Ah, const __nv_bfloat16* __restrict__ Al,
        const __nv_bfloat16* __restrict__ Bh, const __nv_bfloat16* __restrict__ Bl,
        float* __restrict__ C, int M, int N, int K, int ldb,
        const float* __restrict__ bias, const float* __restrict__ rowaux) {
    extern __shared__ char dsm[];
    char* base = (char*)((((uintptr_t)dsm) + 1023) & ~(uintptr_t)1023);
    uint32_t sb0 = smem_u32(base);

    int m0 = blockIdx.y * 128, n0 = blockIdx.x * 128;
    int tid = threadIdx.x;
    int lane = tid & 31, wid = tid >> 5;
    int warp_m = wid & 3, warp_n = wid >> 2;

    float acc[2][8][4];
#pragma unroll
    for (int i = 0; i < 2; i++)
#pragma unroll
        for (int j = 0; j < 8; j++)
#pragma unroll
            for (int q = 0; q < 4; q++) acc[i][j][q] = 0.f;

    int KT = K / KTILE;

    auto load_stage = [&](int s, int kt) {
        uint32_t st = sb0 + s*STAGE;
        uint32_t ah_s = st, al_s = st + PLANE, bh_s = st + 2*PLANE, bl_s = st + 3*PLANE;
        int k0 = kt * KTILE;
#pragma unroll
        for (int i = 0; i < 2; i++) {
            int idx = tid + i*256;
            int row = idx >> 2, kc = idx & 3;
            uint32_t doff = row*LDA + kc*16;
            cpa16(ah_s + doff, Ah + (size_t)(m0 + row)*K + k0 + kc*8);
            cpa16(al_s + doff, Al + (size_t)(m0 + row)*K + k0 + kc*8);
            cpa16(bh_s + doff, Bh + (size_t)(n0 + row)*ldb + k0 + kc*8);
            cpa16(bl_s + doff, Bl + (size_t)(n0 + row)*ldb + k0 + kc*8);
        }
        cp_commit();
    };

    load_stage(0, 0);
    for (int kt = 0; kt < KT; kt++) {
        if (kt + 1 < KT) { load_stage((kt + 1) & 1, kt + 1); cp_wait<1>(); }
        else             { cp_wait<0>(); }
        __syncthreads();
        uint32_t st = sb0 + (kt & 1)*STAGE;
        uint32_t ah_b = st, al_b = st + PLANE, bh_b = st + 2*PLANE, bl_b = st + 3*PLANE;
#pragma unroll
        for (int ks = 0; ks < 2; ks++) {
            int kb = ks*16;
            uint32_t aH[2][4], aL[2][4];
#pragma unroll
            for (int im = 0; im < 2; im++) {
                int row = warp_m*32 + im*16 + (lane & 15);
                uint32_t off = row*LDA + (kb + (lane >> 4)*8)*2;
                ldsm4(aH[im], ah_b + off);
                ldsm4(aL[im], al_b + off);
            }
#pragma unroll
            for (int nc = 0; nc < 4; nc++) {
                uint32_t bH[4], bL[4];
                int row = warp_n*64 + nc*16 + (lane & 15);
                uint32_t off = row*LDA + (kb + (lane >> 4)*8)*2;
                ldsm4(bH, bh_b + off);
                ldsm4(bL, bl_b + off);
#pragma unroll
                for (int im = 0; im < 2; im++) {
                    float* a0 = acc[im][nc*2];
                    float* a1 = acc[im][nc*2 + 1];
                    mma_bf(a0, aH[im], bH[0], bH[2]);
                    mma_bf(a0, aH[im], bL[0], bL[2]);
                    mma_bf(a0, aL[im], bH[0], bH[2]);
                    mma_bf(a1, aH[im], bH[1], bH[3]);
                    mma_bf(a1, aH[im], bL[1], bL[3]);
                    mma_bf(a1, aL[im], bH[1], bH[3]);
                }
            }
        }
        __syncthreads();
    }

    int rbase = m0 + warp_m*32 + (lane >> 2);
    int cbase = n0 + warp_n*64 + (lane & 3)*2;
#pragma unroll
    for (int im = 0; im < 2; im++) {
#pragma unroll
        for (int nf = 0; nf < 8; nf++) {
            int m = rbase + im*16;
            int n = cbase + nf*8;
            float v0 = acc[im][nf][0], v1 = acc[im][nf][1];
            float v2 = acc[im][nf][2], v3 = acc[im][nf][3];
            if (bias)   { float b0 = bias[n], b1 = bias[n+1]; v0 += b0; v1 += b1; v2 += b0; v3 += b1; }
            if (rowaux) {
                float r0 = rowaux[(size_t)(m >> 5)*N + n],     r1 = rowaux[(size_t)(m >> 5)*N + n + 1];
                float r2 = rowaux[(size_t)((m+8) >> 5)*N + n], r3 = rowaux[(size_t)((m+8) >> 5)*N + n + 1];
                v0 += r0; v1 += r1; v2 += r2; v3 += r3;
            }
            *(float2*)&C[(size_t)m*N + n]     = make_float2(v0, v1);
            *(float2*)&C[(size_t)(m+8)*N + n] = make_float2(v2, v3);
        }
    }
}

// =====================================================================
//   fp16 single-pass GEMM (NT): D = Ah @ Bh^T  — logits
// =====================================================================
#define H1STAGE (2*PLANE)
#define H1SMEM_REQ (2*H1STAGE + 1024)

__global__ void __launch_bounds__(256) mma_gemm_nt_h1(
        const __half* __restrict__ Ah, const __half* __restrict__ Bh,
        float* __restrict__ C, int M, int N, int K, int ldb,
        const float* __restrict__ bias) {
    extern __shared__ char dsm[];
    char* base = (char*)((((uintptr_t)dsm) + 1023) & ~(uintptr_t)1023);
    uint32_t sb0 = smem_u32(base);

    int m0 = blockIdx.y * 128, n0 = blockIdx.x * 128;
    int tid = threadIdx.x;
    int lane = tid & 31, wid = tid >> 5;
    int warp_m = wid & 3, warp_n = wid >> 2;

    float acc[2][8][4];
#pragma unroll
    for (int i = 0; i < 2; i++)
#pragma unroll
        for (int j = 0; j < 8; j++)
#pragma unroll
            for (int q = 0; q < 4; q++) acc[i][j][q] = 0.f;

    int KT = K / KTILE;

    auto load_stage = [&](int s, int kt) {
        uint32_t st = sb0 + s*H1STAGE;
        uint32_t ah_s = st, bh_s = st + PLANE;
        int k0 = kt * KTILE;
#pragma unroll
        for (int i = 0; i < 2; i++) {
            int idx = tid + i*256;
            int row = idx >> 2, kc = idx & 3;
            uint32_t doff = row*LDA + kc*16;
            cpa16(ah_s + doff, Ah + (size_t)(m0 + row)*K + k0 + kc*8);
            cpa16(bh_s + doff, Bh + (size_t)(n0 + row)*ldb + k0 + kc*8);
        }
        cp_commit();
    };

    load_stage(0, 0);
    for (int kt = 0; kt < KT; kt++) {
        if (kt + 1 < KT) { load_stage((kt + 1) & 1, kt + 1); cp_wait<1>(); }
        else             { cp_wait<0>(); }
        __syncthreads();
        uint32_t st = sb0 + (kt & 1)*H1STAGE;
        uint32_t ah_b = st, bh_b = st + PLANE;
#pragma unroll
        for (int ks = 0; ks < 2; ks++) {
            int kb = ks*16;
            uint32_t aH[2][4];
#pragma unroll
            for (int im = 0; im < 2; im++) {
                int row = warp_m*32 + im*16 + (lane & 15);
                ldsm4(aH[im], ah_b + row*LDA + (kb + (lane >> 4)*8)*2);
            }
#pragma unroll
            for (int nc = 0; nc < 4; nc++) {
                uint32_t bH[4];
                int row = warp_n*64 + nc*16 + (lane & 15);
                ldsm4(bH, bh_b + row*LDA + (kb + (lane >> 4)*8)*2);
#pragma unroll
                for (int im = 0; im < 2; im++) {
                    mma_fp(acc[im][nc*2],     aH[im], bH[0], bH[2]);
                    mma_fp(acc[im][nc*2 + 1], aH[im], bH[1], bH[3]);
                }
            }
        }
        __syncthreads();
    }

    int rbase = m0 + warp_m*32 + (lane >> 2);
    int cbase = n0 + warp_n*64 + (lane & 3)*2;
#pragma unroll
    for (int im = 0; im < 2; im++) {
#pragma unroll
        for (int nf = 0; nf < 8; nf++) {
            int m = rbase + im*16;
            int n = cbase + nf*8;
            float v0 = acc[im][nf][0], v1 = acc[im][nf][1];
            float v2 = acc[im][nf][2], v3 = acc[im][nf][3];
            if (bias) { float b0 = bias[n], b1 = bias[n+1]; v0 += b0; v1 += b1; v2 += b0; v3 += b1; }
            *(float2*)&C[(size_t)m*N + n]     = make_float2(v0, v1);
            *(float2*)&C[(size_t)(m+8)*N + n] = make_float2(v2, v3);
        }
    }
}

// =====================================================================
//   fp16 single-pass GEMM (NN) with fused per-row stats — pointwise conv
// =====================================================================
#define HKT 64
#define HLDA 144
#define HLDB 272
#define HPA (128*HLDA)
#define HPB (64*HLDB)
#define HSTAGE (HPA + HPB)
#define HSMEM_REQ (2*HSTAGE + 1024)

__global__ void __launch_bounds__(256) hgemm_nn(
        const __half* __restrict__ A, const __half* __restrict__ B,
        __half* __restrict__ C, double2* __restrict__ part,
        int M, int N, int K, int ldb, size_t strideB, size_t strideC) {
    extern __shared__ char dsm[];
    char* base = (char*)((((uintptr_t)dsm) + 1023) & ~(uintptr_t)1023);
    uint32_t sb0 = smem_u32(base);

    const __half* Bb = B + (size_t)blockIdx.z * strideB;
    __half* Cb = C + (size_t)blockIdx.z * strideC;
    int m0 = blockIdx.x * 128, n0 = blockIdx.y * 128;   // m fast
    int nidx = blockIdx.y;
    int tid = threadIdx.x;
    int lane = tid & 31, wid = tid >> 5;
    int warp_m = wid & 3, warp_n = wid >> 2;

    float acc[2][8][4];
#pragma unroll
    for (int i = 0; i < 2; i++)
#pragma unroll
        for (int j = 0; j < 8; j++)
#pragma unroll
            for (int q = 0; q < 4; q++) acc[i][j][q] = 0.f;

    int KT = K / HKT;   // 4

    auto load_stage = [&](int s, int kt) {
        uint32_t st = sb0 + s*HSTAGE;
        uint32_t as = st, bs = st + HPA;
        int k0 = kt * HKT;
#pragma unroll
        for (int i = 0; i < 4; i++) {
            int idx = tid + i*256;
            int row = idx >> 3, kc = idx & 7;
            cpa16(as + row*HLDA + kc*16, A + (size_t)(m0 + row)*K + k0 + kc*8);
        }
#pragma unroll
        for (int i = 0; i < 4; i++) {
            int idx = tid + i*256;
            int row = idx >> 4, c = idx & 15;
            cpa16(bs + row*HLDB + c*16, Bb + (size_t)(k0 + row)*ldb + n0 + c*8);
        }
        cp_commit();
    };

    load_stage(0, 0);
    for (int kt = 0; kt < KT; kt++) {
        if (kt + 1 < KT) { load_stage((kt + 1) & 1, kt + 1); cp_wait<1>(); }
        else             { cp_wait<0>(); }
        __syncthreads();
        uint32_t st = sb0 + (kt & 1)*HSTAGE;
        uint32_t as = st, bs = st + HPA;
#pragma unroll
        for (int ks = 0; ks < 4; ks++) {
            int kb = ks*16;
            uint32_t aF[2][4];
#pragma unroll
            for (int im = 0; im < 2; im++) {
                int row = warp_m*32 + im*16 + (lane & 15);
                uint32_t off = row*HLDA + (kb + (lane >> 4)*8)*2;
                ldsm4(aF[im], as + off);
            }
#pragma unroll
            for (int nc = 0; nc < 4; nc++) {
                uint32_t bF[4];
                int row = kb + (lane & 15);
                int col = warp_n*64 + nc*16 + (lane >> 4)*8;
                ldsm4t(bF, bs + row*HLDB + col*2);
#pragma unroll
                for (int im = 0; im < 2; im++) {
                    mma_fp(acc[im][nc*2],     aF[im], bF[0], bF[1]);
                    mma_fp(acc[im][nc*2 + 1], aF[im], bF[2], bF[3]);
                }
            }
        }
        __syncthreads();
    }

    // ---- epilogue: fp16 store + per-row (channel) sum/sumsq ----
    int rloc = warp_m*32 + (lane >> 2);
    int cbase = n0 + warp_n*64 + (lane & 3)*2;
    float s[4]  = {0.f, 0.f, 0.f, 0.f};
    float s2[4] = {0.f, 0.f, 0.f, 0.f};
#pragma unroll
    for (int im = 0; im < 2; im++) {
#pragma unroll
        for (int nf = 0; nf < 8; nf++) {
            int m = m0 + rloc + im*16;
            int n = cbase + nf*8;
            float v0 = acc[im][nf][0], v1 = acc[im][nf][1];
            float v2 = acc[im][nf][2], v3 = acc[im][nf][3];
            __half2 h01 = __floats2half2_rn(v0, v1);
            __half2 h23 = __floats2half2_rn(v2, v3);
            *(__half2*)&Cb[(size_t)m*N + n]     = h01;
            *(__half2*)&Cb[(size_t)(m+8)*N + n] = h23;
            s [im*2+0] += v0 + v1;    s2[im*2+0] += v0*v0 + v1*v1;
            s [im*2+1] += v2 + v3;    s2[im*2+1] += v2*v2 + v3*v3;
        }
    }
#pragma unroll
    for (int r = 0; r < 4; r++) {
        s [r] += __shfl_xor_sync(0xffffffffu, s [r], 1);
        s [r] += __shfl_xor_sync(0xffffffffu, s [r], 2);
        s2[r] += __shfl_xor_sync(0xffffffffu, s2[r], 1);
        s2[r] += __shfl_xor_sync(0xffffffffu, s2[r], 2);
    }
    float2* sst = (float2*)base;
    __syncthreads();
    if ((lane & 3) == 0) {
#pragma unroll
        for (int r = 0; r < 4; r++) {
            int row = rloc + (r >> 1)*16 + (r & 1)*8;
            sst[warp_n*128 + row] = make_float2(s[r], s2[r]);
        }
    }
    __syncthreads();
    if (tid < 128) {
        float2 a = sst[tid], b = sst[128 + tid];
        double2 p;
        p.x = (double)a.x + (double)b.x;
        p.y = (double)a.y + (double)b.y;
        part[(size_t)(m0 + tid)*(BSZ*98) + blockIdx.z*98 + nidx] = p;
    }
}

// finalize BN2 scale/shift from fused partials; warp per channel
__global__ void chan_finalize2(const double2* __restrict__ part,
                               const float* __restrict__ g, const float* __restrict__ bt,
                               float* __restrict__ scale, float* __restrict__ shift) {
    int warp = (blockIdx.x*256 + threadIdx.x) >> 5;
    int lane = threadIdx.x & 31;
    if (warp >= C2) return;
    double s = 0, s2 = 0;
    for (int i = lane; i < BSZ*98; i += 32) {
        double2 p = part[(size_t)warp*(BSZ*98) + i];
        s += p.x; s2 += p.y;
    }
#pragma unroll
    for (int o = 16; o; o >>= 1) {
        s  += __shfl_xor_sync(0xffffffffu, s,  o);
        s2 += __shfl_xor_sync(0xffffffffu, s2, o);
    }
    if (lane == 0) {
        double cnt = (double)BSZ * HW;
        double m = s / cnt;
        double var = s2 / cnt - m*m;
        float rs = (float)(1.0 / sqrt(var + 1e-5));
        float sc = g[warp] * rs;
        scale[warp] = sc;
        shift[warp] = bt[warp] - (float)m * sc;
    }
}

// =====================================================================
//   conv1 as fp16 implicit GEMM + fused BN1 stats
//   (stats accumulated into SHARED after each half — keeps register
//    lifetime short so the two halves reuse the accumulator file)
// =====================================================================
__global__ void __launch_bounds__(256) conv1_igemm(
        const float* __restrict__ img, const float* __restrict__ w,
        __half* __restrict__ out, float2* __restrict__ part1) {
    __shared__ __half wt [256*40];
    __shared__ __half imt[128*40];
    __shared__ float  inr[9*224];
    __shared__ float2 sst[256];
    int oy = blockIdx.x, b = blockIdx.y;
    int tid = threadIdx.x;
    int lane = tid & 31, wid = tid >> 5;

    sst[tid] = make_float2(0.f, 0.f);
    for (int i = tid; i < 256*32; i += 256) {
        int c = i >> 5, k = i & 31;
        float v = (k < 27) ? __ldg(&w[c*27 + k]) : 0.f;
        wt[c*40 + k] = __float2half_rn(v);
    }
    const float* ip = img + (size_t)b*3*224*224;
    for (int i = tid; i < 9*224; i += 256) {
        int r = i / 224, x = i - r*224;
        int ci = r / 3, ky = r - ci*3;
        int iy = oy*2 - 1 + ky;
        inr[i] = (iy >= 0 && iy < 224) ? ip[(ci*224 + iy)*224 + x] : 0.f;
    }
    __syncthreads();
    for (int i = tid; i < 128*32; i += 256) {
        int p = i >> 5, k = i & 31;
        float v = 0.f;
        if (p < 112 && k < 27) {
            int ci = k / 9, r = k - ci*9;
            int ky = r / 3, kx = r - ky*3;
            int ix = p*2 - 1 + kx;
            if (ix >= 0 && ix < 224) v = inr[(ci*3 + ky)*224 + ix];
        }
        imt[p*40 + k] = __float2half_rn(v);
    }
    __syncthreads();

    uint32_t wt_b = smem_u32(wt), imt_b = smem_u32(imt);
    size_t obase = (size_t)b*C1*HW + (size_t)oy*112;
#pragma unroll
    for (int half = 0; half < 2; half++) {
        float acc[2][8][4];
#pragma unroll
        for (int i = 0; i < 2; i++)
#pragma unroll
            for (int j = 0; j < 8; j++)
#pragma unroll
                for (int q = 0; q < 4; q++) acc[i][j][q] = 0.f;
#pragma unroll
        for (int ks = 0; ks < 2; ks++) {
            int kb = ks*16;
            uint32_t aF[2][4];
#pragma unroll
            for (int im = 0; im < 2; im++) {
                int row = wid*32 + im*16 + (lane & 15);
                ldsm4(aF[im], wt_b + (row*40 + kb + (lane >> 4)*8)*2);
            }
#pragma unroll
            for (int nc = 0; nc < 4; nc++) {
                uint32_t bF[4];
                int row = half*64 + nc*16 + (lane & 15);
                ldsm4(bF, imt_b + (row*40 + kb + (lane >> 4)*8)*2);
#pragma unroll
                for (int im = 0; im < 2; im++) {
                    mma_fp(acc[im][nc*2],     aF[im], bF[0], bF[2]);
                    mma_fp(acc[im][nc*2 + 1], aF[im], bF[1], bF[3]);
                }
            }
        }
        // epilogue for this half: store + local stats (short register lifetime)
        float s[4]  = {0.f, 0.f, 0.f, 0.f};
        float s2[4] = {0.f, 0.f, 0.f, 0.f};
#pragma unroll
        for (int im = 0; im < 2; im++) {
#pragma unroll
            for (int nf = 0; nf < 8; nf++) {
                int m = wid*32 + im*16 + (lane >> 2);
                int n = half*64 + nf*8 + (lane & 3)*2;
                if (n < 112) {
                    float v0 = acc[im][nf][0], v1 = acc[im][nf][1];
                    float v2 = acc[im][nf][2], v3 = acc[im][nf][3];
                    __half2 h01 = __floats2half2_rn(v0, v1);
                    __half2 h23 = __floats2half2_rn(v2, v3);
                    *(__half2*)&out[obase + (size_t)m*HW + n]     = h01;
                    *(__half2*)&out[obase + (size_t)(m+8)*HW + n] = h23;
                    s [im*2+0] += v0 + v1;   s2[im*2+0] += v0*v0 + v1*v1;
                    s [im*2+1] += v2 + v3;   s2[im*2+1] += v2*v2 + v3*v3;
                }
            }
        }
#pragma unroll
        for (int r = 0; r < 4; r++) {
            s [r] += __shfl_xor_sync(0xffffffffu, s [r], 1);
            s [r] += __shfl_xor_sync(0xffffffffu, s [r], 2);
            s2[r] += __shfl_xor_sync(0xffffffffu, s2[r], 1);
            s2[r] += __shfl_xor_sync(0xffffffffu, s2[r], 2);
        }
        if ((lane & 3) == 0) {
#pragma unroll
            for (int r = 0; r < 4; r++) {
                int row = wid*32 + (r >> 1)*16 + (r & 1)*8 + (lane >> 2);
                float2 p = sst[row];
                p.x += s[r]; p.y += s2[r];
                sst[row] = p;     // unique writer per row (same thread both halves)
            }
        }
    }
    __syncthreads();
    {
        float2 p = sst[tid];
        part1[(size_t)tid*(BSZ*112) + b*112 + oy] = p;
    }
}

// finalize BN1 from fused float2 partials (1792 per channel); warp per channel
__global__ void chan_finalize1(const float2* __restrict__ part,
                               const float* __restrict__ g, const float* __restrict__ bt,
                               float* __restrict__ scale, float* __restrict__ shift) {
    int warp = (blockIdx.x*256 + threadIdx.x) >> 5;
    int lane = threadIdx.x & 31;
    if (warp >= C1) return;
    double s = 0, s2 = 0;
    for (int i = lane; i < BSZ*112; i += 32) {
        float2 p = part[(size_t)warp*(BSZ*112) + i];
        s += (double)p.x; s2 += (double)p.y;
    }
#pragma unroll
    for (int o = 16; o; o >>= 1) {
        s  += __shfl_xor_sync(0xffffffffu, s,  o);
        s2 += __shfl_xor_sync(0xffffffffu, s2, o);
    }
    if (lane == 0) {
        double cnt = (double)BSZ * HW;
        double m = s / cnt;
        double var = s2 / cnt - m*m;
        float rs = (float)(1.0 / sqrt(var + 1e-5));
        float sc = g[warp] * rs;
        scale[warp] = sc;
        shift[warp] = bt[warp] - (float)m * sc;
    }
}

// ---------------- depthwise 3x3 s1 p1 (BN1+ReLU fused), fp16 in/out -------------
__global__ void dw_kernel(const __half* __restrict__ in, const float* __restrict__ w,
                          const float* __restrict__ scale, const float* __restrict__ shift,
                          __half* __restrict__ outh) {
    int warp = threadIdx.x >> 5, lane = threadIdx.x & 31;
    int y = blockIdx.x*8 + warp;
    int c = blockIdx.y, b = blockIdx.z;
    float sc = scale[c], sh = shift[c];
    const __half* ip = in + ((size_t)b*C1 + c)*HW;
    int x0 = lane*4;
    bool inx = (x0 < 112);

    float v[3][4];
    float lft[3], rgt[3];
#pragma unroll
    for (int r = 0; r < 3; r++) {
        int yy = y - 1 + r;
        float t0 = 0.f, t1 = 0.f, t2 = 0.f, t3 = 0.f;
        if (inx && yy >= 0 && yy < 112) {
            uint2 u = *(const uint2*)&ip[yy*112 + x0];
            float2 p0 = __half22float2(*(__half2*)&u.x);
            float2 p1 = __half22float2(*(__half2*)&u.y);
            t0 = p0.x; t1 = p0.y; t2 = p1.x; t3 = p1.y;
        }
        v[r][0] = fmaxf(t0*sc + sh, 0.f);
        v[r][1] = fmaxf(t1*sc + sh, 0.f);
        v[r][2] = fmaxf(t2*sc + sh, 0.f);
        v[r][3] = fmaxf(t3*sc + sh, 0.f);
        if (!inx || yy < 0 || yy >= 112) { v[r][0]=v[r][1]=v[r][2]=v[r][3]=0.f; }
        lft[r] = __shfl_up_sync(0xffffffffu, v[r][3], 1);
        if (lane == 0) lft[r] = 0.f;
        rgt[r] = __shfl_down_sync(0xffffffffu, v[r][0], 1);
        if (lane >= 27) rgt[r] = 0.f;
    }
    float wv[9];
#pragma unroll
    for (int k = 0; k < 9; k++) wv[k] = __ldg(&w[c*9 + k]);

    float o0 = 0.f, o1 = 0.f, o2 = 0.f, o3 = 0.f;
#pragma unroll
    for (int r = 0; r < 3; r++) {
        float e0 = lft[r], e1 = v[r][0], e2 = v[r][1], e3 = v[r][2], e4 = v[r][3], e5 = rgt[r];
        float w0 = wv[r*3+0], w1 = wv[r*3+1], w2 = wv[r*3+2];
        o0 += w0*e0 + w1*e1 + w2*e2;
        o1 += w0*e1 + w1*e2 + w2*e3;
        o2 += w0*e2 + w1*e3 + w2*e4;
        o3 += w0*e3 + w1*e4 + w2*e5;
    }
    if (inx) {
        __half2 h01 = __floats2half2_rn(o0, o1);
        __half2 h23 = __floats2half2_rn(o2, o3);
        size_t off = ((size_t)b*C1 + c)*HW + y*112 + x0;
        *(uint2*)&outh[off] = make_uint2(*(uint32_t*)&h01, *(uint32_t*)&h23);
    }
}

// ---------------- pooled[b][c] = mean_p relu(bn2(pw)), fp16 source ----------------
__global__ void pooled_kernel(const __half* __restrict__ x, const float* __restrict__ scale,
                              const float* __restrict__ shift, float* __restrict__ pooled) {
    int c = blockIdx.x, b = blockIdx.y;
    const __half2* p = (const __half2*)(x + ((size_t)b*C2 + c)*HW);
    float sc = scale[c], sh = shift[c];
    double s = 0;
    for (int i = threadIdx.x; i < HW/2; i += 256) {
        float2 v = __half22float2(p[i]);
        float a = v.x*sc + sh, bq = v.y*sc + sh;
        if (a > 0.f) s += a;
        if (bq > 0.f) s += bq;
    }
    __shared__ double shm[256];
    shm[threadIdx.x] = s; __syncthreads();
    for (int o = 128; o; o >>= 1) {
        if (threadIdx.x < o) shm[threadIdx.x] += shm[threadIdx.x+o];
        __syncthreads();
    }
    if (threadIdx.x == 0) pooled[b*C2 + c] = (float)(shm[0] / (double)HW);
}

// ---------------- small GEMM ----------------
__global__ void small_gemm(const float* __restrict__ in, int K,
                           const float* __restrict__ W, int ldw, int woff,
                           const float* __restrict__ bias, const float* __restrict__ aux,
                           int O, int act, float* __restrict__ out) {
    __shared__ float sin_s[BSZ*512];
    for (int i = threadIdx.x; i < BSZ*K; i += 256) sin_s[i] = in[i];
    __syncthreads();
    int warp = threadIdx.x >> 5, lane = threadIdx.x & 31;
    int o = blockIdx.x*8 + warp;
    float part[BSZ];
#pragma unroll
    for (int b = 0; b < BSZ; b++) part[b] = 0.f;
    for (int k = lane; k < K; k += 32) {
        float wv = W[(size_t)o*ldw + woff + k];
#pragma unroll
        for (int b = 0; b < BSZ; b++) part[b] += wv * sin_s[b*K + k];
    }
#pragma unroll
    for (int b = 0; b < BSZ; b++) {
        float v = part[b];
#pragma unroll
        for (int off = 16; off; off >>= 1) v += __shfl_xor_sync(0xffffffffu, v, off);
        if (lane == b) {
            if (bias) v += bias[o];
            if (act == 1) v = v > 0.f ? v : 0.f;
            else if (act == 2) v = (1.f/(1.f + expf(-v))) * aux[b*O + o];
            out[b*O + o] = v;
        }
    }
}

// ---------------- gather caption embeddings: bf16 split planes ----------------
__global__ void gather_embs(const int* __restrict__ cap, const float* __restrict__ embed,
                            __nv_bfloat16* __restrict__ eh, __nv_bfloat16* __restrict__ el) {
    int row = blockIdx.x;
    int b = row >> 5, t = row & 31;
    int tok = cap[b*33 + t];
    const float* src = embed + (size_t)tok*HID;
    int i = threadIdx.x*2;
    float2 v = *(const float2*)&src[i];
    float h0,l0,h1,l1;
    split2(v.x,h0,l0); split2(v.y,h1,l1);
    *(uint32_t*)&eh[(size_t)row*HID + i] = pack_bf2(h0,h1);
    *(uint32_t*)&el[(size_t)row*HID + i] = pack_bf2(l0,l1);
}

// ---------------- persistent GRU (hall fp16 for logits) ----------------
__global__ void gru_reset() {
    if (threadIdx.x < TT) g_gbar[threadIdx.x] = 0;
}
#define GRU_BLKS 64
__global__ void __launch_bounds__(256) gru_persist(
        const float* __restrict__ gi, const float* __restrict__ whh,
        const float* __restrict__ bhh, float* __restrict__ hall,
        __half* __restrict__ hallh) {
    __shared__ float hs[BSZ*HID];
    int tid = threadIdx.x;
    int warp = tid >> 5, lane = tid & 31;
    int j = blockIdx.x*8 + warp;
    float w0[16], w1[16], w2[16];
#pragma unroll
    for (int i = 0; i < 16; i++) {
        int k = lane + 32*i;
        w0[i] = whh[(size_t)j*HID + k];
        w1[i] = whh[(size_t)(j + 512)*HID + k];
        w2[i] = whh[(size_t)(j + 1024)*HID + k];
    }
    float bhr = bhh[j], bhz = bhh[j + 512], bhn = bhh[j + 1024];

    for (int t = 0; t < TT; t++) {
        for (int i = tid; i < BSZ*HID; i += 256) {
            int b = i >> 9, jj = i & 511;
            hs[i] = (t == 0) ? 0.f : hall[((size_t)(b*TT + t - 1))*HID + jj];
        }
        __syncthreads();
        for (int b = 0; b < BSZ; b++) {
            float pr = 0.f, pz = 0.f, pn = 0.f;
#pragma unroll
            for (int i = 0; i < 16; i++) {
                float hv = hs[b*HID + lane + 32*i];
                pr += hv*w0[i]; pz += hv*w1[i]; pn += hv*w2[i];
            }
#pragma unroll
            for (int o = 16; o; o >>= 1) {
                pr += __shfl_xor_sync(0xffffffffu, pr, o);
                pz += __shfl_xor_sync(0xffffffffu, pz, o);
                pn += __shfl_xor_sync(0xffffffffu, pn, o);
            }
            if (lane == 0) {
                size_t gib = ((size_t)(b*TT + t))*1536;
                float ir = gi[gib + j], iz = gi[gib + 512 + j], inn = gi[gib + 1024 + j];
                float r = 1.f/(1.f + expf(-(ir + pr + bhr)));
                float z = 1.f/(1.f + expf(-(iz + pz + bhz)));
                float n = tanhf(inn + r*(pn + bhn));
                float hp = hs[b*HID + j];
                float hn2 = (1.f - z)*n + z*hp;
                size_t oidx = ((size_t)(b*TT + t))*HID + j;
                hall[oidx] = hn2;
                hallh[oidx] = __float2half_rn(hn2);
            }
        }
        __threadfence();
        __syncthreads();
        if (tid == 0) {
            atomicAdd(&g_gbar[t], 1);
            while (atomicAdd(&g_gbar[t], 0) < GRU_BLKS) __nanosleep(64);
        }
        __syncthreads();
    }
}

// =======================================================================
extern "C" void kernel_launch(void* const* d_in, const int* in_sizes, int n_in,
                              void* d_out, int out_size) {
    const float* images   = (const float*)d_in[0];
    const int*   captions = (const int*)  d_in[1];
    const float* conv1_w  = (const float*)d_in[2];
    const float* bn1_g    = (const float*)d_in[3];
    const float* bn1_b    = (const float*)d_in[4];
    const float* dw_w     = (const float*)d_in[5];
    const float* pw_w     = (const float*)d_in[6];
    const float* bn2_g    = (const float*)d_in[7];
    const float* bn2_b    = (const float*)d_in[8];
    const float* se_fc1_w = (const float*)d_in[9];
    const float* se_fc2_w = (const float*)d_in[10];
    const float* enc_fc_w = (const float*)d_in[11];
    const float* enc_fc_b = (const float*)d_in[12];
    const float* embed    = (const float*)d_in[13];
    // d_in[14] = q_w (unused), d_in[15] = k_w (unused)
    const float* v_w      = (const float*)d_in[16];
    const float* gru_w_ih = (const float*)d_in[17];
    const float* gru_w_hh = (const float*)d_in[18];
    const float* gru_b_ih = (const float*)d_in[19];
    const float* gru_b_hh = (const float*)d_in[20];
    const float* fc_w     = (const float*)d_in[21];
    const float* fc_b     = (const float*)d_in[22];

    __half *conv1buf;
    float2 *part1;
    double2 *part2;
    float *scale1, *shift1, *scale2, *shift2;
    float *pooled, *t1, *fbuf, *feats, *ctx, *gctx, *gi, *hall;
    __half *dwh, *pwwh, *pwout, *fcwh, *hallh;
    __nv_bfloat16 *wihh, *wihl, *embsh, *embsl;
    cudaGetSymbolAddress((void**)&conv1buf, g_conv1);
    cudaGetSymbolAddress((void**)&part1,    g_part1);
    cudaGetSymbolAddress((void**)&part2,    g_part2);
    cudaGetSymbolAddress((void**)&scale1,   g_scale1);
    cudaGetSymbolAddress((void**)&shift1,   g_shift1);
    cudaGetSymbolAddress((void**)&scale2,   g_scale2);
    cudaGetSymbolAddress((void**)&shift2,   g_shift2);
    cudaGetSymbolAddress((void**)&pooled,   g_pooled);
    cudaGetSymbolAddress((void**)&t1,       g_t1);
    cudaGetSymbolAddress((void**)&fbuf,     g_f);
    cudaGetSymbolAddress((void**)&feats,    g_feats);
    cudaGetSymbolAddress((void**)&ctx,      g_ctx);
    cudaGetSymbolAddress((void**)&gctx,     g_gctx);
    cudaGetSymbolAddress((void**)&gi,       g_gi);
    cudaGetSymbolAddress((void**)&hall,     g_hall);
    cudaGetSymbolAddress((void**)&dwh,      g_dwh);
    cudaGetSymbolAddress((void**)&pwwh,     g_pwwh);
    cudaGetSymbolAddress((void**)&pwout,    g_pwout);
    cudaGetSymbolAddress((void**)&fcwh,     g_fcwh);
    cudaGetSymbolAddress((void**)&wihh,     g_wihh);
    cudaGetSymbolAddress((void**)&wihl,     g_wihl);
    cudaGetSymbolAddress((void**)&embsh,    g_embsh);
    cudaGetSymbolAddress((void**)&embsl,    g_embsl);
    cudaGetSymbolAddress((void**)&hallh,    g_hallh);

    cudaFuncSetAttribute(mma_gemm_nt,    cudaFuncAttributeMaxDynamicSharedMemorySize, SMEM_REQ);
    cudaFuncSetAttribute(mma_gemm_nt_h1, cudaFuncAttributeMaxDynamicSharedMemorySize, H1SMEM_REQ);
    cudaFuncSetAttribute(hgemm_nn,       cudaFuncAttributeMaxDynamicSharedMemorySize, HSMEM_REQ);

    // weight conversions (independent of encoder)
    to_half<<<(C2*C1)/1024, 256>>>(pw_w, pwwh, (size_t)C2*C1);
    to_half<<<((size_t)VOC*HID)/1024, 256>>>(fc_w, fcwh, (size_t)VOC*HID);
    split_strided<<<(1536*512)/1024, 256>>>(gru_w_ih, 1024, wihh, wihl);

    // encoder
    conv1_igemm<<<dim3(112, BSZ), 256>>>(images, conv1_w, conv1buf, part1);
    chan_finalize1<<<32, 256>>>(part1, bn1_g, bn1_b, scale1, shift1);
    dw_kernel<<<dim3(14, C1, BSZ), 256>>>(conv1buf, dw_w, scale1, shift1, dwh);
    // pointwise conv (fp16 single-pass GEMM, fused BN2 stats)
    hgemm_nn<<<dim3(4, 98, BSZ), 256, HSMEM_REQ>>>(pwwh, dwh, pwout, part2,
                                                   C2, HW, C1, HW,
                                                   (size_t)C1*HW, (size_t)C2*HW);
    chan_finalize2<<<64, 256>>>(part2, bn2_g, bn2_b, scale2, shift2);
    pooled_kernel<<<dim3(C2, BSZ), 256>>>(pwout, scale2, shift2, pooled);

    // SE + encoder FC + ctx (tiny GEMMs)
    small_gemm<<<16, 256>>>(pooled, 512, se_fc1_w, 512, 0, nullptr, nullptr, 128, 1, t1);
    small_gemm<<<64, 256>>>(t1, 128, se_fc2_w, 128, 0, nullptr, pooled, 512, 2, fbuf);
    small_gemm<<<64, 256>>>(fbuf, 512, enc_fc_w, 512, 0, enc_fc_b, nullptr, 512, 0, feats);
    small_gemm<<<64, 256>>>(feats, 512, v_w, 512, 0, nullptr, nullptr, 512, 0, ctx);

    // decoder: precompute input gates (bf16 3-pass — precision-critical via GRU)
    small_gemm<<<192, 256>>>(ctx, 512, gru_w_ih, 1024, 512, gru_b_ih, nullptr, 1536, 0, gctx);
    gather_embs<<<512, 256>>>(captions, embed, embsh, embsl);
    mma_gemm_nt<<<dim3(12, 4, 1), 256, SMEM_REQ>>>(embsh, embsl, wihh, wihl, gi,
                                                   512, 1536, 512, 512, nullptr, gctx);

    // persistent GRU recurrence
    gru_reset<<<1, 32>>>();
    gru_persist<<<GRU_BLKS, 256>>>(gi, gru_w_hh, gru_b_hh, hall, hallh);

    // logits: fp16 single-pass
    mma_gemm_nt_h1<<<dim3(250, 4, 1), 256, H1SMEM_REQ>>>(hallh, fcwh, (float*)d_out,
                                                         512, VOC, 512, 512, fc_b);
}

// round 16
// speedup vs baseline: 1.3488x; 1.0126x over previous
#include <cuda_runtime.h>
#include <cuda_bf16.h>
#include <cuda_fp16.h>
#include <math.h>
#include <stdint.h>

#define BSZ 16
#define HW 12544
#define C1 256
#define C2 512
#define TT 32
#define HID 512
#define VOC 32000

// ---------------- scratch (static device arrays; no allocation) ----------------
__device__ __half  g_conv1[(size_t)BSZ*C1*HW];
__device__ float2  g_part1[(size_t)C1*BSZ*112];
__device__ double2 g_part2[(size_t)C2*BSZ*98];
__device__ float   g_scale1[C1], g_shift1[C1];
__device__ float   g_scale2[C2], g_shift2[C2];
__device__ float   g_pooled[BSZ*C2], g_t1[BSZ*128], g_f[BSZ*C2], g_feats[BSZ*C2], g_ctx[BSZ*C2];
__device__ float   g_gctx[BSZ*1536];
__device__ float   g_gi  [(size_t)BSZ*TT*1536];
__device__ float   g_hall[(size_t)BSZ*TT*HID];
__device__ int     g_gbar[TT];

// fp16 planes
__device__ __half g_dwh[(size_t)BSZ*C1*HW];
__device__ __half g_pwwh[C2*C1];
__device__ __half g_pwout[(size_t)BSZ*C2*HW];
__device__ __half g_fcwh[(size_t)VOC*HID];   // fc_w fp16
__device__ __half g_hallh[512*HID];          // hall fp16 (single plane)
// bf16 hi/lo planes for the gi GEMM (3-pass, precision-critical path kept)
__device__ __nv_bfloat16 g_wihh[1536*HID],  g_wihl[1536*HID];
__device__ __nv_bfloat16 g_embsh[512*HID],  g_embsl[512*HID];

// =====================================================================
//                    helpers
// =====================================================================
__device__ __forceinline__ uint32_t smem_u32(const void* p) {
    uint32_t a;
    asm("{ .reg .u64 t; cvta.to.shared.u64 t, %1; cvt.u32.u64 %0, t; }" : "=r"(a) : "l"(p));
    return a;
}
__device__ __forceinline__ void ldsm4(uint32_t* r, uint32_t addr) {
    asm volatile("ldmatrix.sync.aligned.m8n8.x4.shared.b16 {%0,%1,%2,%3}, [%4];"
                 : "=r"(r[0]), "=r"(r[1]), "=r"(r[2]), "=r"(r[3]) : "r"(addr));
}
__device__ __forceinline__ void ldsm4t(uint32_t* r, uint32_t addr) {
    asm volatile("ldmatrix.sync.aligned.m8n8.x4.trans.shared.b16 {%0,%1,%2,%3}, [%4];"
                 : "=r"(r[0]), "=r"(r[1]), "=r"(r[2]), "=r"(r[3]) : "r"(addr));
}
__device__ __forceinline__ void mma_bf(float* d, const uint32_t* a, uint32_t b0, uint32_t b1) {
    asm volatile(
        "mma.sync.aligned.m16n8k16.row.col.f32.bf16.bf16.f32 "
        "{%0,%1,%2,%3}, {%4,%5,%6,%7}, {%8,%9}, {%0,%1,%2,%3};"
        : "+f"(d[0]), "+f"(d[1]), "+f"(d[2]), "+f"(d[3])
        : "r"(a[0]), "r"(a[1]), "r"(a[2]), "r"(a[3]), "r"(b0), "r"(b1));
}
__device__ __forceinline__ void mma_fp(float* d, const uint32_t* a, uint32_t b0, uint32_t b1) {
    asm volatile(
        "mma.sync.aligned.m16n8k16.row.col.f32.f16.f16.f32 "
        "{%0,%1,%2,%3}, {%4,%5,%6,%7}, {%8,%9}, {%0,%1,%2,%3};"
        : "+f"(d[0]), "+f"(d[1]), "+f"(d[2]), "+f"(d[3])
        : "r"(a[0]), "r"(a[1]), "r"(a[2]), "r"(a[3]), "r"(b0), "r"(b1));
}
__device__ __forceinline__ uint32_t pack_bf2(float lo, float hi) {
    uint32_t r;
    asm("cvt.rn.bf16x2.f32 %0, %1, %2;" : "=r"(r) : "f"(hi), "f"(lo));
    return r;
}
__device__ __forceinline__ void split2(float x, float& h, float& l) {
    h = __bfloat162float(__float2bfloat16(x));
    l = x - h;
}
__device__ __forceinline__ void cpa16(uint32_t dst, const void* src) {
    asm volatile("cp.async.cg.shared.global [%0], [%1], 16;" :: "r"(dst), "l"(src));
}
__device__ __forceinline__ void cp_commit() { asm volatile("cp.async.commit_group;"); }
template<int NW> __device__ __forceinline__ void cp_wait() {
    asm volatile("cp.async.wait_group %0;" :: "n"(NW));
}

// =====================================================================
//   conversion kernels
// =====================================================================
__global__ void split_strided(const float* __restrict__ src, int ld,
                              __nv_bfloat16* __restrict__ dh, __nv_bfloat16* __restrict__ dl) {
    size_t i = ((size_t)blockIdx.x*256 + threadIdx.x)*4;
    int row = (int)(i >> 9), col = (int)(i & 511);
    float4 v = *(const float4*)&src[(size_t)row*ld + col];
    float hx, lx, hy, ly, hz, lz, hw, lw;
    split2(v.x, hx, lx); split2(v.y, hy, ly); split2(v.z, hz, lz); split2(v.w, hw, lw);
    *(uint2*)&dh[i] = make_uint2(pack_bf2(hx, hy), pack_bf2(hz, hw));
    *(uint2*)&dl[i] = make_uint2(pack_bf2(lx, ly), pack_bf2(lz, lw));
}
__global__ void to_half(const float* __restrict__ src, __half* __restrict__ dst, size_t n) {
    size_t i = ((size_t)blockIdx.x*256 + threadIdx.x)*4;
    if (i >= n) return;
    float4 v = *(const float4*)&src[i];
    __half2 a = __floats2half2_rn(v.x, v.y), b = __floats2half2_rn(v.z, v.w);
    *(uint2*)&dst[i] = make_uint2(*(uint32_t*)&a, *(uint32_t*)&b);
}

// =====================================================================
//   bf16 3-pass GEMM (NT) — gi only
// =====================================================================
#define KTILE 32
#define LDA   80
#define PLANE 10240
#define STAGE (4*PLANE)
#define SMEM_REQ (2*STAGE + 1024)

__global__ void __launch_bounds__(256) mma_gemm_nt(
        const __nv_bfloat16* __restrict__ Ah, const __nv_bfloat16* __restrict__ Al,
        const __nv_bfloat16* __restrict__ Bh, const __nv_bfloat16* __restrict__ Bl,
        float* __restrict__ C, int M, int N, int K, int ldb,
        const float* __restrict__ bias, const float* __restrict__ rowaux) {
    extern __shared__ char dsm[];
    char* base = (char*)((((uintptr_t)dsm) + 1023) & ~(uintptr_t)1023);
    uint32_t sb0 = smem_u32(base);

    int m0 = blockIdx.y * 128, n0 = blockIdx.x * 128;
    int tid = threadIdx.x;
    int lane = tid & 31, wid = tid >> 5;
    int warp_m = wid & 3, warp_n = wid >> 2;

    float acc[2][8][4];
#pragma unroll
    for (int i = 0; i < 2; i++)
#pragma unroll
        for (int j = 0; j < 8; j++)
#pragma unroll
            for (int q = 0; q < 4; q++) acc[i][j][q] = 0.f;

    int KT = K / KTILE;

    auto load_stage = [&](int s, int kt) {
        uint32_t st = sb0 + s*STAGE;
        uint32_t ah_s = st, al_s = st + PLANE, bh_s = st + 2*PLANE, bl_s = st + 3*PLANE;
        int k0 = kt * KTILE;
#pragma unroll
        for (int i = 0; i < 2; i++) {
            int idx = tid + i*256;
            int row = idx >> 2, kc = idx & 3;
            uint32_t doff = row*LDA + kc*16;
            cpa16(ah_s + doff, Ah + (size_t)(m0 + row)*K + k0 + kc*8);
            cpa16(al_s + doff, Al + (size_t)(m0 + row)*K + k0 + kc*8);
            cpa16(bh_s + doff, Bh + (size_t)(n0 + row)*ldb + k0 + kc*8);
            cpa16(bl_s + doff, Bl + (size_t)(n0 + row)*ldb + k0 + kc*8);
        }
        cp_commit();
    };

    load_stage(0, 0);
    for (int kt = 0; kt < KT; kt++) {
        if (kt + 1 < KT) { load_stage((kt + 1) & 1, kt + 1); cp_wait<1>(); }
        else             { cp_wait<0>(); }
        __syncthreads();
        uint32_t st = sb0 + (kt & 1)*STAGE;
        uint32_t ah_b = st, al_b = st + PLANE, bh_b = st + 2*PLANE, bl_b = st + 3*PLANE;
#pragma unroll
        for (int ks = 0; ks < 2; ks++) {
            int kb = ks*16;
            uint32_t aH[2][4], aL[2][4];
#pragma unroll
            for (int im = 0; im < 2; im++) {
                int row = warp_m*32 + im*16 + (lane & 15);
                uint32_t off = row*LDA + (kb + (lane >> 4)*8)*2;
                ldsm4(aH[im], ah_b + off);
                ldsm4(aL[im], al_b + off);
            }
#pragma unroll
            for (int nc = 0; nc < 4; nc++) {
                uint32_t bH[4], bL[4];
                int row = warp_n*64 + nc*16 + (lane & 15);
                uint32_t off = row*LDA + (kb + (lane >> 4)*8)*2;
                ldsm4(bH, bh_b + off);
                ldsm4(bL, bl_b + off);
#pragma unroll
                for (int im = 0; im < 2; im++) {
                    float* a0 = acc[im][nc*2];
                    float* a1 = acc[im][nc*2 + 1];
                    mma_bf(a0, aH[im], bH[0], bH[2]);
                    mma_bf(a0, aH[im], bL[0], bL[2]);
                    mma_bf(a0, aL[im], bH[0], bH[2]);
                    mma_bf(a1, aH[im], bH[1], bH[3]);
                    mma_bf(a1, aH[im], bL[1], bL[3]);
                    mma_bf(a1, aL[im], bH[1], bH[3]);
                }
            }
        }
        __syncthreads();
    }

    int rbase = m0 + warp_m*32 + (lane >> 2);
    int cbase = n0 + warp_n*64 + (lane & 3)*2;
#pragma unroll
    for (int im = 0; im < 2; im++) {
#pragma unroll
        for (int nf = 0; nf < 8; nf++) {
            int m = rbase + im*16;
            int n = cbase + nf*8;
            float v0 = acc[im][nf][0], v1 = acc[im][nf][1];
            float v2 = acc[im][nf][2], v3 = acc[im][nf][3];
            if (bias)   { float b0 = bias[n], b1 = bias[n+1]; v0 += b0; v1 += b1; v2 += b0; v3 += b1; }
            if (rowaux) {
                float r0 = rowaux[(size_t)(m >> 5)*N + n],     r1 = rowaux[(size_t)(m >> 5)*N + n + 1];
                float r2 = rowaux[(size_t)((m+8) >> 5)*N + n], r3 = rowaux[(size_t)((m+8) >> 5)*N + n + 1];
                v0 += r0; v1 += r1; v2 += r2; v3 += r3;
            }
            *(float2*)&C[(size_t)m*N + n]     = make_float2(v0, v1);
            *(float2*)&C[(size_t)(m+8)*N + n] = make_float2(v2, v3);
        }
    }
}

// =====================================================================
//   fp16 single-pass GEMM (NT): D = Ah @ Bh^T  — logits
// =====================================================================
#define H1STAGE (2*PLANE)
#define H1SMEM_REQ (2*H1STAGE + 1024)

__global__ void __launch_bounds__(256) mma_gemm_nt_h1(
        const __half* __restrict__ Ah, const __half* __restrict__ Bh,
        float* __restrict__ C, int M, int N, int K, int ldb,
        const float* __restrict__ bias) {
    extern __shared__ char dsm[];
    char* base = (char*)((((uintptr_t)dsm) + 1023) & ~(uintptr_t)1023);
    uint32_t sb0 = smem_u32(base);

    int m0 = blockIdx.y * 128, n0 = blockIdx.x * 128;
    int tid = threadIdx.x;
    int lane = tid & 31, wid = tid >> 5;
    int warp_m = wid & 3, warp_n = wid >> 2;

    float acc[2][8][4];
#pragma unroll
    for (int i = 0; i < 2; i++)
#pragma unroll
        for (int j = 0; j < 8; j++)
#pragma unroll
            for (int q = 0; q < 4; q++) acc[i][j][q] = 0.f;

    int KT = K / KTILE;

    auto load_stage = [&](int s, int kt) {
        uint32_t st = sb0 + s*H1STAGE;
        uint32_t ah_s = st, bh_s = st + PLANE;
        int k0 = kt * KTILE;
#pragma unroll
        for (int i = 0; i < 2; i++) {
            int idx = tid + i*256;
            int row = idx >> 2, kc = idx & 3;
            uint32_t doff = row*LDA + kc*16;
            cpa16(ah_s + doff, Ah + (size_t)(m0 + row)*K + k0 + kc*8);
            cpa16(bh_s + doff, Bh + (size_t)(n0 + row)*ldb + k0 + kc*8);
        }
        cp_commit();
    };

    load_stage(0, 0);
    for (int kt = 0; kt < KT; kt++) {
        if (kt + 1 < KT) { load_stage((kt + 1) & 1, kt + 1); cp_wait<1>(); }
        else             { cp_wait<0>(); }
        __syncthreads();
        uint32_t st = sb0 + (kt & 1)*H1STAGE;
        uint32_t ah_b = st, bh_b = st + PLANE;
#pragma unroll
        for (int ks = 0; ks < 2; ks++) {
            int kb = ks*16;
            uint32_t aH[2][4];
#pragma unroll
            for (int im = 0; im < 2; im++) {
                int row = warp_m*32 + im*16 + (lane & 15);
                ldsm4(aH[im], ah_b + row*LDA + (kb + (lane >> 4)*8)*2);
            }
#pragma unroll
            for (int nc = 0; nc < 4; nc++) {
                uint32_t bH[4];
                int row = warp_n*64 + nc*16 + (lane & 15);
                ldsm4(bH, bh_b + row*LDA + (kb + (lane >> 4)*8)*2);
#pragma unroll
                for (int im = 0; im < 2; im++) {
                    mma_fp(acc[im][nc*2],     aH[im], bH[0], bH[2]);
                    mma_fp(acc[im][nc*2 + 1], aH[im], bH[1], bH[3]);
                }
            }
        }
        __syncthreads();
    }

    int rbase = m0 + warp_m*32 + (lane >> 2);
    int cbase = n0 + warp_n*64 + (lane & 3)*2;
#pragma unroll
    for (int im = 0; im < 2; im++) {
#pragma unroll
        for (int nf = 0; nf < 8; nf++) {
            int m = rbase + im*16;
            int n = cbase + nf*8;
            float v0 = acc[im][nf][0], v1 = acc[im][nf][1];
            float v2 = acc[im][nf][2], v3 = acc[im][nf][3];
            if (bias) { float b0 = bias[n], b1 = bias[n+1]; v0 += b0; v1 += b1; v2 += b0; v3 += b1; }
            *(float2*)&C[(size_t)m*N + n]     = make_float2(v0, v1);
            *(float2*)&C[(size_t)(m+8)*N + n] = make_float2(v2, v3);
        }
    }
}

// =====================================================================
//   fp16 single-pass GEMM (NN) with fused per-row stats — pointwise conv
// =====================================================================
#define HKT 64
#define HLDA 144
#define HLDB 272
#define HPA (128*HLDA)
#define HPB (64*HLDB)
#define HSTAGE (HPA + HPB)
#define HSMEM_REQ (2*HSTAGE + 1024)

__global__ void __launch_bounds__(256) hgemm_nn(
        const __half* __restrict__ A, const __half* __restrict__ B,
        __half* __restrict__ C, double2* __restrict__ part,
        int M, int N, int K, int ldb, size_t strideB, size_t strideC) {
    extern __shared__ char dsm[];
    char* base = (char*)((((uintptr_t)dsm) + 1023) & ~(uintptr_t)1023);
    uint32_t sb0 = smem_u32(base);

    const __half* Bb = B + (size_t)blockIdx.z * strideB;
    __half* Cb = C + (size_t)blockIdx.z * strideC;
    int m0 = blockIdx.x * 128, n0 = blockIdx.y * 128;   // m fast
    int nidx = blockIdx.y;
    int tid = threadIdx.x;
    int lane = tid & 31, wid = tid >> 5;
    int warp_m = wid & 3, warp_n = wid >> 2;

    float acc[2][8][4];
#pragma unroll
    for (int i = 0; i < 2; i++)
#pragma unroll
        for (int j = 0; j < 8; j++)
#pragma unroll
            for (int q = 0; q < 4; q++) acc[i][j][q] = 0.f;

    int KT = K / HKT;   // 4

    auto load_stage = [&](int s, int kt) {
        uint32_t st = sb0 + s*HSTAGE;
        uint32_t as = st, bs = st + HPA;
        int k0 = kt * HKT;
#pragma unroll
        for (int i = 0; i < 4; i++) {
            int idx = tid + i*256;
            int row = idx >> 3, kc = idx & 7;
            cpa16(as + row*HLDA + kc*16, A + (size_t)(m0 + row)*K + k0 + kc*8);
        }
#pragma unroll
        for (int i = 0; i < 4; i++) {
            int idx = tid + i*256;
            int row = idx >> 4, c = idx & 15;
            cpa16(bs + row*HLDB + c*16, Bb + (size_t)(k0 + row)*ldb + n0 + c*8);
        }
        cp_commit();
    };

    load_stage(0, 0);
    for (int kt = 0; kt < KT; kt++) {
        if (kt + 1 < KT) { load_stage((kt + 1) & 1, kt + 1); cp_wait<1>(); }
        else             { cp_wait<0>(); }
        __syncthreads();
        uint32_t st = sb0 + (kt & 1)*HSTAGE;
        uint32_t as = st, bs = st + HPA;
#pragma unroll
        for (int ks = 0; ks < 4; ks++) {
            int kb = ks*16;
            uint32_t aF[2][4];
#pragma unroll
            for (int im = 0; im < 2; im++) {
                int row = warp_m*32 + im*16 + (lane & 15);
                uint32_t off = row*HLDA + (kb + (lane >> 4)*8)*2;
                ldsm4(aF[im], as + off);
            }
#pragma unroll
            for (int nc = 0; nc < 4; nc++) {
                uint32_t bF[4];
                int row = kb + (lane & 15);
                int col = warp_n*64 + nc*16 + (lane >> 4)*8;
                ldsm4t(bF, bs + row*HLDB + col*2);
#pragma unroll
                for (int im = 0; im < 2; im++) {
                    mma_fp(acc[im][nc*2],     aF[im], bF[0], bF[1]);
                    mma_fp(acc[im][nc*2 + 1], aF[im], bF[2], bF[3]);
                }
            }
        }
        __syncthreads();
    }

    // ---- epilogue: fp16 store + per-row (channel) sum/sumsq ----
    int rloc = warp_m*32 + (lane >> 2);
    int cbase = n0 + warp_n*64 + (lane & 3)*2;
    float s[4]  = {0.f, 0.f, 0.f, 0.f};
    float s2[4] = {0.f, 0.f, 0.f, 0.f};
#pragma unroll
    for (int im = 0; im < 2; im++) {
#pragma unroll
        for (int nf = 0; nf < 8; nf++) {
            int m = m0 + rloc + im*16;
            int n = cbase + nf*8;
            float v0 = acc[im][nf][0], v1 = acc[im][nf][1];
            float v2 = acc[im][nf][2], v3 = acc[im][nf][3];
            __half2 h01 = __floats2half2_rn(v0, v1);
            __half2 h23 = __floats2half2_rn(v2, v3);
            *(__half2*)&Cb[(size_t)m*N + n]     = h01;
            *(__half2*)&Cb[(size_t)(m+8)*N + n] = h23;
            s [im*2+0] += v0 + v1;    s2[im*2+0] += v0*v0 + v1*v1;
            s [im*2+1] += v2 + v3;    s2[im*2+1] += v2*v2 + v3*v3;
        }
    }
#pragma unroll
    for (int r = 0; r < 4; r++) {
        s [r] += __shfl_xor_sync(0xffffffffu, s [r], 1);
        s [r] += __shfl_xor_sync(0xffffffffu, s [r], 2);
        s2[r] += __shfl_xor_sync(0xffffffffu, s2[r], 1);
        s2[r] += __shfl_xor_sync(0xffffffffu, s2[r], 2);
    }
    float2* sst = (float2*)base;
    __syncthreads();
    if ((lane & 3) == 0) {
#pragma unroll
        for (int r = 0; r < 4; r++) {
            int row = rloc + (r >> 1)*16 + (r & 1)*8;
            sst[warp_n*128 + row] = make_float2(s[r], s2[r]);
        }
    }
    __syncthreads();
    if (tid < 128) {
        float2 a = sst[tid], b = sst[128 + tid];
        double2 p;
        p.x = (double)a.x + (double)b.x;
        p.y = (double)a.y + (double)b.y;
        part[(size_t)(m0 + tid)*(BSZ*98) + blockIdx.z*98 + nidx] = p;
    }
}

// finalize BN2 scale/shift from fused partials; warp per channel
__global__ void chan_finalize2(const double2* __restrict__ part,
                               const float* __restrict__ g, const float* __restrict__ bt,
                               float* __restrict__ scale, float* __restrict__ shift) {
    int warp = (blockIdx.x*256 + threadIdx.x) >> 5;
    int lane = threadIdx.x & 31;
    if (warp >= C2) return;
    double s = 0, s2 = 0;
    for (int i = lane; i < BSZ*98; i += 32) {
        double2 p = part[(size_t)warp*(BSZ*98) + i];
        s += p.x; s2 += p.y;
    }
#pragma unroll
    for (int o = 16; o; o >>= 1) {
        s  += __shfl_xor_sync(0xffffffffu, s,  o);
        s2 += __shfl_xor_sync(0xffffffffu, s2, o);
    }
    if (lane == 0) {
        double cnt = (double)BSZ * HW;
        double m = s / cnt;
        double var = s2 / cnt - m*m;
        float rs = (float)(1.0 / sqrt(var + 1e-5));
        float sc = g[warp] * rs;
        scale[warp] = sc;
        shift[warp] = bt[warp] - (float)m * sc;
    }
}

// =====================================================================
//   conv1 as fp16 implicit GEMM + fused BN1 stats
//   __launch_bounds__(256,3): cap regs (~84) -> 3 CTAs/SM occupancy
// =====================================================================
__global__ void __launch_bounds__(256, 3) conv1_igemm(
        const float* __restrict__ img, const float* __restrict__ w,
        __half* __restrict__ out, float2* __restrict__ part1) {
    __shared__ __half wt [256*40];
    __shared__ __half imt[128*40];
    __shared__ float  inr[9*224];
    __shared__ float2 sst[256];
    int oy = blockIdx.x, b = blockIdx.y;
    int tid = threadIdx.x;
    int lane = tid & 31, wid = tid >> 5;

    sst[tid] = make_float2(0.f, 0.f);
    for (int i = tid; i < 256*32; i += 256) {
        int c = i >> 5, k = i & 31;
        float v = (k < 27) ? __ldg(&w[c*27 + k]) : 0.f;
        wt[c*40 + k] = __float2half_rn(v);
    }
    const float* ip = img + (size_t)b*3*224*224;
    for (int i = tid; i < 9*224; i += 256) {
        int r = i / 224, x = i - r*224;
        int ci = r / 3, ky = r - ci*3;
        int iy = oy*2 - 1 + ky;
        inr[i] = (iy >= 0 && iy < 224) ? ip[(ci*224 + iy)*224 + x] : 0.f;
    }
    __syncthreads();
    for (int i = tid; i < 128*32; i += 256) {
        int p = i >> 5, k = i & 31;
        float v = 0.f;
        if (p < 112 && k < 27) {
            int ci = k / 9, r = k - ci*9;
            int ky = r / 3, kx = r - ky*3;
            int ix = p*2 - 1 + kx;
            if (ix >= 0 && ix < 224) v = inr[(ci*3 + ky)*224 + ix];
        }
        imt[p*40 + k] = __float2half_rn(v);
    }
    __syncthreads();

    uint32_t wt_b = smem_u32(wt), imt_b = smem_u32(imt);
    size_t obase = (size_t)b*C1*HW + (size_t)oy*112;
#pragma unroll
    for (int half = 0; half < 2; half++) {
        float acc[2][8][4];
#pragma unroll
        for (int i = 0; i < 2; i++)
#pragma unroll
            for (int j = 0; j < 8; j++)
#pragma unroll
                for (int q = 0; q < 4; q++) acc[i][j][q] = 0.f;
#pragma unroll
        for (int ks = 0; ks < 2; ks++) {
            int kb = ks*16;
            uint32_t aF[2][4];
#pragma unroll
            for (int im = 0; im < 2; im++) {
                int row = wid*32 + im*16 + (lane & 15);
                ldsm4(aF[im], wt_b + (row*40 + kb + (lane >> 4)*8)*2);
            }
#pragma unroll
            for (int nc = 0; nc < 4; nc++) {
                uint32_t bF[4];
                int row = half*64 + nc*16 + (lane & 15);
                ldsm4(bF, imt_b + (row*40 + kb + (lane >> 4)*8)*2);
#pragma unroll
                for (int im = 0; im < 2; im++) {
                    mma_fp(acc[im][nc*2],     aF[im], bF[0], bF[2]);
                    mma_fp(acc[im][nc*2 + 1], aF[im], bF[1], bF[3]);
                }
            }
        }
        // epilogue for this half: store + local stats
        float s[4]  = {0.f, 0.f, 0.f, 0.f};
        float s2[4] = {0.f, 0.f, 0.f, 0.f};
#pragma unroll
        for (int im = 0; im < 2; im++) {
#pragma unroll
            for (int nf = 0; nf < 8; nf++) {
                int m = wid*32 + im*16 + (lane >> 2);
                int n = half*64 + nf*8 + (lane & 3)*2;
                if (n < 112) {
                    float v0 = acc[im][nf][0], v1 = acc[im][nf][1];
                    float v2 = acc[im][nf][2], v3 = acc[im][nf][3];
                    __half2 h01 = __floats2half2_rn(v0, v1);
                    __half2 h23 = __floats2half2_rn(v2, v3);
                    *(__half2*)&out[obase + (size_t)m*HW + n]     = h01;
                    *(__half2*)&out[obase + (size_t)(m+8)*HW + n] = h23;
                    s [im*2+0] += v0 + v1;   s2[im*2+0] += v0*v0 + v1*v1;
                    s [im*2+1] += v2 + v3;   s2[im*2+1] += v2*v2 + v3*v3;
                }
            }
        }
#pragma unroll
        for (int r = 0; r < 4; r++) {
            s [r] += __shfl_xor_sync(0xffffffffu, s [r], 1);
            s [r] += __shfl_xor_sync(0xffffffffu, s [r], 2);
            s2[r] += __shfl_xor_sync(0xffffffffu, s2[r], 1);
            s2[r] += __shfl_xor_sync(0xffffffffu, s2[r], 2);
        }
        if ((lane & 3) == 0) {
#pragma unroll
            for (int r = 0; r < 4; r++) {
                int row = wid*32 + (r >> 1)*16 + (r & 1)*8 + (lane >> 2);
                float2 p = sst[row];
                p.x += s[r]; p.y += s2[r];
                sst[row] = p;
            }
        }
    }
    __syncthreads();
    {
        float2 p = sst[tid];
        part1[(size_t)tid*(BSZ*112) + b*112 + oy] = p;
    }
}

// finalize BN1 from fused float2 partials (1792 per channel); warp per channel
__global__ void chan_finalize1(const float2* __restrict__ part,
                               const float* __restrict__ g, const float* __restrict__ bt,
                               float* __restrict__ scale, float* __restrict__ shift) {
    int warp = (blockIdx.x*256 + threadIdx.x) >> 5;
    int lane = threadIdx.x & 31;
    if (warp >= C1) return;
    double s = 0, s2 = 0;
    for (int i = lane; i < BSZ*112; i += 32) {
        float2 p = part[(size_t)warp*(BSZ*112) + i];
        s += (double)p.x; s2 += (double)p.y;
    }
#pragma unroll
    for (int o = 16; o; o >>= 1) {
        s  += __shfl_xor_sync(0xffffffffu, s,  o);
        s2 += __shfl_xor_sync(0xffffffffu, s2, o);
    }
    if (lane == 0) {
        double cnt = (double)BSZ * HW;
        double m = s / cnt;
        double var = s2 / cnt - m*m;
        float rs = (float)(1.0 / sqrt(var + 1e-5));
        float sc = g[warp] * rs;
        scale[warp] = sc;
        shift[warp] = bt[warp] - (float)m * sc;
    }
}

// ---------------- depthwise 3x3 s1 p1 (BN1+ReLU fused), fp16 in/out -------------
__global__ void dw_kernel(const __half* __restrict__ in, const float* __restrict__ w,
                          const float* __restrict__ scale, const float* __restrict__ shift,
                          __half* __restrict__ outh) {
    int warp = threadIdx.x >> 5, lane = threadIdx.x & 31;
    int y = blockIdx.x*8 + warp;
    int c = blockIdx.y, b = blockIdx.z;
    float sc = scale[c], sh = shift[c];
    const __half* ip = in + ((size_t)b*C1 + c)*HW;
    int x0 = lane*4;
    bool inx = (x0 < 112);

    float v[3][4];
    float lft[3], rgt[3];
#pragma unroll
    for (int r = 0; r < 3; r++) {
        int yy = y - 1 + r;
        float t0 = 0.f, t1 = 0.f, t2 = 0.f, t3 = 0.f;
        if (inx && yy >= 0 && yy < 112) {
            uint2 u = *(const uint2*)&ip[yy*112 + x0];
            float2 p0 = __half22float2(*(__half2*)&u.x);
            float2 p1 = __half22float2(*(__half2*)&u.y);
            t0 = p0.x; t1 = p0.y; t2 = p1.x; t3 = p1.y;
        }
        v[r][0] = fmaxf(t0*sc + sh, 0.f);
        v[r][1] = fmaxf(t1*sc + sh, 0.f);
        v[r][2] = fmaxf(t2*sc + sh, 0.f);
        v[r][3] = fmaxf(t3*sc + sh, 0.f);
        if (!inx || yy < 0 || yy >= 112) { v[r][0]=v[r][1]=v[r][2]=v[r][3]=0.f; }
        lft[r] = __shfl_up_sync(0xffffffffu, v[r][3], 1);
        if (lane == 0) lft[r] = 0.f;
        rgt[r] = __shfl_down_sync(0xffffffffu, v[r][0], 1);
        if (lane >= 27) rgt[r] = 0.f;
    }
    float wv[9];
#pragma unroll
    for (int k = 0; k < 9; k++) wv[k] = __ldg(&w[c*9 + k]);

    float o0 = 0.f, o1 = 0.f, o2 = 0.f, o3 = 0.f;
#pragma unroll
    for (int r = 0; r < 3; r++) {
        float e0 = lft[r], e1 = v[r][0], e2 = v[r][1], e3 = v[r][2], e4 = v[r][3], e5 = rgt[r];
        float w0 = wv[r*3+0], w1 = wv[r*3+1], w2 = wv[r*3+2];
        o0 += w0*e0 + w1*e1 + w2*e2;
        o1 += w0*e1 + w1*e2 + w2*e3;
        o2 += w0*e2 + w1*e3 + w2*e4;
        o3 += w0*e3 + w1*e4 + w2*e5;
    }
    if (inx) {
        __half2 h01 = __floats2half2_rn(o0, o1);
        __half2 h23 = __floats2half2_rn(o2, o3);
        size_t off = ((size_t)b*C1 + c)*HW + y*112 + x0;
        *(uint2*)&outh[off] = make_uint2(*(uint32_t*)&h01, *(uint32_t*)&h23);
    }
}

// ---------------- pooled[b][c] = mean_p relu(bn2(pw)), fp16 source ----------------
__global__ void pooled_kernel(const __half* __restrict__ x, const float* __restrict__ scale,
                              const float* __restrict__ shift, float* __restrict__ pooled) {
    int c = blockIdx.x, b = blockIdx.y;
    const __half2* p = (const __half2*)(x + ((size_t)b*C2 + c)*HW);
    float sc = scale[c], sh = shift[c];
    double s = 0;
    for (int i = threadIdx.x; i < HW/2; i += 256) {
        float2 v = __half22float2(p[i]);
        float a = v.x*sc + sh, bq = v.y*sc + sh;
        if (a > 0.f) s += a;
        if (bq > 0.f) s += bq;
    }
    __shared__ double shm[256];
    shm[threadIdx.x] = s; __syncthreads();
    for (int o = 128; o; o >>= 1) {
        if (threadIdx.x < o) shm[threadIdx.x] += shm[threadIdx.x+o];
        __syncthreads();
    }
    if (threadIdx.x == 0) pooled[b*C2 + c] = (float)(shm[0] / (double)HW);
}

// ---------------- small GEMM ----------------
__global__ void small_gemm(const float* __restrict__ in, int K,
                           const float* __restrict__ W, int ldw, int woff,
                           const float* __restrict__ bias, const float* __restrict__ aux,
                           int O, int act, float* __restrict__ out) {
    __shared__ float sin_s[BSZ*512];
    for (int i = threadIdx.x; i < BSZ*K; i += 256) sin_s[i] = in[i];
    __syncthreads();
    int warp = threadIdx.x >> 5, lane = threadIdx.x & 31;
    int o = blockIdx.x*8 + warp;
    float part[BSZ];
#pragma unroll
    for (int b = 0; b < BSZ; b++) part[b] = 0.f;
    for (int k = lane; k < K; k += 32) {
        float wv = W[(size_t)o*ldw + woff + k];
#pragma unroll
        for (int b = 0; b < BSZ; b++) part[b] += wv * sin_s[b*K + k];
    }
#pragma unroll
    for (int b = 0; b < BSZ; b++) {
        float v = part[b];
#pragma unroll
        for (int off = 16; off; off >>= 1) v += __shfl_xor_sync(0xffffffffu, v, off);
        if (lane == b) {
            if (bias) v += bias[o];
            if (act == 1) v = v > 0.f ? v : 0.f;
            else if (act == 2) v = (1.f/(1.f + expf(-v))) * aux[b*O + o];
            out[b*O + o] = v;
        }
    }
}

// ---------------- gather caption embeddings: bf16 split planes ----------------
__global__ void gather_embs(const int* __restrict__ cap, const float* __restrict__ embed,
                            __nv_bfloat16* __restrict__ eh, __nv_bfloat16* __restrict__ el) {
    int row = blockIdx.x;
    int b = row >> 5, t = row & 31;
    int tok = cap[b*33 + t];
    const float* src = embed + (size_t)tok*HID;
    int i = threadIdx.x*2;
    float2 v = *(const float2*)&src[i];
    float h0,l0,h1,l1;
    split2(v.x,h0,l0); split2(v.y,h1,l1);
    *(uint32_t*)&eh[(size_t)row*HID + i] = pack_bf2(h0,h1);
    *(uint32_t*)&el[(size_t)row*HID + i] = pack_bf2(l0,l1);
}

// ---------------- persistent GRU (hall fp16 for logits) ----------------
__global__ void gru_reset() {
    if (threadIdx.x < TT) g_gbar[threadIdx.x] = 0;
}
#define GRU_BLKS 64
__global__ void __launch_bounds__(256) gru_persist(
        const float* __restrict__ gi, const float* __restrict__ whh,
        const float* __restrict__ bhh, float* __restrict__ hall,
        __half* __restrict__ hallh) {
    __shared__ float hs[BSZ*HID];
    int tid = threadIdx.x;
    int warp = tid >> 5, lane = tid & 31;
    int j = blockIdx.x*8 + warp;
    float w0[16], w1[16], w2[16];
#pragma unroll
    for (int i = 0; i < 16; i++) {
        int k = lane + 32*i;
        w0[i] = whh[(size_t)j*HID + k];
        w1[i] = whh[(size_t)(j + 512)*HID + k];
        w2[i] = whh[(size_t)(j + 1024)*HID + k];
    }
    float bhr = bhh[j], bhz = bhh[j + 512], bhn = bhh[j + 1024];

    for (int t = 0; t < TT; t++) {
        for (int i = tid; i < BSZ*HID; i += 256) {
            int b = i >> 9, jj = i & 511;
            hs[i] = (t == 0) ? 0.f : hall[((size_t)(b*TT + t - 1))*HID + jj];
        }
        __syncthreads();
        for (int b = 0; b < BSZ; b++) {
            float pr = 0.f, pz = 0.f, pn = 0.f;
#pragma unroll
            for (int i = 0; i < 16; i++) {
                float hv = hs[b*HID + lane + 32*i];
                pr += hv*w0[i]; pz += hv*w1[i]; pn += hv*w2[i];
            }
#pragma unroll
            for (int o = 16; o; o >>= 1) {
                pr += __shfl_xor_sync(0xffffffffu, pr, o);
                pz += __shfl_xor_sync(0xffffffffu, pz, o);
                pn += __shfl_xor_sync(0xffffffffu, pn, o);
            }
            if (lane == 0) {
                size_t gib = ((size_t)(b*TT + t))*1536;
                float ir = gi[gib + j], iz = gi[gib + 512 + j], inn = gi[gib + 1024 + j];
                float r = 1.f/(1.f + expf(-(ir + pr + bhr)));
                float z = 1.f/(1.f + expf(-(iz + pz + bhz)));
                float n = tanhf(inn + r*(pn + bhn));
                float hp = hs[b*HID + j];
                float hn2 = (1.f - z)*n + z*hp;
                size_t oidx = ((size_t)(b*TT + t))*HID + j;
                hall[oidx] = hn2;
                hallh[oidx] = __float2half_rn(hn2);
            }
        }
        __threadfence();
        __syncthreads();
        if (tid == 0) {
            atomicAdd(&g_gbar[t], 1);
            while (atomicAdd(&g_gbar[t], 0) < GRU_BLKS) __nanosleep(64);
        }
        __syncthreads();
    }
}

// =======================================================================
extern "C" void kernel_launch(void* const* d_in, const int* in_sizes, int n_in,
                              void* d_out, int out_size) {
    const float* images   = (const float*)d_in[0];
    const int*   captions = (const int*)  d_in[1];
    const float* conv1_w  = (const float*)d_in[2];
    const float* bn1_g    = (const float*)d_in[3];
    const float* bn1_b    = (const float*)d_in[4];
    const float* dw_w     = (const float*)d_in[5];
    const float* pw_w     = (const float*)d_in[6];
    const float* bn2_g    = (const float*)d_in[7];
    const float* bn2_b    = (const float*)d_in[8];
    const float* se_fc1_w = (const float*)d_in[9];
    const float* se_fc2_w = (const float*)d_in[10];
    const float* enc_fc_w = (const float*)d_in[11];
    const float* enc_fc_b = (const float*)d_in[12];
    const float* embed    = (const float*)d_in[13];
    // d_in[14] = q_w (unused), d_in[15] = k_w (unused)
    const float* v_w      = (const float*)d_in[16];
    const float* gru_w_ih = (const float*)d_in[17];
    const float* gru_w_hh = (const float*)d_in[18];
    const float* gru_b_ih = (const float*)d_in[19];
    const float* gru_b_hh = (const float*)d_in[20];
    const float* fc_w     = (const float*)d_in[21];
    const float* fc_b     = (const float*)d_in[22];

    __half *conv1buf;
    float2 *part1;
    double2 *part2;
    float *scale1, *shift1, *scale2, *shift2;
    float *pooled, *t1, *fbuf, *feats, *ctx, *gctx, *gi, *hall;
    __half *dwh, *pwwh, *pwout, *fcwh, *hallh;
    __nv_bfloat16 *wihh, *wihl, *embsh, *embsl;
    cudaGetSymbolAddress((void**)&conv1buf, g_conv1);
    cudaGetSymbolAddress((void**)&part1,    g_part1);
    cudaGetSymbolAddress((void**)&part2,    g_part2);
    cudaGetSymbolAddress((void**)&scale1,   g_scale1);
    cudaGetSymbolAddress((void**)&shift1,   g_shift1);
    cudaGetSymbolAddress((void**)&scale2,   g_scale2);
    cudaGetSymbolAddress((void**)&shift2,   g_shift2);
    cudaGetSymbolAddress((void**)&pooled,   g_pooled);
    cudaGetSymbolAddress((void**)&t1,       g_t1);
    cudaGetSymbolAddress((void**)&fbuf,     g_f);
    cudaGetSymbolAddress((void**)&feats,    g_feats);
    cudaGetSymbolAddress((void**)&ctx,      g_ctx);
    cudaGetSymbolAddress((void**)&gctx,     g_gctx);
    cudaGetSymbolAddress((void**)&gi,       g_gi);
    cudaGetSymbolAddress((void**)&hall,     g_hall);
    cudaGetSymbolAddress((void**)&dwh,      g_dwh);
    cudaGetSymbolAddress((void**)&pwwh,     g_pwwh);
    cudaGetSymbolAddress((void**)&pwout,    g_pwout);
    cudaGetSymbolAddress((void**)&fcwh,     g_fcwh);
    cudaGetSymbolAddress((void**)&wihh,     g_wihh);
    cudaGetSymbolAddress((void**)&wihl,     g_wihl);
    cudaGetSymbolAddress((void**)&embsh,    g_embsh);
    cudaGetSymbolAddress((void**)&embsl,    g_embsl);
    cudaGetSymbolAddress((void**)&hallh,    g_hallh);

    cudaFuncSetAttribute(mma_gemm_nt,    cudaFuncAttributeMaxDynamicSharedMemorySize, SMEM_REQ);
    cudaFuncSetAttribute(mma_gemm_nt_h1, cudaFuncAttributeMaxDynamicSharedMemorySize, H1SMEM_REQ);
    cudaFuncSetAttribute(hgemm_nn,       cudaFuncAttributeMaxDynamicSharedMemorySize, HSMEM_REQ);

    // weight conversions (independent of encoder)
    to_half<<<(C2*C1)/1024, 256>>>(pw_w, pwwh, (size_t)C2*C1);
    to_half<<<((size_t)VOC*HID)/1024, 256>>>(fc_w, fcwh, (size_t)VOC*HID);
    split_strided<<<(1536*512)/1024, 256>>>(gru_w_ih, 1024, wihh, wihl);

    // encoder
    conv1_igemm<<<dim3(112, BSZ), 256>>>(images, conv1_w, conv1buf, part1);
    chan_finalize1<<<32, 256>>>(part1, bn1_g, bn1_b, scale1, shift1);
    dw_kernel<<<dim3(14, C1, BSZ), 256>>>(conv1buf, dw_w, scale1, shift1, dwh);
    // pointwise conv (fp16 single-pass GEMM, fused BN2 stats)
    hgemm_nn<<<dim3(4, 98, BSZ), 256, HSMEM_REQ>>>(pwwh, dwh, pwout, part2,
                                                   C2, HW, C1, HW,
                                                   (size_t)C1*HW, (size_t)C2*HW);
    chan_finalize2<<<64, 256>>>(part2, bn2_g, bn2_b, scale2, shift2);
    pooled_kernel<<<dim3(C2, BSZ), 256>>>(pwout, scale2, shift2, pooled);

    // SE + encoder FC + ctx (tiny GEMMs)
    small_gemm<<<16, 256>>>(pooled, 512, se_fc1_w, 512, 0, nullptr, nullptr, 128, 1, t1);
    small_gemm<<<64, 256>>>(t1, 128, se_fc2_w, 128, 0, nullptr, pooled, 512, 2, fbuf);
    small_gemm<<<64, 256>>>(fbuf, 512, enc_fc_w, 512, 0, enc_fc_b, nullptr, 512, 0, feats);
    small_gemm<<<64, 256>>>(feats, 512, v_w, 512, 0, nullptr, nullptr, 512, 0, ctx);

    // decoder: precompute input gates (bf16 3-pass — precision-critical via GRU)
    small_gemm<<<192, 256>>>(ctx, 512, gru_w_ih, 1024, 512, gru_b_ih, nullptr, 1536, 0, gctx);
    gather_embs<<<512, 256>>>(captions, embed, embsh, embsl);
    mma_gemm_nt<<<dim3(12, 4, 1), 256, SMEM_REQ>>>(embsh, embsl, wihh, wihl, gi,
                                                   512, 1536, 512, 512, nullptr, gctx);

    // persistent GRU recurrence
    gru_reset<<<1, 32>>>();
    gru_persist<<<GRU_BLKS, 256>>>(gi, gru_w_hh, gru_b_hh, hall, hallh);

    // logits: fp16 single-pass
    mma_gemm_nt_h1<<<dim3(250, 4, 1), 256, H1SMEM_REQ>>>(hallh, fcwh, (float*)d_out,
                                                         512, VOC, 512, 512, fc_b);
}

// round 17
// speedup vs baseline: 1.3500x; 1.0009x over previous
#include <cuda_runtime.h>
#include <cuda_bf16.h>
#include <cuda_fp16.h>
#include <math.h>
#include <stdint.h>

#define BSZ 16
#define HW 12544
#define C1 256
#define C2 512
#define TT 32
#define HID 512
#define VOC 32000

// ---------------- scratch (static device arrays; no allocation) ----------------
__device__ __half  g_conv1[(size_t)BSZ*C1*HW];
__device__ float2  g_part1[(size_t)C1*BSZ*112];
__device__ double2 g_part2[(size_t)C2*BSZ*98];
__device__ float   g_scale1[C1], g_shift1[C1];
__device__ float   g_scale2[C2], g_shift2[C2];
__device__ float   g_pooled[BSZ*C2], g_t1[BSZ*128], g_f[BSZ*C2], g_feats[BSZ*C2], g_ctx[BSZ*C2];
__device__ float   g_gctx[BSZ*1536];
__device__ float   g_gi  [(size_t)BSZ*TT*1536];
__device__ float   g_hall[(size_t)BSZ*TT*HID];
__device__ int     g_gbar[TT];

// fp16 planes
__device__ __half g_dwh[(size_t)BSZ*C1*HW];
__device__ __half g_pwwh[C2*C1];
__device__ __half g_pwout[(size_t)BSZ*C2*HW];
__device__ __half g_fcwh[(size_t)VOC*HID];   // fc_w fp16
__device__ __half g_hallh[512*HID];          // hall fp16 (single plane)
// bf16 hi/lo planes for the gi GEMM (3-pass, precision-critical path kept)
__device__ __nv_bfloat16 g_wihh[1536*HID],  g_wihl[1536*HID];
__device__ __nv_bfloat16 g_embsh[512*HID],  g_embsl[512*HID];

// =====================================================================
//                    helpers
// =====================================================================
__device__ __forceinline__ uint32_t smem_u32(const void* p) {
    uint32_t a;
    asm("{ .reg .u64 t; cvta.to.shared.u64 t, %1; cvt.u32.u64 %0, t; }" : "=r"(a) : "l"(p));
    return a;
}
__device__ __forceinline__ void ldsm4(uint32_t* r, uint32_t addr) {
    asm volatile("ldmatrix.sync.aligned.m8n8.x4.shared.b16 {%0,%1,%2,%3}, [%4];"
                 : "=r"(r[0]), "=r"(r[1]), "=r"(r[2]), "=r"(r[3]) : "r"(addr));
}
__device__ __forceinline__ void ldsm4t(uint32_t* r, uint32_t addr) {
    asm volatile("ldmatrix.sync.aligned.m8n8.x4.trans.shared.b16 {%0,%1,%2,%3}, [%4];"
                 : "=r"(r[0]), "=r"(r[1]), "=r"(r[2]), "=r"(r[3]) : "r"(addr));
}
__device__ __forceinline__ void mma_bf(float* d, const uint32_t* a, uint32_t b0, uint32_t b1) {
    asm volatile(
        "mma.sync.aligned.m16n8k16.row.col.f32.bf16.bf16.f32 "
        "{%0,%1,%2,%3}, {%4,%5,%6,%7}, {%8,%9}, {%0,%1,%2,%3};"
        : "+f"(d[0]), "+f"(d[1]), "+f"(d[2]), "+f"(d[3])
        : "r"(a[0]), "r"(a[1]), "r"(a[2]), "r"(a[3]), "r"(b0), "r"(b1));
}
__device__ __forceinline__ void mma_fp(float* d, const uint32_t* a, uint32_t b0, uint32_t b1) {
    asm volatile(
        "mma.sync.aligned.m16n8k16.row.col.f32.f16.f16.f32 "
        "{%0,%1,%2,%3}, {%4,%5,%6,%7}, {%8,%9}, {%0,%1,%2,%3};"
        : "+f"(d[0]), "+f"(d[1]), "+f"(d[2]), "+f"(d[3])
        : "r"(a[0]), "r"(a[1]), "r"(a[2]), "r"(a[3]), "r"(b0), "r"(b1));
}
__device__ __forceinline__ uint32_t pack_bf2(float lo, float hi) {
    uint32_t r;
    asm("cvt.rn.bf16x2.f32 %0, %1, %2;" : "=r"(r) : "f"(hi), "f"(lo));
    return r;
}
__device__ __forceinline__ void split2(float x, float& h, float& l) {
    h = __bfloat162float(__float2bfloat16(x));
    l = x - h;
}
__device__ __forceinline__ void cpa16(uint32_t dst, const void* src) {
    asm volatile("cp.async.cg.shared.global [%0], [%1], 16;" :: "r"(dst), "l"(src));
}
__device__ __forceinline__ void cp_commit() { asm volatile("cp.async.commit_group;"); }
template<int NW> __device__ __forceinline__ void cp_wait() {
    asm volatile("cp.async.wait_group %0;" :: "n"(NW));
}

// =====================================================================
//   conversion kernels
// =====================================================================
__global__ void split_strided(const float* __restrict__ src, int ld,
                              __nv_bfloat16* __restrict__ dh, __nv_bfloat16* __restrict__ dl) {
    size_t i = ((size_t)blockIdx.x*256 + threadIdx.x)*4;
    int row = (int)(i >> 9), col = (int)(i & 511);
    float4 v = *(const float4*)&src[(size_t)row*ld + col];
    float hx, lx, hy, ly, hz, lz, hw, lw;
    split2(v.x, hx, lx); split2(v.y, hy, ly); split2(v.z, hz, lz); split2(v.w, hw, lw);
    *(uint2*)&dh[i] = make_uint2(pack_bf2(hx, hy), pack_bf2(hz, hw));
    *(uint2*)&dl[i] = make_uint2(pack_bf2(lx, ly), pack_bf2(lz, lw));
}
__global__ void to_half(const float* __restrict__ src, __half* __restrict__ dst, size_t n) {
    size_t i = ((size_t)blockIdx.x*256 + threadIdx.x)*4;
    if (i >= n) return;
    float4 v = *(const float4*)&src[i];
    __half2 a = __floats2half2_rn(v.x, v.y), b = __floats2half2_rn(v.z, v.w);
    *(uint2*)&dst[i] = make_uint2(*(uint32_t*)&a, *(uint32_t*)&b);
}

// =====================================================================
//   bf16 3-pass GEMM (NT) — gi only
// =====================================================================
#define KTILE 32
#define LDA   80
#define PLANE 10240
#define STAGE (4*PLANE)
#define SMEM_REQ (2*STAGE + 1024)

__global__ void __launch_bounds__(256) mma_gemm_nt(
        const __nv_bfloat16* __restrict__ Ah, const __nv_bfloat16* __restrict__ Al,
        const __nv_bfloat16* __restrict__ Bh, const __nv_bfloat16* __restrict__ Bl,
        float* __restrict__ C, int M, int N, int K, int ldb,
        const float* __restrict__ bias, const float* __restrict__ rowaux) {
    extern __shared__ char dsm[];
    char* base = (char*)((((uintptr_t)dsm) + 1023) & ~(uintptr_t)1023);
    uint32_t sb0 = smem_u32(base);

    int m0 = blockIdx.y * 128, n0 = blockIdx.x * 128;
    int tid = threadIdx.x;
    int lane = tid & 31, wid = tid >> 5;
    int warp_m = wid & 3, warp_n = wid >> 2;

    float acc[2][8][4];
#pragma unroll
    for (int i = 0; i < 2; i++)
#pragma unroll
        for (int j = 0; j < 8; j++)
#pragma unroll
            for (int q = 0; q < 4; q++) acc[i][j][q] = 0.f;

    int KT = K / KTILE;

    auto load_stage = [&](int s, int kt) {
        uint32_t st = sb0 + s*STAGE;
        uint32_t ah_s = st, al_s = st + PLANE, bh_s = st + 2*PLANE, bl_s = st + 3*PLANE;
        int k0 = kt * KTILE;
#pragma unroll
        for (int i = 0; i < 2; i++) {
            int idx = tid + i*256;
            int row = idx >> 2, kc = idx & 3;
            uint32_t doff = row*LDA + kc*16;
            cpa16(ah_s + doff, Ah + (size_t)(m0 + row)*K + k0 + kc*8);
            cpa16(al_s + doff, Al + (size_t)(m0 + row)*K + k0 + kc*8);
            cpa16(bh_s + doff, Bh + (size_t)(n0 + row)*ldb + k0 + kc*8);
            cpa16(bl_s + doff, Bl + (size_t)(n0 + row)*ldb + k0 + kc*8);
        }
        cp_commit();
    };

    load_stage(0, 0);
    for (int kt = 0; kt < KT; kt++) {
        if (kt + 1 < KT) { load_stage((kt + 1) & 1, kt + 1); cp_wait<1>(); }
        else             { cp_wait<0>(); }
        __syncthreads();
        uint32_t st = sb0 + (kt & 1)*STAGE;
        uint32_t ah_b = st, al_b = st + PLANE, bh_b = st + 2*PLANE, bl_b = st + 3*PLANE;
#pragma unroll
        for (int ks = 0; ks < 2; ks++) {
            int kb = ks*16;
            uint32_t aH[2][4], aL[2][4];
#pragma unroll
            for (int im = 0; im < 2; im++) {
                int row = warp_m*32 + im*16 + (lane & 15);
                uint32_t off = row*LDA + (kb + (lane >> 4)*8)*2;
                ldsm4(aH[im], ah_b + off);
                ldsm4(aL[im], al_b + off);
            }
#pragma unroll
            for (int nc = 0; nc < 4; nc++) {
                uint32_t bH[4], bL[4];
                int row = warp_n*64 + nc*16 + (lane & 15);
                uint32_t off = row*LDA + (kb + (lane >> 4)*8)*2;
                ldsm4(bH, bh_b + off);
                ldsm4(bL, bl_b + off);
#pragma unroll
                for (int im = 0; im < 2; im++) {
                    float* a0 = acc[im][nc*2];
                    float* a1 = acc[im][nc*2 + 1];
                    mma_bf(a0, aH[im], bH[0], bH[2]);
                    mma_bf(a0, aH[im], bL[0], bL[2]);
                    mma_bf(a0, aL[im], bH[0], bH[2]);
                    mma_bf(a1, aH[im], bH[1], bH[3]);
                    mma_bf(a1, aH[im], bL[1], bL[3]);
                    mma_bf(a1, aL[im], bH[1], bH[3]);
                }
            }
        }
        __syncthreads();
    }

    int rbase = m0 + warp_m*32 + (lane >> 2);
    int cbase = n0 + warp_n*64 + (lane & 3)*2;
#pragma unroll
    for (int im = 0; im < 2; im++) {
#pragma unroll
        for (int nf = 0; nf < 8; nf++) {
            int m = rbase + im*16;
            int n = cbase + nf*8;
            float v0 = acc[im][nf][0], v1 = acc[im][nf][1];
            float v2 = acc[im][nf][2], v3 = acc[im][nf][3];
            if (bias)   { float b0 = bias[n], b1 = bias[n+1]; v0 += b0; v1 += b1; v2 += b0; v3 += b1; }
            if (rowaux) {
                float r0 = rowaux[(size_t)(m >> 5)*N + n],     r1 = rowaux[(size_t)(m >> 5)*N + n + 1];
                float r2 = rowaux[(size_t)((m+8) >> 5)*N + n], r3 = rowaux[(size_t)((m+8) >> 5)*N + n + 1];
                v0 += r0; v1 += r1; v2 += r2; v3 += r3;
            }
            *(float2*)&C[(size_t)m*N + n]     = make_float2(v0, v1);
            *(float2*)&C[(size_t)(m+8)*N + n] = make_float2(v2, v3);
        }
    }
}

// =====================================================================
//   fp16 single-pass GEMM (NT): D = Ah @ Bh^T  — logits
// =====================================================================
#define H1STAGE (2*PLANE)
#define H1SMEM_REQ (2*H1STAGE + 1024)

__global__ void __launch_bounds__(256) mma_gemm_nt_h1(
        const __half* __restrict__ Ah, const __half* __restrict__ Bh,
        float* __restrict__ C, int M, int N, int K, int ldb,
        const float* __restrict__ bias) {
    extern __shared__ char dsm[];
    char* base = (char*)((((uintptr_t)dsm) + 1023) & ~(uintptr_t)1023);
    uint32_t sb0 = smem_u32(base);

    int m0 = blockIdx.y * 128, n0 = blockIdx.x * 128;
    int tid = threadIdx.x;
    int lane = tid & 31, wid = tid >> 5;
    int warp_m = wid & 3, warp_n = wid >> 2;

    float acc[2][8][4];
#pragma unroll
    for (int i = 0; i < 2; i++)
#pragma unroll
        for (int j = 0; j < 8; j++)
#pragma unroll
            for (int q = 0; q < 4; q++) acc[i][j][q] = 0.f;

    int KT = K / KTILE;

    auto load_stage = [&](int s, int kt) {
        uint32_t st = sb0 + s*H1STAGE;
        uint32_t ah_s = st, bh_s = st + PLANE;
        int k0 = kt * KTILE;
#pragma unroll
        for (int i = 0; i < 2; i++) {
            int idx = tid + i*256;
            int row = idx >> 2, kc = idx & 3;
            uint32_t doff = row*LDA + kc*16;
            cpa16(ah_s + doff, Ah + (size_t)(m0 + row)*K + k0 + kc*8);
            cpa16(bh_s + doff, Bh + (size_t)(n0 + row)*ldb + k0 + kc*8);
        }
        cp_commit();
    };

    load_stage(0, 0);
    for (int kt = 0; kt < KT; kt++) {
        if (kt + 1 < KT) { load_stage((kt + 1) & 1, kt + 1); cp_wait<1>(); }
        else             { cp_wait<0>(); }
        __syncthreads();
        uint32_t st = sb0 + (kt & 1)*H1STAGE;
        uint32_t ah_b = st, bh_b = st + PLANE;
#pragma unroll
        for (int ks = 0; ks < 2; ks++) {
            int kb = ks*16;
            uint32_t aH[2][4];
#pragma unroll
            for (int im = 0; im < 2; im++) {
                int row = warp_m*32 + im*16 + (lane & 15);
                ldsm4(aH[im], ah_b + row*LDA + (kb + (lane >> 4)*8)*2);
            }
#pragma unroll
            for (int nc = 0; nc < 4; nc++) {
                uint32_t bH[4];
                int row = warp_n*64 + nc*16 + (lane & 15);
                ldsm4(bH, bh_b + row*LDA + (kb + (lane >> 4)*8)*2);
#pragma unroll
                for (int im = 0; im < 2; im++) {
                    mma_fp(acc[im][nc*2],     aH[im], bH[0], bH[2]);
                    mma_fp(acc[im][nc*2 + 1], aH[im], bH[1], bH[3]);
                }
            }
        }
        __syncthreads();
    }

    int rbase = m0 + warp_m*32 + (lane >> 2);
    int cbase = n0 + warp_n*64 + (lane & 3)*2;
#pragma unroll
    for (int im = 0; im < 2; im++) {
#pragma unroll
        for (int nf = 0; nf < 8; nf++) {
            int m = rbase + im*16;
            int n = cbase + nf*8;
            float v0 = acc[im][nf][0], v1 = acc[im][nf][1];
            float v2 = acc[im][nf][2], v3 = acc[im][nf][3];
            if (bias) { float b0 = bias[n], b1 = bias[n+1]; v0 += b0; v1 += b1; v2 += b0; v3 += b1; }
            *(float2*)&C[(size_t)m*N + n]     = make_float2(v0, v1);
            *(float2*)&C[(size_t)(m+8)*N + n] = make_float2(v2, v3);
        }
    }
}

// =====================================================================
//   fp16 single-pass GEMM (NN) with fused per-row stats — pointwise conv
// =====================================================================
#define HKT 64
#define HLDA 144
#define HLDB 272
#define HPA (128*HLDA)
#define HPB (64*HLDB)
#define HSTAGE (HPA + HPB)
#define HSMEM_REQ (2*HSTAGE + 1024)

__global__ void __launch_bounds__(256) hgemm_nn(
        const __half* __restrict__ A, const __half* __restrict__ B,
        __half* __restrict__ C, double2* __restrict__ part,
        int M, int N, int K, int ldb, size_t strideB, size_t strideC) {
    extern __shared__ char dsm[];
    char* base = (char*)((((uintptr_t)dsm) + 1023) & ~(uintptr_t)1023);
    uint32_t sb0 = smem_u32(base);

    const __half* Bb = B + (size_t)blockIdx.z * strideB;
    __half* Cb = C + (size_t)blockIdx.z * strideC;
    int m0 = blockIdx.x * 128, n0 = blockIdx.y * 128;   // m fast
    int nidx = blockIdx.y;
    int tid = threadIdx.x;
    int lane = tid & 31, wid = tid >> 5;
    int warp_m = wid & 3, warp_n = wid >> 2;

    float acc[2][8][4];
#pragma unroll
    for (int i = 0; i < 2; i++)
#pragma unroll
        for (int j = 0; j < 8; j++)
#pragma unroll
            for (int q = 0; q < 4; q++) acc[i][j][q] = 0.f;

    int KT = K / HKT;   // 4

    auto load_stage = [&](int s, int kt) {
        uint32_t st = sb0 + s*HSTAGE;
        uint32_t as = st, bs = st + HPA;
        int k0 = kt * HKT;
#pragma unroll
        for (int i = 0; i < 4; i++) {
            int idx = tid + i*256;
            int row = idx >> 3, kc = idx & 7;
            cpa16(as + row*HLDA + kc*16, A + (size_t)(m0 + row)*K + k0 + kc*8);
        }
#pragma unroll
        for (int i = 0; i < 4; i++) {
            int idx = tid + i*256;
            int row = idx >> 4, c = idx & 15;
            cpa16(bs + row*HLDB + c*16, Bb + (size_t)(k0 + row)*ldb + n0 + c*8);
        }
        cp_commit();
    };

    load_stage(0, 0);
    for (int kt = 0; kt < KT; kt++) {
        if (kt + 1 < KT) { load_stage((kt + 1) & 1, kt + 1); cp_wait<1>(); }
        else             { cp_wait<0>(); }
        __syncthreads();
        uint32_t st = sb0 + (kt & 1)*HSTAGE;
        uint32_t as = st, bs = st + HPA;
#pragma unroll
        for (int ks = 0; ks < 4; ks++) {
            int kb = ks*16;
            uint32_t aF[2][4];
#pragma unroll
            for (int im = 0; im < 2; im++) {
                int row = warp_m*32 + im*16 + (lane & 15);
                uint32_t off = row*HLDA + (kb + (lane >> 4)*8)*2;
                ldsm4(aF[im], as + off);
            }
#pragma unroll
            for (int nc = 0; nc < 4; nc++) {
                uint32_t bF[4];
                int row = kb + (lane & 15);
                int col = warp_n*64 + nc*16 + (lane >> 4)*8;
                ldsm4t(bF, bs + row*HLDB + col*2);
#pragma unroll
                for (int im = 0; im < 2; im++) {
                    mma_fp(acc[im][nc*2],     aF[im], bF[0], bF[1]);
                    mma_fp(acc[im][nc*2 + 1], aF[im], bF[2], bF[3]);
                }
            }
        }
        __syncthreads();
    }

    // ---- epilogue: fp16 store + per-row (channel) sum/sumsq ----
    int rloc = warp_m*32 + (lane >> 2);
    int cbase = n0 + warp_n*64 + (lane & 3)*2;
    float s[4]  = {0.f, 0.f, 0.f, 0.f};
    float s2[4] = {0.f, 0.f, 0.f, 0.f};
#pragma unroll
    for (int im = 0; im < 2; im++) {
#pragma unroll
        for (int nf = 0; nf < 8; nf++) {
            int m = m0 + rloc + im*16;
            int n = cbase + nf*8;
            float v0 = acc[im][nf][0], v1 = acc[im][nf][1];
            float v2 = acc[im][nf][2], v3 = acc[im][nf][3];
            __half2 h01 = __floats2half2_rn(v0, v1);
            __half2 h23 = __floats2half2_rn(v2, v3);
            *(__half2*)&Cb[(size_t)m*N + n]     = h01;
            *(__half2*)&Cb[(size_t)(m+8)*N + n] = h23;
            s [im*2+0] += v0 + v1;    s2[im*2+0] += v0*v0 + v1*v1;
            s [im*2+1] += v2 + v3;    s2[im*2+1] += v2*v2 + v3*v3;
        }
    }
#pragma unroll
    for (int r = 0; r < 4; r++) {
        s [r] += __shfl_xor_sync(0xffffffffu, s [r], 1);
        s [r] += __shfl_xor_sync(0xffffffffu, s [r], 2);
        s2[r] += __shfl_xor_sync(0xffffffffu, s2[r], 1);
        s2[r] += __shfl_xor_sync(0xffffffffu, s2[r], 2);
    }
    float2* sst = (float2*)base;
    __syncthreads();
    if ((lane & 3) == 0) {
#pragma unroll
        for (int r = 0; r < 4; r++) {
            int row = rloc + (r >> 1)*16 + (r & 1)*8;
            sst[warp_n*128 + row] = make_float2(s[r], s2[r]);
        }
    }
    __syncthreads();
    if (tid < 128) {
        float2 a = sst[tid], b = sst[128 + tid];
        double2 p;
        p.x = (double)a.x + (double)b.x;
        p.y = (double)a.y + (double)b.y;
        part[(size_t)(m0 + tid)*(BSZ*98) + blockIdx.z*98 + nidx] = p;
    }
}

// finalize BN2 scale/shift from fused partials; warp per channel
__global__ void chan_finalize2(const double2* __restrict__ part,
                               const float* __restrict__ g, const float* __restrict__ bt,
                               float* __restrict__ scale, float* __restrict__ shift) {
    int warp = (blockIdx.x*256 + threadIdx.x) >> 5;
    int lane = threadIdx.x & 31;
    if (warp >= C2) return;
    double s = 0, s2 = 0;
    for (int i = lane; i < BSZ*98; i += 32) {
        double2 p = part[(size_t)warp*(BSZ*98) + i];
        s += p.x; s2 += p.y;
    }
#pragma unroll
    for (int o = 16; o; o >>= 1) {
        s  += __shfl_xor_sync(0xffffffffu, s,  o);
        s2 += __shfl_xor_sync(0xffffffffu, s2, o);
    }
    if (lane == 0) {
        double cnt = (double)BSZ * HW;
        double m = s / cnt;
        double var = s2 / cnt - m*m;
        float rs = (float)(1.0 / sqrt(var + 1e-5));
        float sc = g[warp] * rs;
        scale[warp] = sc;
        shift[warp] = bt[warp] - (float)m * sc;
    }
}

// =====================================================================
//   conv1 as fp16 implicit GEMM + fused BN1 stats
// =====================================================================
__global__ void __launch_bounds__(256, 3) conv1_igemm(
        const float* __restrict__ img, const float* __restrict__ w,
        __half* __restrict__ out, float2* __restrict__ part1) {
    __shared__ __half wt [256*40];
    __shared__ __half imt[128*40];
    __shared__ float  inr[9*224];
    __shared__ float2 sst[256];
    int oy = blockIdx.x, b = blockIdx.y;
    int tid = threadIdx.x;
    int lane = tid & 31, wid = tid >> 5;

    sst[tid] = make_float2(0.f, 0.f);
    for (int i = tid; i < 256*32; i += 256) {
        int c = i >> 5, k = i & 31;
        float v = (k < 27) ? __ldg(&w[c*27 + k]) : 0.f;
        wt[c*40 + k] = __float2half_rn(v);
    }
    const float* ip = img + (size_t)b*3*224*224;
    for (int i = tid; i < 9*224; i += 256) {
        int r = i / 224, x = i - r*224;
        int ci = r / 3, ky = r - ci*3;
        int iy = oy*2 - 1 + ky;
        inr[i] = (iy >= 0 && iy < 224) ? ip[(ci*224 + iy)*224 + x] : 0.f;
    }
    __syncthreads();
    for (int i = tid; i < 128*32; i += 256) {
        int p = i >> 5, k = i & 31;
        float v = 0.f;
        if (p < 112 && k < 27) {
            int ci = k / 9, r = k - ci*9;
            int ky = r / 3, kx = r - ky*3;
            int ix = p*2 - 1 + kx;
            if (ix >= 0 && ix < 224) v = inr[(ci*3 + ky)*224 + ix];
        }
        imt[p*40 + k] = __float2half_rn(v);
    }
    __syncthreads();

    uint32_t wt_b = smem_u32(wt), imt_b = smem_u32(imt);
    size_t obase = (size_t)b*C1*HW + (size_t)oy*112;
#pragma unroll
    for (int half = 0; half < 2; half++) {
        float acc[2][8][4];
#pragma unroll
        for (int i = 0; i < 2; i++)
#pragma unroll
            for (int j = 0; j < 8; j++)
#pragma unroll
                for (int q = 0; q < 4; q++) acc[i][j][q] = 0.f;
#pragma unroll
        for (int ks = 0; ks < 2; ks++) {
            int kb = ks*16;
            uint32_t aF[2][4];
#pragma unroll
            for (int im = 0; im < 2; im++) {
                int row = wid*32 + im*16 + (lane & 15);
                ldsm4(aF[im], wt_b + (row*40 + kb + (lane >> 4)*8)*2);
            }
#pragma unroll
            for (int nc = 0; nc < 4; nc++) {
                uint32_t bF[4];
                int row = half*64 + nc*16 + (lane & 15);
                ldsm4(bF, imt_b + (row*40 + kb + (lane >> 4)*8)*2);
#pragma unroll
                for (int im = 0; im < 2; im++) {
                    mma_fp(acc[im][nc*2],     aF[im], bF[0], bF[2]);
                    mma_fp(acc[im][nc*2 + 1], aF[im], bF[1], bF[3]);
                }
            }
        }
        float s[4]  = {0.f, 0.f, 0.f, 0.f};
        float s2[4] = {0.f, 0.f, 0.f, 0.f};
#pragma unroll
        for (int im = 0; im < 2; im++) {
#pragma unroll
            for (int nf = 0; nf < 8; nf++) {
                int m = wid*32 + im*16 + (lane >> 2);
                int n = half*64 + nf*8 + (lane & 3)*2;
                if (n < 112) {
                    float v0 = acc[im][nf][0], v1 = acc[im][nf][1];
                    float v2 = acc[im][nf][2], v3 = acc[im][nf][3];
                    __half2 h01 = __floats2half2_rn(v0, v1);
                    __half2 h23 = __floats2half2_rn(v2, v3);
                    *(__half2*)&out[obase + (size_t)m*HW + n]     = h01;
                    *(__half2*)&out[obase + (size_t)(m+8)*HW + n] = h23;
                    s [im*2+0] += v0 + v1;   s2[im*2+0] += v0*v0 + v1*v1;
                    s [im*2+1] += v2 + v3;   s2[im*2+1] += v2*v2 + v3*v3;
                }
            }
        }
#pragma unroll
        for (int r = 0; r < 4; r++) {
            s [r] += __shfl_xor_sync(0xffffffffu, s [r], 1);
            s [r] += __shfl_xor_sync(0xffffffffu, s [r], 2);
            s2[r] += __shfl_xor_sync(0xffffffffu, s2[r], 1);
            s2[r] += __shfl_xor_sync(0xffffffffu, s2[r], 2);
        }
        if ((lane & 3) == 0) {
#pragma unroll
            for (int r = 0; r < 4; r++) {
                int row = wid*32 + (r >> 1)*16 + (r & 1)*8 + (lane >> 2);
                float2 p = sst[row];
                p.x += s[r]; p.y += s2[r];
                sst[row] = p;
            }
        }
    }
    __syncthreads();
    {
        float2 p = sst[tid];
        part1[(size_t)tid*(BSZ*112) + b*112 + oy] = p;
    }
}

// finalize BN1 from fused float2 partials (1792 per channel); warp per channel
__global__ void chan_finalize1(const float2* __restrict__ part,
                               const float* __restrict__ g, const float* __restrict__ bt,
                               float* __restrict__ scale, float* __restrict__ shift) {
    int warp = (blockIdx.x*256 + threadIdx.x) >> 5;
    int lane = threadIdx.x & 31;
    if (warp >= C1) return;
    double s = 0, s2 = 0;
    for (int i = lane; i < BSZ*112; i += 32) {
        float2 p = part[(size_t)warp*(BSZ*112) + i];
        s += (double)p.x; s2 += (double)p.y;
    }
#pragma unroll
    for (int o = 16; o; o >>= 1) {
        s  += __shfl_xor_sync(0xffffffffu, s,  o);
        s2 += __shfl_xor_sync(0xffffffffu, s2, o);
    }
    if (lane == 0) {
        double cnt = (double)BSZ * HW;
        double m = s / cnt;
        double var = s2 / cnt - m*m;
        float rs = (float)(1.0 / sqrt(var + 1e-5));
        float sc = g[warp] * rs;
        scale[warp] = sc;
        shift[warp] = bt[warp] - (float)m * sc;
    }
}

// ---------------- depthwise 3x3 s1 p1 (BN1+ReLU fused), fp16 in/out -------------
__global__ void dw_kernel(const __half* __restrict__ in, const float* __restrict__ w,
                          const float* __restrict__ scale, const float* __restrict__ shift,
                          __half* __restrict__ outh) {
    int warp = threadIdx.x >> 5, lane = threadIdx.x & 31;
    int y = blockIdx.x*8 + warp;
    int c = blockIdx.y, b = blockIdx.z;
    float sc = scale[c], sh = shift[c];
    const __half* ip = in + ((size_t)b*C1 + c)*HW;
    int x0 = lane*4;
    bool inx = (x0 < 112);

    float v[3][4];
    float lft[3], rgt[3];
#pragma unroll
    for (int r = 0; r < 3; r++) {
        int yy = y - 1 + r;
        float t0 = 0.f, t1 = 0.f, t2 = 0.f, t3 = 0.f;
        if (inx && yy >= 0 && yy < 112) {
            uint2 u = *(const uint2*)&ip[yy*112 + x0];
            float2 p0 = __half22float2(*(__half2*)&u.x);
            float2 p1 = __half22float2(*(__half2*)&u.y);
            t0 = p0.x; t1 = p0.y; t2 = p1.x; t3 = p1.y;
        }
        v[r][0] = fmaxf(t0*sc + sh, 0.f);
        v[r][1] = fmaxf(t1*sc + sh, 0.f);
        v[r][2] = fmaxf(t2*sc + sh, 0.f);
        v[r][3] = fmaxf(t3*sc + sh, 0.f);
        if (!inx || yy < 0 || yy >= 112) { v[r][0]=v[r][1]=v[r][2]=v[r][3]=0.f; }
        lft[r] = __shfl_up_sync(0xffffffffu, v[r][3], 1);
        if (lane == 0) lft[r] = 0.f;
        rgt[r] = __shfl_down_sync(0xffffffffu, v[r][0], 1);
        if (lane >= 27) rgt[r] = 0.f;
    }
    float wv[9];
#pragma unroll
    for (int k = 0; k < 9; k++) wv[k] = __ldg(&w[c*9 + k]);

    float o0 = 0.f, o1 = 0.f, o2 = 0.f, o3 = 0.f;
#pragma unroll
    for (int r = 0; r < 3; r++) {
        float e0 = lft[r], e1 = v[r][0], e2 = v[r][1], e3 = v[r][2], e4 = v[r][3], e5 = rgt[r];
        float w0 = wv[r*3+0], w1 = wv[r*3+1], w2 = wv[r*3+2];
        o0 += w0*e0 + w1*e1 + w2*e2;
        o1 += w0*e1 + w1*e2 + w2*e3;
        o2 += w0*e2 + w1*e3 + w2*e4;
        o3 += w0*e3 + w1*e4 + w2*e5;
    }
    if (inx) {
        __half2 h01 = __floats2half2_rn(o0, o1);
        __half2 h23 = __floats2half2_rn(o2, o3);
        size_t off = ((size_t)b*C1 + c)*HW + y*112 + x0;
        *(uint2*)&outh[off] = make_uint2(*(uint32_t*)&h01, *(uint32_t*)&h23);
    }
}

// ---------------- pooled[b][c] = mean_p relu(bn2(pw)), fp16 source ----------------
__global__ void pooled_kernel(const __half* __restrict__ x, const float* __restrict__ scale,
                              const float* __restrict__ shift, float* __restrict__ pooled) {
    int c = blockIdx.x, b = blockIdx.y;
    const __half2* p = (const __half2*)(x + ((size_t)b*C2 + c)*HW);
    float sc = scale[c], sh = shift[c];
    double s = 0;
    for (int i = threadIdx.x; i < HW/2; i += 256) {
        float2 v = __half22float2(p[i]);
        float a = v.x*sc + sh, bq = v.y*sc + sh;
        if (a > 0.f) s += a;
        if (bq > 0.f) s += bq;
    }
    __shared__ double shm[256];
    shm[threadIdx.x] = s; __syncthreads();
    for (int o = 128; o; o >>= 1) {
        if (threadIdx.x < o) shm[threadIdx.x] += shm[threadIdx.x+o];
        __syncthreads();
    }
    if (threadIdx.x == 0) pooled[b*C2 + c] = (float)(shm[0] / (double)HW);
}

// ---------------- small GEMM ----------------
__global__ void small_gemm(const float* __restrict__ in, int K,
                           const float* __restrict__ W, int ldw, int woff,
                           const float* __restrict__ bias, const float* __restrict__ aux,
                           int O, int act, float* __restrict__ out) {
    __shared__ float sin_s[BSZ*512];
    for (int i = threadIdx.x; i < BSZ*K; i += 256) sin_s[i] = in[i];
    __syncthreads();
    int warp = threadIdx.x >> 5, lane = threadIdx.x & 31;
    int o = blockIdx.x*8 + warp;
    float part[BSZ];
#pragma unroll
    for (int b = 0; b < BSZ; b++) part[b] = 0.f;
    for (int k = lane; k < K; k += 32) {
        float wv = W[(size_t)o*ldw + woff + k];
#pragma unroll
        for (int b = 0; b < BSZ; b++) part[b] += wv * sin_s[b*K + k];
    }
#pragma unroll
    for (int b = 0; b < BSZ; b++) {
        float v = part[b];
#pragma unroll
        for (int off = 16; off; off >>= 1) v += __shfl_xor_sync(0xffffffffu, v, off);
        if (lane == b) {
            if (bias) v += bias[o];
            if (act == 1) v = v > 0.f ? v : 0.f;
            else if (act == 2) v = (1.f/(1.f + expf(-v))) * aux[b*O + o];
            out[b*O + o] = v;
        }
    }
}

// ---------------- gather caption embeddings: bf16 split planes ----------------
__global__ void gather_embs(const int* __restrict__ cap, const float* __restrict__ embed,
                            __nv_bfloat16* __restrict__ eh, __nv_bfloat16* __restrict__ el) {
    int row = blockIdx.x;
    int b = row >> 5, t = row & 31;
    int tok = cap[b*33 + t];
    const float* src = embed + (size_t)tok*HID;
    int i = threadIdx.x*2;
    float2 v = *(const float2*)&src[i];
    float h0,l0,h1,l1;
    split2(v.x,h0,l0); split2(v.y,h1,l1);
    *(uint32_t*)&eh[(size_t)row*HID + i] = pack_bf2(h0,h1);
    *(uint32_t*)&el[(size_t)row*HID + i] = pack_bf2(l0,l1);
}

// ---------------- persistent GRU (hall fp16 for logits) ----------------
__global__ void gru_reset() {
    if (threadIdx.x < TT) g_gbar[threadIdx.x] = 0;
}
#define GRU_BLKS 64
__global__ void __launch_bounds__(256) gru_persist(
        const float* __restrict__ gi, const float* __restrict__ whh,
        const float* __restrict__ bhh, float* __restrict__ hall,
        __half* __restrict__ hallh) {
    __shared__ float hs[BSZ*HID];
    int tid = threadIdx.x;
    int warp = tid >> 5, lane = tid & 31;
    int j = blockIdx.x*8 + warp;
    float w0[16], w1[16], w2[16];
#pragma unroll
    for (int i = 0; i < 16; i++) {
        int k = lane + 32*i;
        w0[i] = whh[(size_t)j*HID + k];
        w1[i] = whh[(size_t)(j + 512)*HID + k];
        w2[i] = whh[(size_t)(j + 1024)*HID + k];
    }
    float bhr = bhh[j], bhz = bhh[j + 512], bhn = bhh[j + 1024];

    for (int t = 0; t < TT; t++) {
        for (int i = tid; i < BSZ*HID; i += 256) {
            int b = i >> 9, jj = i & 511;
            hs[i] = (t == 0) ? 0.f : hall[((size_t)(b*TT + t - 1))*HID + jj];
        }
        __syncthreads();
        for (int b = 0; b < BSZ; b++) {
            float pr = 0.f, pz = 0.f, pn = 0.f;
#pragma unroll
            for (int i = 0; i < 16; i++) {
                float hv = hs[b*HID + lane + 32*i];
                pr += hv*w0[i]; pz += hv*w1[i]; pn += hv*w2[i];
            }
#pragma unroll
            for (int o = 16; o; o >>= 1) {
                pr += __shfl_xor_sync(0xffffffffu, pr, o);
                pz += __shfl_xor_sync(0xffffffffu, pz, o);
                pn += __shfl_xor_sync(0xffffffffu, pn, o);
            }
            if (lane == 0) {
                size_t gib = ((size_t)(b*TT + t))*1536;
                float ir = gi[gib + j], iz = gi[gib + 512 + j], inn = gi[gib + 1024 + j];
                float r = 1.f/(1.f + expf(-(ir + pr + bhr)));
                float z = 1.f/(1.f + expf(-(iz + pz + bhz)));
                float n = tanhf(inn + r*(pn + bhn));
                float hp = hs[b*HID + j];
                float hn2 = (1.f - z)*n + z*hp;
                size_t oidx = ((size_t)(b*TT + t))*HID + j;
                hall[oidx] = hn2;
                hallh[oidx] = __float2half_rn(hn2);
            }
        }
        // grid barrier: single RMW arrival + volatile-load polling (no RMW storm)
        __threadfence();
        __syncthreads();
        if (tid == 0) {
            int prev = atomicAdd(&g_gbar[t], 1);
            if (prev < GRU_BLKS - 1) {
                volatile int* bar = &g_gbar[t];
                while (*bar < GRU_BLKS) __nanosleep(32);
            }
        }
        __syncthreads();
    }
}

// =======================================================================
extern "C" void kernel_launch(void* const* d_in, const int* in_sizes, int n_in,
                              void* d_out, int out_size) {
    const float* images   = (const float*)d_in[0];
    const int*   captions = (const int*)  d_in[1];
    const float* conv1_w  = (const float*)d_in[2];
    const float* bn1_g    = (const float*)d_in[3];
    const float* bn1_b    = (const float*)d_in[4];
    const float* dw_w     = (const float*)d_in[5];
    const float* pw_w     = (const float*)d_in[6];
    const float* bn2_g    = (const float*)d_in[7];
    const float* bn2_b    = (const float*)d_in[8];
    const float* se_fc1_w = (const float*)d_in[9];
    const float* se_fc2_w = (const float*)d_in[10];
    const float* enc_fc_w = (const float*)d_in[11];
    const float* enc_fc_b = (const float*)d_in[12];
    const float* embed    = (const float*)d_in[13];
    // d_in[14] = q_w (unused), d_in[15] = k_w (unused)
    const float* v_w      = (const float*)d_in[16];
    const float* gru_w_ih = (const float*)d_in[17];
    const float* gru_w_hh = (const float*)d_in[18];
    const float* gru_b_ih = (const float*)d_in[19];
    const float* gru_b_hh = (const float*)d_in[20];
    const float* fc_w     = (const float*)d_in[21];
    const float* fc_b     = (const float*)d_in[22];

    __half *conv1buf;
    float2 *part1;
    double2 *part2;
    float *scale1, *shift1, *scale2, *shift2;
    float *pooled, *t1, *fbuf, *feats, *ctx, *gctx, *gi, *hall;
    __half *dwh, *pwwh, *pwout, *fcwh, *hallh;
    __nv_bfloat16 *wihh, *wihl, *embsh, *embsl;
    cudaGetSymbolAddress((void**)&conv1buf, g_conv1);
    cudaGetSymbolAddress((void**)&part1,    g_part1);
    cudaGetSymbolAddress((void**)&part2,    g_part2);
    cudaGetSymbolAddress((void**)&scale1,   g_scale1);
    cudaGetSymbolAddress((void**)&shift1,   g_shift1);
    cudaGetSymbolAddress((void**)&scale2,   g_scale2);
    cudaGetSymbolAddress((void**)&shift2,   g_shift2);
    cudaGetSymbolAddress((void**)&pooled,   g_pooled);
    cudaGetSymbolAddress((void**)&t1,       g_t1);
    cudaGetSymbolAddress((void**)&fbuf,     g_f);
    cudaGetSymbolAddress((void**)&feats,    g_feats);
    cudaGetSymbolAddress((void**)&ctx,      g_ctx);
    cudaGetSymbolAddress((void**)&gctx,     g_gctx);
    cudaGetSymbolAddress((void**)&gi,       g_gi);
    cudaGetSymbolAddress((void**)&hall,     g_hall);
    cudaGetSymbolAddress((void**)&dwh,      g_dwh);
    cudaGetSymbolAddress((void**)&pwwh,     g_pwwh);
    cudaGetSymbolAddress((void**)&pwout,    g_pwout);
    cudaGetSymbolAddress((void**)&fcwh,     g_fcwh);
    cudaGetSymbolAddress((void**)&wihh,     g_wihh);
    cudaGetSymbolAddress((void**)&wihl,     g_wihl);
    cudaGetSymbolAddress((void**)&embsh,    g_embsh);
    cudaGetSymbolAddress((void**)&embsl,    g_embsl);
    cudaGetSymbolAddress((void**)&hallh,    g_hallh);

    cudaFuncSetAttribute(mma_gemm_nt,    cudaFuncAttributeMaxDynamicSharedMemorySize, SMEM_REQ);
    cudaFuncSetAttribute(mma_gemm_nt_h1, cudaFuncAttributeMaxDynamicSharedMemorySize, H1SMEM_REQ);
    cudaFuncSetAttribute(hgemm_nn,       cudaFuncAttributeMaxDynamicSharedMemorySize, HSMEM_REQ);

    // weight conversions (independent of encoder)
    to_half<<<(C2*C1)/1024, 256>>>(pw_w, pwwh, (size_t)C2*C1);
    to_half<<<((size_t)VOC*HID)/1024, 256>>>(fc_w, fcwh, (size_t)VOC*HID);
    split_strided<<<(1536*512)/1024, 256>>>(gru_w_ih, 1024, wihh, wihl);

    // encoder
    conv1_igemm<<<dim3(112, BSZ), 256>>>(images, conv1_w, conv1buf, part1);
    chan_finalize1<<<32, 256>>>(part1, bn1_g, bn1_b, scale1, shift1);
    dw_kernel<<<dim3(14, C1, BSZ), 256>>>(conv1buf, dw_w, scale1, shift1, dwh);
    // pointwise conv (fp16 single-pass GEMM, fused BN2 stats)
    hgemm_nn<<<dim3(4, 98, BSZ), 256, HSMEM_REQ>>>(pwwh, dwh, pwout, part2,
                                                   C2, HW, C1, HW,
                                                   (size_t)C1*HW, (size_t)C2*HW);
    chan_finalize2<<<64, 256>>>(part2, bn2_g, bn2_b, scale2, shift2);
    pooled_kernel<<<dim3(C2, BSZ), 256>>>(pwout, scale2, shift2, pooled);

    // SE + encoder FC + ctx (tiny GEMMs)
    small_gemm<<<16, 256>>>(pooled, 512, se_fc1_w, 512, 0, nullptr, nullptr, 128, 1, t1);
    small_gemm<<<64, 256>>>(t1, 128, se_fc2_w, 128, 0, nullptr, pooled, 512, 2, fbuf);
    small_gemm<<<64, 256>>>(fbuf, 512, enc_fc_w, 512, 0, enc_fc_b, nullptr, 512, 0, feats);
    small_gemm<<<64, 256>>>(feats, 512, v_w, 512, 0, nullptr, nullptr, 512, 0, ctx);

    // decoder: precompute input gates (bf16 3-pass — precision-critical via GRU)
    small_gemm<<<192, 256>>>(ctx, 512, gru_w_ih, 1024, 512, gru_b_ih, nullptr, 1536, 0, gctx);
    gather_embs<<<512, 256>>>(captions, embed, embsh, embsl);
    mma_gemm_nt<<<dim3(12, 4, 1), 256, SMEM_REQ>>>(embsh, embsl, wihh, wihl, gi,
                                                   512, 1536, 512, 512, nullptr, gctx);

    // persistent GRU recurrence
    gru_reset<<<1, 32>>>();
    gru_persist<<<GRU_BLKS, 256>>>(gi, gru_w_hh, gru_b_hh, hall, hallh);

    // logits: fp16 single-pass
    mma_gemm_nt_h1<<<dim3(250, 4, 1), 256, H1SMEM_REQ>>>(hallh, fcwh, (float*)d_out,
                                                         512, VOC, 512, 512, fc_b);
}